// round 8
// baseline (speedup 1.0000x reference)
#include <cuda_runtime.h>

#define HEADS 8
#define DH 64
#define DIM 512
#define ONION 15
#define SC 4
#define NVELO 28504
#define NSURF 3682
#define NPTS 32186
#define SKEEP 3586
#define FLAP 500
#define NTOK 64
#define L1 4182
#define VC 60
#define NPT_TOT (NVELO + SKEEP)
#define PREP_N ((NTOK * DIM) > NPT_TOT ? (NTOK * DIM) : NPT_TOT)
#define ATT_SCALE 0.125f
#define LN_EPS 1e-5f
#define FLASH_SMEM (4 * 64 * 68 * 4)
#define ATTN2_SMEM (5 * 64 * 68 * 4)

__device__ float g_fx[NPTS * DIM];
__device__ float g_xm[NPTS * DIM];
__device__ float g_newf[NPTS * DIM];
__device__ float g_q1[HEADS * L1 * DH];
__device__ float g_k1[HEADS * L1 * DH];
__device__ float g_v1[HEADS * L1 * DH];
__device__ float g_o1[HEADS * L1 * DH];
__device__ int   g_tok1src[L1];
__device__ int   g_ptrow[NPT_TOT];
__device__ int   g_ptgrp[NPT_TOT];
__device__ float g_tokacc[NTOK * DIM];
__device__ float g_toknorm[NTOK * DIM];
__device__ float g_outtok[HEADS * NTOK * DH];
__device__ float g_outvelo[VC * DIM];
__device__ float g_outsurf[SC * DIM];
__device__ float g_Pws[NSURF * SC];
__device__ float g_Pvc[NSURF * VC];
__device__ float g_Pv[NVELO * VC];

// C[M,N] = gather(A)[M,K] @ B[K,N] + bias ; 64x64 tile, BK=16, 4x4 microtile
__global__ void gemm_bias(const float* __restrict__ A, int lda,
                          const int* __restrict__ rowidx,
                          const float* __restrict__ B, int ldb,
                          const float* __restrict__ bias,
                          float* __restrict__ C, int ldc,
                          int M, int N, int K)
{
    __shared__ float As[16][68];
    __shared__ float Bs[16][68];
    int m0 = blockIdx.y * 64, n0 = blockIdx.x * 64;
    int tid = threadIdx.x, ty = tid >> 4, tx = tid & 15;
    float acc[4][4] = {};
    for (int k0 = 0; k0 < K; k0 += 16) {
        #pragma unroll
        for (int e = tid; e < 1024; e += 256) {
            int r = e >> 4, k = e & 15;
            int gm = m0 + r, gk = k0 + k;
            float v = 0.f;
            if (gm < M && gk < K) {
                int row = rowidx ? rowidx[gm] : gm;
                v = A[row * lda + gk];
            }
            As[k][r] = v;
        }
        #pragma unroll
        for (int e = tid; e < 1024; e += 256) {
            int k = e >> 6, n = e & 63;
            int gk = k0 + k, gn = n0 + n;
            Bs[k][n] = (gk < K && gn < N) ? B[gk * ldb + gn] : 0.f;
        }
        __syncthreads();
        #pragma unroll
        for (int kk = 0; kk < 16; kk++) {
            float4 a4 = *(const float4*)&As[kk][ty * 4];
            float4 b4 = *(const float4*)&Bs[kk][tx * 4];
            float ar[4] = {a4.x, a4.y, a4.z, a4.w};
            float br[4] = {b4.x, b4.y, b4.z, b4.w};
            #pragma unroll
            for (int i = 0; i < 4; i++)
                #pragma unroll
                for (int j = 0; j < 4; j++)
                    acc[i][j] += ar[i] * br[j];
        }
        __syncthreads();
    }
    #pragma unroll
    for (int i = 0; i < 4; i++) {
        int gm = m0 + ty * 4 + i;
        if (gm >= M) continue;
        #pragma unroll
        for (int j = 0; j < 4; j++) {
            int gn = n0 + tx * 4 + j;
            if (gn < N) C[gm * ldc + gn] = acc[i][j] + bias[gn];
        }
    }
}

__global__ void prep_kernel(const float* __restrict__ onion,
                            const int* __restrict__ labels,
                            const int* __restrict__ closest,
                            const int* __restrict__ velo_idx,
                            const int* __restrict__ surf_idx)
{
    int i = blockIdx.x * 256 + threadIdx.x;
    if (i < L1) g_tok1src[i] = (i < FLAP) ? velo_idx[i] : surf_idx[i - FLAP];
    if (i < NTOK * DIM) g_tokacc[i] = 0.f;   // must cover all 32768 elems!
    if (i >= NPT_TOT) return;
    if (i < NVELO) {
        int lab = 0;
        #pragma unroll
        for (int l = 1; l < ONION; l++)
            if (onion[l * NVELO + i] > 0.5f) lab = l;
        g_ptrow[i] = velo_idx[i];
        g_ptgrp[i] = SC + lab * SC + labels[closest[i]];
    } else {
        int j = i - NVELO;
        int sr = (j < 16) ? j : j + 96;
        g_ptrow[i] = surf_idx[sr];
        g_ptgrp[i] = labels[j];
    }
}

// q/k/v projection for attention-1, per (token-tile, head)
__global__ void proj1_kernel(const float* __restrict__ Wq1,
                             const float* __restrict__ Wk1,
                             const float* __restrict__ Wv1)
{
    __shared__ float Ts[64][68];
    __shared__ float Ws[64][68];
    int h = blockIdx.y, t0 = blockIdx.x * 64;
    int tid = threadIdx.x, ty = tid >> 4, tx = tid & 15;
    #pragma unroll
    for (int e = tid; e < 4096; e += 256) {
        int t = e >> 6, d = e & 63;
        int gt = t0 + t;
        Ts[t][d] = (gt < L1) ? g_fx[g_tok1src[gt] * DIM + h * DH + d] : 0.f;
    }
    const float* Wm[3] = {Wq1, Wk1, Wv1};
    float* Om[3] = {g_q1, g_k1, g_v1};
    #pragma unroll
    for (int m = 0; m < 3; m++) {
        __syncthreads();
        #pragma unroll
        for (int e = tid; e < 4096; e += 256) Ws[e >> 6][e & 63] = Wm[m][e];
        __syncthreads();
        float acc[4][4] = {};
        #pragma unroll
        for (int x = 0; x < 64; x++) {
            float ar[4];
            #pragma unroll
            for (int i = 0; i < 4; i++) ar[i] = Ts[ty * 4 + i][x];
            float4 b4 = *(const float4*)&Ws[x][tx * 4];
            float br[4] = {b4.x, b4.y, b4.z, b4.w};
            #pragma unroll
            for (int i = 0; i < 4; i++)
                #pragma unroll
                for (int j = 0; j < 4; j++)
                    acc[i][j] += ar[i] * br[j];
        }
        #pragma unroll
        for (int i = 0; i < 4; i++) {
            int gt = t0 + ty * 4 + i;
            if (gt >= L1) continue;
            #pragma unroll
            for (int j = 0; j < 4; j++)
                Om[m][h * (L1 * DH) + gt * DH + tx * 4 + j] = acc[i][j];
        }
    }
}

// flash attention over L1 keys; block = (64-query tile, head)
__global__ void __launch_bounds__(256, 2) flash1_kernel()
{
    extern __shared__ float smem[];
    float (*Qs)[68] = (float(*)[68])smem;
    float (*Ks)[68] = Qs + 64;
    float (*Vs)[68] = Ks + 64;
    float (*Ss)[68] = Vs + 64;
    __shared__ float m_s[64], l_s[64], c_s[64];
    int h = blockIdx.y, q0 = blockIdx.x * 64;
    int tid = threadIdx.x, ty = tid >> 4, tx = tid & 15;
    const float* Qh = g_q1 + h * (L1 * DH);
    const float* Kh = g_k1 + h * (L1 * DH);
    const float* Vh = g_v1 + h * (L1 * DH);
    #pragma unroll
    for (int e = tid; e < 4096; e += 256) {
        int t = e >> 6, d = e & 63;
        int gt = q0 + t;
        Qs[d][t] = (gt < L1) ? Qh[gt * DH + d] : 0.f;
    }
    if (tid < 64) { m_s[tid] = -1e30f; l_s[tid] = 0.f; }
    float acc[4][4] = {};
    __syncthreads();
    for (int k0 = 0; k0 < L1; k0 += 64) {
        #pragma unroll
        for (int e = tid; e < 4096; e += 256) {
            int t = e >> 6, d = e & 63;
            int gt = k0 + t;
            float kv = 0.f, vv = 0.f;
            if (gt < L1) { kv = Kh[gt * DH + d]; vv = Vh[gt * DH + d]; }
            Ks[d][t] = kv;
            Vs[t][d] = vv;
        }
        __syncthreads();
        float s[4][4] = {};
        #pragma unroll
        for (int d = 0; d < 64; d++) {
            float4 a4 = *(const float4*)&Qs[d][ty * 4];
            float4 b4 = *(const float4*)&Ks[d][tx * 4];
            float ar[4] = {a4.x, a4.y, a4.z, a4.w};
            float br[4] = {b4.x, b4.y, b4.z, b4.w};
            #pragma unroll
            for (int i = 0; i < 4; i++)
                #pragma unroll
                for (int j = 0; j < 4; j++)
                    s[i][j] += ar[i] * br[j];
        }
        #pragma unroll
        for (int i = 0; i < 4; i++)
            #pragma unroll
            for (int j = 0; j < 4; j++) {
                float v = s[i][j] * ATT_SCALE;
                if (k0 + tx * 4 + j >= L1) v = -1e30f;
                Ss[ty * 4 + i][tx * 4 + j] = v;
            }
        __syncthreads();
        if (tid < 64) {
            float mo = m_s[tid], mx = mo;
            #pragma unroll 8
            for (int j = 0; j < 64; j++) mx = fmaxf(mx, Ss[tid][j]);
            float corr = __expf(mo - mx);
            m_s[tid] = mx; c_s[tid] = corr; l_s[tid] *= corr;
        }
        __syncthreads();
        #pragma unroll
        for (int i = 0; i < 4; i++) {
            int r = ty * 4 + i;
            float mrow = m_s[r], corr = c_s[r];
            #pragma unroll
            for (int j = 0; j < 4; j++) {
                acc[i][j] *= corr;
                Ss[r][tx * 4 + j] = __expf(Ss[r][tx * 4 + j] - mrow);
            }
        }
        __syncthreads();
        if (tid < 64) {
            float sum = 0.f;
            #pragma unroll 8
            for (int j = 0; j < 64; j++) sum += Ss[tid][j];
            l_s[tid] += sum;
        }
        #pragma unroll 16
        for (int kk = 0; kk < 64; kk++) {
            float4 b4 = *(const float4*)&Vs[kk][tx * 4];
            float br[4] = {b4.x, b4.y, b4.z, b4.w};
            float pr[4];
            #pragma unroll
            for (int i = 0; i < 4; i++) pr[i] = Ss[ty * 4 + i][kk];
            #pragma unroll
            for (int i = 0; i < 4; i++)
                #pragma unroll
                for (int j = 0; j < 4; j++)
                    acc[i][j] += pr[i] * br[j];
        }
        __syncthreads();
    }
    #pragma unroll
    for (int i = 0; i < 4; i++) {
        int gq = q0 + ty * 4 + i;
        if (gq >= L1) continue;
        float inv = 1.f / l_s[ty * 4 + i];
        #pragma unroll
        for (int j = 0; j < 4; j++)
            g_o1[h * (L1 * DH) + gq * DH + tx * 4 + j] = acc[i][j] * inv;
    }
}

// pooled-token accumulation via smem atomics
#define ACC_CHUNK 1024
__global__ void pool_accum()
{
    __shared__ float sa[64][64];
    int d0 = blockIdx.y * 64, p0 = blockIdx.x * ACC_CHUNK;
    int tid = threadIdx.x, dd = tid & 63, q4 = tid >> 6;
    #pragma unroll
    for (int e = tid; e < 4096; e += 256) ((float*)sa)[e] = 0.f;
    __syncthreads();
    int pend = min(p0 + ACC_CHUNK, NPT_TOT);
    for (int p = p0 + q4; p < pend; p += 4) {
        float v = g_fx[g_ptrow[p] * DIM + d0 + dd];
        atomicAdd(&sa[g_ptgrp[p]][dd], v);
    }
    __syncthreads();
    #pragma unroll
    for (int e = tid; e < 4096; e += 256) {
        int g = e >> 6, d = e & 63;
        float v = sa[g][d];
        if (v != 0.f) atomicAdd(&g_tokacc[g * DIM + d0 + d], v);
    }
}

// layernorm across token axis (per channel), then gamma[t]/beta[t]
__global__ void ln_kernel(const float* __restrict__ gamma,
                          const float* __restrict__ beta)
{
    int d = threadIdx.x;
    const float n_s = 1.f / (float)SKEEP, n_v = 1.f / (float)NVELO;
    float s = 0.f;
    #pragma unroll
    for (int t = 0; t < NTOK; t++)
        s += g_tokacc[t * DIM + d] * ((t < SC) ? n_s : n_v);
    float mu = s * (1.f / NTOK);
    float v2 = 0.f;
    #pragma unroll
    for (int t = 0; t < NTOK; t++) {
        float dv = g_tokacc[t * DIM + d] * ((t < SC) ? n_s : n_v) - mu;
        v2 += dv * dv;
    }
    float inv = rsqrtf(v2 * (1.f / NTOK) + LN_EPS);
    #pragma unroll
    for (int t = 0; t < NTOK; t++) {
        float val = g_tokacc[t * DIM + d] * ((t < SC) ? n_s : n_v);
        g_toknorm[t * DIM + d] = (val - mu) * inv * gamma[t] + beta[t];
    }
}

// attention over the 64 pooled tokens; one block per head
__global__ void attn2_kernel(const float* __restrict__ Wq,
                             const float* __restrict__ Wk,
                             const float* __restrict__ Wv)
{
    extern __shared__ float sm2[];
    float (*tk)[68] = (float(*)[68])sm2;
    float (*qs)[68] = tk + 64;
    float (*ks)[68] = qs + 64;
    float (*vs)[68] = ks + 64;
    float (*ss)[68] = vs + 64;
    int h = blockIdx.x, tid = threadIdx.x;
    #pragma unroll
    for (int e = tid; e < 4096; e += 256) {
        int t = e >> 6, d = e & 63;
        tk[t][d] = g_toknorm[t * DIM + h * DH + d];
    }
    __syncthreads();
    #pragma unroll
    for (int e = tid; e < 4096; e += 256) {
        int t = e >> 6, d = e & 63;
        float aq = 0.f, ak = 0.f, av = 0.f;
        for (int x = 0; x < 64; x++) {
            float tv = tk[t][x];
            aq += tv * Wq[x * 64 + d];
            ak += tv * Wk[x * 64 + d];
            av += tv * Wv[x * 64 + d];
        }
        qs[t][d] = aq; ks[t][d] = ak; vs[t][d] = av;
    }
    __syncthreads();
    #pragma unroll
    for (int e = tid; e < 4096; e += 256) {
        int t = e >> 6, u = e & 63;
        float sv = 0.f;
        for (int d = 0; d < 64; d++) sv += qs[t][d] * ks[u][d];
        ss[t][u] = sv * ATT_SCALE;
    }
    __syncthreads();
    if (tid < 64) {
        float mx = -1e30f;
        for (int j = 0; j < 64; j++) mx = fmaxf(mx, ss[tid][j]);
        float sum = 0.f;
        for (int j = 0; j < 64; j++) {
            float p = __expf(ss[tid][j] - mx);
            ss[tid][j] = p; sum += p;
        }
        float inv = 1.f / sum;
        for (int j = 0; j < 64; j++) ss[tid][j] *= inv;
    }
    __syncthreads();
    #pragma unroll
    for (int e = tid; e < 4096; e += 256) {
        int t = e >> 6, d = e & 63;
        float o = 0.f;
        for (int u = 0; u < 64; u++) o += ss[t][u] * vs[u][d];
        g_outtok[h * (NTOK * DH) + t * DH + d] = o;
    }
}

// reshape out_tok into out_surf (4x512) and out_velo (60x512)
__global__ void mat_out_kernel()
{
    int i = blockIdx.x * 256 + threadIdx.x;
    if (i < VC * DIM) {
        int r = i >> 9, d = i & 511;
        g_outvelo[i] = g_outtok[(d >> 6) * 4096 + (SC + r) * 64 + (d & 63)];
    }
    if (i < SC * DIM)
        g_outsurf[i] = g_outtok[(i >> 8) * 4096 + (((i >> 6) & 3) << 6) + (i & 63)];
}

// feat_surf = 0.5*(Pws@out_surf + Pvc@out_velo) + surf_first_lap -> scatter
__global__ void feat_surf_k(const int* __restrict__ surf_idx)
{
    __shared__ float Pw[64][4];
    __shared__ float Pc[64][60];
    __shared__ float Osf[4][64];
    __shared__ float Ovl[60][64];
    int i0 = blockIdx.x * 64, h = blockIdx.y, d0 = h * 64;
    int tid = threadIdx.x, ty = tid >> 4, tx = tid & 15;
    for (int e = tid; e < 64 * 4; e += 256) {
        int r = e >> 2, c = e & 3;
        int gi = i0 + r;
        Pw[r][c] = (gi < NSURF) ? g_Pws[gi * 4 + c] : 0.f;
    }
    for (int e = tid; e < 64 * 60; e += 256) {
        int r = e / 60, c = e % 60;
        int gi = i0 + r;
        Pc[r][c] = (gi < NSURF) ? g_Pvc[gi * 60 + c] : 0.f;
    }
    for (int e = tid; e < 4 * 64; e += 256)
        Osf[e >> 6][e & 63] = g_outsurf[(e >> 6) * DIM + d0 + (e & 63)];
    for (int e = tid; e < 60 * 64; e += 256)
        Ovl[e >> 6][e & 63] = g_outvelo[(e >> 6) * DIM + d0 + (e & 63)];
    __syncthreads();
    float acc[4][4] = {};
    #pragma unroll
    for (int c = 0; c < 4; c++) {
        float ar[4];
        #pragma unroll
        for (int i = 0; i < 4; i++) ar[i] = Pw[ty * 4 + i][c];
        #pragma unroll
        for (int i = 0; i < 4; i++)
            #pragma unroll
            for (int j = 0; j < 4; j++)
                acc[i][j] += ar[i] * Osf[c][tx * 4 + j];
    }
    #pragma unroll
    for (int r = 0; r < 60; r++) {
        float ar[4];
        #pragma unroll
        for (int i = 0; i < 4; i++) ar[i] = Pc[ty * 4 + i][r];
        #pragma unroll
        for (int i = 0; i < 4; i++)
            #pragma unroll
            for (int j = 0; j < 4; j++)
                acc[i][j] += ar[i] * Ovl[r][tx * 4 + j];
    }
    #pragma unroll
    for (int i = 0; i < 4; i++) {
        int gi = i0 + ty * 4 + i;
        if (gi >= NSURF) continue;
        int orow = surf_idx[gi];
        #pragma unroll
        for (int j = 0; j < 4; j++) {
            int dd = tx * 4 + j;
            g_newf[orow * DIM + d0 + dd] =
                0.5f * acc[i][j] + g_o1[h * (L1 * DH) + (FLAP + gi) * DH + dd];
        }
    }
}

// feat_velo = Pv@out_velo (+ velo_first_lap rows<500) -> scatter
__global__ void feat_velo_k(const int* __restrict__ velo_idx)
{
    __shared__ float Pv_s[64][60];
    __shared__ float Ovl[60][64];
    int i0 = blockIdx.x * 64, h = blockIdx.y, d0 = h * 64;
    int tid = threadIdx.x, ty = tid >> 4, tx = tid & 15;
    for (int e = tid; e < 64 * 60; e += 256) {
        int r = e / 60, c = e % 60;
        int gi = i0 + r;
        Pv_s[r][c] = (gi < NVELO) ? g_Pv[gi * 60 + c] : 0.f;
    }
    for (int e = tid; e < 60 * 64; e += 256)
        Ovl[e >> 6][e & 63] = g_outvelo[(e >> 6) * DIM + d0 + (e & 63)];
    __syncthreads();
    float acc[4][4] = {};
    #pragma unroll
    for (int r = 0; r < 60; r++) {
        float ar[4];
        #pragma unroll
        for (int i = 0; i < 4; i++) ar[i] = Pv_s[ty * 4 + i][r];
        #pragma unroll
        for (int i = 0; i < 4; i++)
            #pragma unroll
            for (int j = 0; j < 4; j++)
                acc[i][j] += ar[i] * Ovl[r][tx * 4 + j];
    }
    #pragma unroll
    for (int i = 0; i < 4; i++) {
        int gi = i0 + ty * 4 + i;
        if (gi >= NVELO) continue;
        int orow = velo_idx[gi];
        #pragma unroll
        for (int j = 0; j < 4; j++) {
            int dd = tx * 4 + j;
            float v = acc[i][j];
            if (gi < FLAP) v += g_o1[h * (L1 * DH) + gi * DH + dd];
            g_newf[orow * DIM + d0 + dd] = v;
        }
    }
}

extern "C" void kernel_launch(void* const* d_in, const int* in_sizes, int n_in,
                              void* d_out, int out_size)
{
    (void)in_sizes; (void)n_in; (void)out_size;
    const float* x     = (const float*)d_in[0];
    const float* onion = (const float*)d_in[1];
    const float* W_fx  = (const float*)d_in[2];
    const float* b_fx  = (const float*)d_in[3];
    const float* W_x   = (const float*)d_in[4];
    const float* b_x   = (const float*)d_in[5];
    const float* Wq1   = (const float*)d_in[6];
    const float* Wk1   = (const float*)d_in[7];
    const float* Wv1   = (const float*)d_in[8];
    const float* Wq    = (const float*)d_in[9];
    const float* Wk    = (const float*)d_in[10];
    const float* Wv    = (const float*)d_in[11];
    const float* gamma = (const float*)d_in[12];
    const float* beta  = (const float*)d_in[13];
    const float* W_ws  = (const float*)d_in[14];
    const float* b_ws  = (const float*)d_in[15];
    const float* W_vv  = (const float*)d_in[16];
    const float* b_vv  = (const float*)d_in[17];
    const float* W_vc  = (const float*)d_in[18];
    const float* b_vc  = (const float*)d_in[19];
    const float* W_out = (const float*)d_in[20];
    const float* b_out = (const float*)d_in[21];
    const int* surf_idx = (const int*)d_in[22];
    const int* velo_idx = (const int*)d_in[23];
    /* d_in[24] = first_lap_idx (arange, unused) */
    const int* closest  = (const int*)d_in[25];
    const int* labels   = (const int*)d_in[26];
    float* out = (float*)d_out;

    float *p_fx, *p_xm, *p_newf, *p_Pws, *p_Pvc, *p_Pv;
    cudaGetSymbolAddress((void**)&p_fx, g_fx);
    cudaGetSymbolAddress((void**)&p_xm, g_xm);
    cudaGetSymbolAddress((void**)&p_newf, g_newf);
    cudaGetSymbolAddress((void**)&p_Pws, g_Pws);
    cudaGetSymbolAddress((void**)&p_Pvc, g_Pvc);
    cudaGetSymbolAddress((void**)&p_Pv, g_Pv);

    cudaFuncSetAttribute(flash1_kernel, cudaFuncAttributeMaxDynamicSharedMemorySize, FLASH_SMEM);
    cudaFuncSetAttribute(attn2_kernel, cudaFuncAttributeMaxDynamicSharedMemorySize, ATTN2_SMEM);

    dim3 gBig(DIM / 64, (NPTS + 63) / 64);
    gemm_bias<<<gBig, 256>>>(x, DIM, nullptr, W_fx, DIM, b_fx, p_fx, DIM, NPTS, DIM, DIM);
    gemm_bias<<<gBig, 256>>>(x, DIM, nullptr, W_x, DIM, b_x, p_xm, DIM, NPTS, DIM, DIM);

    // grid must cover NTOK*DIM (32768) for the g_tokacc zeroing, not just NPT_TOT
    prep_kernel<<<(PREP_N + 255) / 256, 256>>>(onion, labels, closest, velo_idx, surf_idx);

    proj1_kernel<<<dim3((L1 + 63) / 64, HEADS), 256>>>(Wq1, Wk1, Wv1);
    flash1_kernel<<<dim3((L1 + 63) / 64, HEADS), 256, FLASH_SMEM>>>();

    pool_accum<<<dim3((NPT_TOT + ACC_CHUNK - 1) / ACC_CHUNK, DIM / 64), 256>>>();
    ln_kernel<<<1, DIM>>>(gamma, beta);
    attn2_kernel<<<HEADS, 256, ATTN2_SMEM>>>(Wq, Wk, Wv);
    mat_out_kernel<<<(VC * DIM + 255) / 256, 256>>>();

    gemm_bias<<<dim3(1, (NSURF + 63) / 64), 256>>>(p_xm, DIM, surf_idx, W_ws, SC, b_ws, p_Pws, SC, NSURF, SC, DIM);
    gemm_bias<<<dim3(1, (NSURF + 63) / 64), 256>>>(p_xm, DIM, surf_idx, W_vc, VC, b_vc, p_Pvc, VC, NSURF, VC, DIM);
    gemm_bias<<<dim3(1, (NVELO + 63) / 64), 256>>>(p_xm, DIM, velo_idx, W_vv, VC, b_vv, p_Pv, VC, NVELO, VC, DIM);

    feat_surf_k<<<dim3((NSURF + 63) / 64, HEADS), 256>>>(surf_idx);
    feat_velo_k<<<dim3((NVELO + 63) / 64, HEADS), 256>>>(velo_idx);

    gemm_bias<<<gBig, 256>>>(p_newf, DIM, nullptr, W_out, DIM, b_out, out, DIM, NPTS, DIM, DIM);
}

// round 9
// speedup vs baseline: 1.4323x; 1.4323x over previous
#include <cuda_runtime.h>

#define HEADS 8
#define DH 64
#define DIM 512
#define ONION 15
#define SC 4
#define NVELO 28504
#define NSURF 3682
#define NPTS 32186
#define SKEEP 3586
#define FLAP 500
#define NTOK 64
#define L1 4182
#define VC 60
#define NPT_TOT (NVELO + SKEEP)
#define PREP_N ((NTOK * DIM) > NPT_TOT ? (NTOK * DIM) : NPT_TOT)
#define ATT_SCALE 0.125f
#define LN_EPS 1e-5f
#define FLASH_SMEM (4 * 64 * 68 * 4)
#define ATTN2_SMEM (5 * 64 * 68 * 4)

__device__ float g_fx[NPTS * DIM];
__device__ float g_xm[NPTS * DIM];
__device__ float g_newf[NPTS * DIM];
__device__ float g_q1[HEADS * L1 * DH];
__device__ float g_k1[HEADS * L1 * DH];
__device__ float g_v1[HEADS * L1 * DH];
__device__ float g_o1[HEADS * L1 * DH];
__device__ int   g_tok1src[L1];
__device__ int   g_ptrow[NPT_TOT];
__device__ int   g_ptgrp[NPT_TOT];
__device__ float g_tokacc[NTOK * DIM];
__device__ float g_toknorm[NTOK * DIM];
__device__ float g_outtok[HEADS * NTOK * DH];
__device__ float g_outvelo[VC * DIM];
__device__ float g_outsurf[SC * DIM];
__device__ float g_Psc[NSURF * 64];   // cols 0..3 = Pws, 4..63 = Pvc
__device__ float g_Pv[NVELO * VC];
__device__ float g_Wsc[DIM * 64];     // [W_ws | W_vc] concat
__device__ float g_bsc[64];

// ---------------------------------------------------------------------------
// Big GEMM: C[M,512] = A[M,512] @ B[512,512] + bias. 128x128 tile, BK=16,
// 8x8 microtile, register-staged prefetch.
// ---------------------------------------------------------------------------
__global__ void __launch_bounds__(256, 2) gemm128(
    const float* __restrict__ A, const float* __restrict__ B,
    const float* __restrict__ bias, float* __restrict__ C, int M)
{
    __shared__ float As[16][132];
    __shared__ float Bs[16][132];
    int m0 = blockIdx.y * 128, n0 = blockIdx.x * 128;
    int tid = threadIdx.x, ty = tid >> 4, tx = tid & 15;
    // A staging: slot s -> row s>>2, kcol (s&3)*4 ; slots tid, tid+256
    int ar0 = tid >> 2, ak = (tid & 3) * 4, ar1 = ar0 + 64;
    // B staging: slot s -> k s>>5, n (s&31)*4 ; slots tid, tid+256
    int bk0 = tid >> 5, bn = (tid & 31) * 4, bk1 = bk0 + 8;
    float4 pA0, pA1, pB0, pB1;
    {
        int gm0 = m0 + ar0, gm1 = m0 + ar1;
        pA0 = (gm0 < M) ? *(const float4*)&A[gm0 * DIM + ak] : make_float4(0, 0, 0, 0);
        pA1 = (gm1 < M) ? *(const float4*)&A[gm1 * DIM + ak] : make_float4(0, 0, 0, 0);
        pB0 = *(const float4*)&B[bk0 * DIM + n0 + bn];
        pB1 = *(const float4*)&B[bk1 * DIM + n0 + bn];
    }
    float acc[8][8] = {};
    for (int k0 = 0; k0 < DIM; k0 += 16) {
        As[ak + 0][ar0] = pA0.x; As[ak + 1][ar0] = pA0.y;
        As[ak + 2][ar0] = pA0.z; As[ak + 3][ar0] = pA0.w;
        As[ak + 0][ar1] = pA1.x; As[ak + 1][ar1] = pA1.y;
        As[ak + 2][ar1] = pA1.z; As[ak + 3][ar1] = pA1.w;
        *(float4*)&Bs[bk0][bn] = pB0;
        *(float4*)&Bs[bk1][bn] = pB1;
        __syncthreads();
        int kn = k0 + 16;
        if (kn < DIM) {
            int gm0 = m0 + ar0, gm1 = m0 + ar1;
            pA0 = (gm0 < M) ? *(const float4*)&A[gm0 * DIM + kn + ak] : make_float4(0, 0, 0, 0);
            pA1 = (gm1 < M) ? *(const float4*)&A[gm1 * DIM + kn + ak] : make_float4(0, 0, 0, 0);
            pB0 = *(const float4*)&B[(kn + bk0) * DIM + n0 + bn];
            pB1 = *(const float4*)&B[(kn + bk1) * DIM + n0 + bn];
        }
        #pragma unroll
        for (int kk = 0; kk < 16; kk++) {
            float a[8], b[8];
            *(float4*)&a[0] = *(const float4*)&As[kk][ty * 8];
            *(float4*)&a[4] = *(const float4*)&As[kk][ty * 8 + 4];
            *(float4*)&b[0] = *(const float4*)&Bs[kk][tx * 8];
            *(float4*)&b[4] = *(const float4*)&Bs[kk][tx * 8 + 4];
            #pragma unroll
            for (int i = 0; i < 8; i++)
                #pragma unroll
                for (int j = 0; j < 8; j++)
                    acc[i][j] += a[i] * b[j];
        }
        __syncthreads();
    }
    #pragma unroll
    for (int i = 0; i < 8; i++) {
        int gm = m0 + ty * 8 + i;
        if (gm >= M) continue;
        #pragma unroll
        for (int j = 0; j < 8; j++) {
            int gn = n0 + tx * 8 + j;
            C[gm * DIM + gn] = acc[i][j] + bias[gn];
        }
    }
}

// ---------------------------------------------------------------------------
// Small GEMM (N<=64, gathered rows): C[M,N] = A[rowidx][:,K] @ B[K,N] + bias
// ---------------------------------------------------------------------------
__global__ void gemm_bias(const float* __restrict__ A, int lda,
                          const int* __restrict__ rowidx,
                          const float* __restrict__ B, int ldb,
                          const float* __restrict__ bias,
                          float* __restrict__ C, int ldc,
                          int M, int N, int K)
{
    __shared__ float As[16][68];
    __shared__ float Bs[16][68];
    int m0 = blockIdx.y * 64, n0 = blockIdx.x * 64;
    int tid = threadIdx.x, ty = tid >> 4, tx = tid & 15;
    float acc[4][4] = {};
    for (int k0 = 0; k0 < K; k0 += 16) {
        #pragma unroll
        for (int e = tid; e < 1024; e += 256) {
            int r = e >> 4, k = e & 15;
            int gm = m0 + r, gk = k0 + k;
            float v = 0.f;
            if (gm < M && gk < K) {
                int row = rowidx ? rowidx[gm] : gm;
                v = A[row * lda + gk];
            }
            As[k][r] = v;
        }
        #pragma unroll
        for (int e = tid; e < 1024; e += 256) {
            int k = e >> 6, n = e & 63;
            int gk = k0 + k, gn = n0 + n;
            Bs[k][n] = (gk < K && gn < N) ? B[gk * ldb + gn] : 0.f;
        }
        __syncthreads();
        #pragma unroll
        for (int kk = 0; kk < 16; kk++) {
            float4 a4 = *(const float4*)&As[kk][ty * 4];
            float4 b4 = *(const float4*)&Bs[kk][tx * 4];
            float ar[4] = {a4.x, a4.y, a4.z, a4.w};
            float br[4] = {b4.x, b4.y, b4.z, b4.w};
            #pragma unroll
            for (int i = 0; i < 4; i++)
                #pragma unroll
                for (int j = 0; j < 4; j++)
                    acc[i][j] += ar[i] * br[j];
        }
        __syncthreads();
    }
    #pragma unroll
    for (int i = 0; i < 4; i++) {
        int gm = m0 + ty * 4 + i;
        if (gm >= M) continue;
        #pragma unroll
        for (int j = 0; j < 4; j++) {
            int gn = n0 + tx * 4 + j;
            if (gn < N) C[gm * ldc + gn] = acc[i][j] + bias[gn];
        }
    }
}

__global__ void prep_kernel(const float* __restrict__ onion,
                            const int* __restrict__ labels,
                            const int* __restrict__ closest,
                            const int* __restrict__ velo_idx,
                            const int* __restrict__ surf_idx,
                            const float* __restrict__ W_ws,
                            const float* __restrict__ b_ws,
                            const float* __restrict__ W_vc,
                            const float* __restrict__ b_vc)
{
    int i = blockIdx.x * 256 + threadIdx.x;
    if (i < L1) g_tok1src[i] = (i < FLAP) ? velo_idx[i] : surf_idx[i - FLAP];
    if (i < NTOK * DIM) g_tokacc[i] = 0.f;
    if (i < DIM * 64) {
        int k = i >> 6, n = i & 63;
        g_Wsc[i] = (n < SC) ? W_ws[k * SC + n] : W_vc[k * VC + n - SC];
    }
    if (i < 64) g_bsc[i] = (i < SC) ? b_ws[i] : b_vc[i - SC];
    if (i >= NPT_TOT) return;
    if (i < NVELO) {
        int lab = 0;
        #pragma unroll
        for (int l = 1; l < ONION; l++)
            if (onion[l * NVELO + i] > 0.5f) lab = l;
        g_ptrow[i] = velo_idx[i];
        g_ptgrp[i] = SC + lab * SC + labels[closest[i]];
    } else {
        int j = i - NVELO;
        int sr = (j < 16) ? j : j + 96;
        g_ptrow[i] = surf_idx[sr];
        g_ptgrp[i] = labels[j];
    }
}

// q/k/v projection for attention-1, per (token-tile, head)
__global__ void proj1_kernel(const float* __restrict__ Wq1,
                             const float* __restrict__ Wk1,
                             const float* __restrict__ Wv1)
{
    __shared__ float Ts[64][68];
    __shared__ float Ws[64][68];
    int h = blockIdx.y, t0 = blockIdx.x * 64;
    int tid = threadIdx.x, ty = tid >> 4, tx = tid & 15;
    #pragma unroll
    for (int e = tid; e < 4096; e += 256) {
        int t = e >> 6, d = e & 63;
        int gt = t0 + t;
        Ts[t][d] = (gt < L1) ? g_fx[g_tok1src[gt] * DIM + h * DH + d] : 0.f;
    }
    const float* Wm[3] = {Wq1, Wk1, Wv1};
    float* Om[3] = {g_q1, g_k1, g_v1};
    #pragma unroll
    for (int m = 0; m < 3; m++) {
        __syncthreads();
        #pragma unroll
        for (int e = tid; e < 4096; e += 256) Ws[e >> 6][e & 63] = Wm[m][e];
        __syncthreads();
        float acc[4][4] = {};
        #pragma unroll
        for (int x = 0; x < 64; x++) {
            float ar[4];
            #pragma unroll
            for (int i = 0; i < 4; i++) ar[i] = Ts[ty * 4 + i][x];
            float4 b4 = *(const float4*)&Ws[x][tx * 4];
            float br[4] = {b4.x, b4.y, b4.z, b4.w};
            #pragma unroll
            for (int i = 0; i < 4; i++)
                #pragma unroll
                for (int j = 0; j < 4; j++)
                    acc[i][j] += ar[i] * br[j];
        }
        #pragma unroll
        for (int i = 0; i < 4; i++) {
            int gt = t0 + ty * 4 + i;
            if (gt >= L1) continue;
            #pragma unroll
            for (int j = 0; j < 4; j++)
                Om[m][h * (L1 * DH) + gt * DH + tx * 4 + j] = acc[i][j];
        }
    }
}

// ---------------------------------------------------------------------------
// flash attention; softmax state in registers, row reductions via shfl
// within 16-lane row groups. 3 barriers per K-tile.
// ---------------------------------------------------------------------------
__global__ void __launch_bounds__(256, 2) flash1_kernel()
{
    extern __shared__ float smem[];
    float (*Qs)[68] = (float(*)[68])smem;   // [d][q]
    float (*Ks)[68] = Qs + 64;              // [d][k]
    float (*Vs)[68] = Ks + 64;              // [k][d]
    float (*Ss)[68] = Vs + 64;              // [q][k] probs
    int h = blockIdx.y, q0 = blockIdx.x * 64;
    int tid = threadIdx.x, ty = tid >> 4, tx = tid & 15;
    const float* Qh = g_q1 + h * (L1 * DH);
    const float* Kh = g_k1 + h * (L1 * DH);
    const float* Vh = g_v1 + h * (L1 * DH);
    #pragma unroll
    for (int e = tid; e < 4096; e += 256) {
        int t = e >> 6, d = e & 63;
        int gt = q0 + t;
        Qs[d][t] = (gt < L1) ? Qh[gt * DH + d] : 0.f;
    }
    float m_i[4] = {-1e30f, -1e30f, -1e30f, -1e30f};
    float l_i[4] = {};
    float acc[4][4] = {};
    __syncthreads();
    for (int k0 = 0; k0 < L1; k0 += 64) {
        #pragma unroll
        for (int e = tid; e < 4096; e += 256) {
            int t = e >> 6, d = e & 63;
            int gt = k0 + t;
            float kv = 0.f, vv = 0.f;
            if (gt < L1) { kv = Kh[gt * DH + d]; vv = Vh[gt * DH + d]; }
            Ks[d][t] = kv;
            Vs[t][d] = vv;
        }
        __syncthreads();
        float s[4][4] = {};
        #pragma unroll
        for (int d = 0; d < 64; d++) {
            float4 a4 = *(const float4*)&Qs[d][ty * 4];
            float4 b4 = *(const float4*)&Ks[d][tx * 4];
            float ar[4] = {a4.x, a4.y, a4.z, a4.w};
            float br[4] = {b4.x, b4.y, b4.z, b4.w};
            #pragma unroll
            for (int i = 0; i < 4; i++)
                #pragma unroll
                for (int j = 0; j < 4; j++)
                    s[i][j] += ar[i] * br[j];
        }
        bool edge = (k0 + 64 > L1);
        #pragma unroll
        for (int i = 0; i < 4; i++) {
            #pragma unroll
            for (int j = 0; j < 4; j++) {
                float v = s[i][j] * ATT_SCALE;
                if (edge && (k0 + tx * 4 + j >= L1)) v = -1e30f;
                s[i][j] = v;
            }
            // row max across this thread's 4 cols, then across 16 lanes
            float rmax = fmaxf(fmaxf(s[i][0], s[i][1]), fmaxf(s[i][2], s[i][3]));
            #pragma unroll
            for (int o = 1; o < 16; o <<= 1)
                rmax = fmaxf(rmax, __shfl_xor_sync(0xffffffffu, rmax, o));
            float mnew = fmaxf(m_i[i], rmax);
            float corr = __expf(m_i[i] - mnew);
            m_i[i] = mnew;
            float rsum = 0.f;
            #pragma unroll
            for (int j = 0; j < 4; j++) {
                float p = __expf(s[i][j] - mnew);
                s[i][j] = p;
                rsum += p;
            }
            #pragma unroll
            for (int o = 1; o < 16; o <<= 1)
                rsum += __shfl_xor_sync(0xffffffffu, rsum, o);
            l_i[i] = l_i[i] * corr + rsum;
            #pragma unroll
            for (int j = 0; j < 4; j++) {
                acc[i][j] *= corr;
                Ss[ty * 4 + i][tx * 4 + j] = s[i][j];
            }
        }
        __syncthreads();
        #pragma unroll 16
        for (int kk = 0; kk < 64; kk++) {
            float4 b4 = *(const float4*)&Vs[kk][tx * 4];
            float br[4] = {b4.x, b4.y, b4.z, b4.w};
            float pr[4];
            #pragma unroll
            for (int i = 0; i < 4; i++) pr[i] = Ss[ty * 4 + i][kk];
            #pragma unroll
            for (int i = 0; i < 4; i++)
                #pragma unroll
                for (int j = 0; j < 4; j++)
                    acc[i][j] += pr[i] * br[j];
        }
        __syncthreads();
    }
    #pragma unroll
    for (int i = 0; i < 4; i++) {
        int gq = q0 + ty * 4 + i;
        if (gq >= L1) continue;
        float inv = 1.f / l_i[i];
        #pragma unroll
        for (int j = 0; j < 4; j++)
            g_o1[h * (L1 * DH) + gq * DH + tx * 4 + j] = acc[i][j] * inv;
    }
}

// pooled-token accumulation via smem atomics
#define ACC_CHUNK 1024
__global__ void pool_accum()
{
    __shared__ float sa[64][64];
    int d0 = blockIdx.y * 64, p0 = blockIdx.x * ACC_CHUNK;
    int tid = threadIdx.x, dd = tid & 63, q4 = tid >> 6;
    #pragma unroll
    for (int e = tid; e < 4096; e += 256) ((float*)sa)[e] = 0.f;
    __syncthreads();
    int pend = min(p0 + ACC_CHUNK, NPT_TOT);
    for (int p = p0 + q4; p < pend; p += 4) {
        float v = g_fx[g_ptrow[p] * DIM + d0 + dd];
        atomicAdd(&sa[g_ptgrp[p]][dd], v);
    }
    __syncthreads();
    #pragma unroll
    for (int e = tid; e < 4096; e += 256) {
        int g = e >> 6, d = e & 63;
        float v = sa[g][d];
        if (v != 0.f) atomicAdd(&g_tokacc[g * DIM + d0 + d], v);
    }
}

// layernorm across token axis (per channel), then gamma[t]/beta[t]
__global__ void ln_kernel(const float* __restrict__ gamma,
                          const float* __restrict__ beta)
{
    int d = threadIdx.x;
    const float n_s = 1.f / (float)SKEEP, n_v = 1.f / (float)NVELO;
    float s = 0.f;
    #pragma unroll
    for (int t = 0; t < NTOK; t++)
        s += g_tokacc[t * DIM + d] * ((t < SC) ? n_s : n_v);
    float mu = s * (1.f / NTOK);
    float v2 = 0.f;
    #pragma unroll
    for (int t = 0; t < NTOK; t++) {
        float dv = g_tokacc[t * DIM + d] * ((t < SC) ? n_s : n_v) - mu;
        v2 += dv * dv;
    }
    float inv = rsqrtf(v2 * (1.f / NTOK) + LN_EPS);
    #pragma unroll
    for (int t = 0; t < NTOK; t++) {
        float val = g_tokacc[t * DIM + d] * ((t < SC) ? n_s : n_v);
        g_toknorm[t * DIM + d] = (val - mu) * inv * gamma[t] + beta[t];
    }
}

// attention over the 64 pooled tokens; one block per head
__global__ void attn2_kernel(const float* __restrict__ Wq,
                             const float* __restrict__ Wk,
                             const float* __restrict__ Wv)
{
    extern __shared__ float sm2[];
    float (*tk)[68] = (float(*)[68])sm2;
    float (*qs)[68] = tk + 64;
    float (*ks)[68] = qs + 64;
    float (*vs)[68] = ks + 64;
    float (*ss)[68] = vs + 64;
    int h = blockIdx.x, tid = threadIdx.x;
    #pragma unroll
    for (int e = tid; e < 4096; e += 256) {
        int t = e >> 6, d = e & 63;
        tk[t][d] = g_toknorm[t * DIM + h * DH + d];
    }
    __syncthreads();
    #pragma unroll
    for (int e = tid; e < 4096; e += 256) {
        int t = e >> 6, d = e & 63;
        float aq = 0.f, ak = 0.f, av = 0.f;
        for (int x = 0; x < 64; x++) {
            float tv = tk[t][x];
            aq += tv * Wq[x * 64 + d];
            ak += tv * Wk[x * 64 + d];
            av += tv * Wv[x * 64 + d];
        }
        qs[t][d] = aq; ks[t][d] = ak; vs[t][d] = av;
    }
    __syncthreads();
    #pragma unroll
    for (int e = tid; e < 4096; e += 256) {
        int t = e >> 6, u = e & 63;
        float sv = 0.f;
        for (int d = 0; d < 64; d++) sv += qs[t][d] * ks[u][d];
        ss[t][u] = sv * ATT_SCALE;
    }
    __syncthreads();
    if (tid < 64) {
        float mx = -1e30f;
        for (int j = 0; j < 64; j++) mx = fmaxf(mx, ss[tid][j]);
        float sum = 0.f;
        for (int j = 0; j < 64; j++) {
            float p = __expf(ss[tid][j] - mx);
            ss[tid][j] = p; sum += p;
        }
        float inv = 1.f / sum;
        for (int j = 0; j < 64; j++) ss[tid][j] *= inv;
    }
    __syncthreads();
    #pragma unroll
    for (int e = tid; e < 4096; e += 256) {
        int t = e >> 6, d = e & 63;
        float o = 0.f;
        for (int u = 0; u < 64; u++) o += ss[t][u] * vs[u][d];
        g_outtok[h * (NTOK * DH) + t * DH + d] = o;
    }
}

// reshape out_tok into out_surf (4x512) and out_velo (60x512)
__global__ void mat_out_kernel()
{
    int i = blockIdx.x * 256 + threadIdx.x;
    if (i < VC * DIM) {
        int r = i >> 9, d = i & 511;
        g_outvelo[i] = g_outtok[(d >> 6) * 4096 + (SC + r) * 64 + (d & 63)];
    }
    if (i < SC * DIM)
        g_outsurf[i] = g_outtok[(i >> 8) * 4096 + (((i >> 6) & 3) << 6) + (i & 63)];
}

// feat_surf = 0.5*(Pws@out_surf + Pvc@out_velo) + surf_first_lap -> scatter
__global__ void feat_surf_k(const int* __restrict__ surf_idx)
{
    __shared__ float Pw[64][4];
    __shared__ float Pc[64][60];
    __shared__ float Osf[4][64];
    __shared__ float Ovl[60][64];
    int i0 = blockIdx.x * 64, h = blockIdx.y, d0 = h * 64;
    int tid = threadIdx.x, ty = tid >> 4, tx = tid & 15;
    for (int e = tid; e < 64 * 4; e += 256) {
        int r = e >> 2, c = e & 3;
        int gi = i0 + r;
        Pw[r][c] = (gi < NSURF) ? g_Psc[gi * 64 + c] : 0.f;
    }
    for (int e = tid; e < 64 * 60; e += 256) {
        int r = e / 60, c = e % 60;
        int gi = i0 + r;
        Pc[r][c] = (gi < NSURF) ? g_Psc[gi * 64 + 4 + c] : 0.f;
    }
    for (int e = tid; e < 4 * 64; e += 256)
        Osf[e >> 6][e & 63] = g_outsurf[(e >> 6) * DIM + d0 + (e & 63)];
    for (int e = tid; e < 60 * 64; e += 256)
        Ovl[e >> 6][e & 63] = g_outvelo[(e >> 6) * DIM + d0 + (e & 63)];
    __syncthreads();
    float acc[4][4] = {};
    #pragma unroll
    for (int c = 0; c < 4; c++) {
        float ar[4];
        #pragma unroll
        for (int i = 0; i < 4; i++) ar[i] = Pw[ty * 4 + i][c];
        #pragma unroll
        for (int i = 0; i < 4; i++)
            #pragma unroll
            for (int j = 0; j < 4; j++)
                acc[i][j] += ar[i] * Osf[c][tx * 4 + j];
    }
    #pragma unroll
    for (int r = 0; r < 60; r++) {
        float ar[4];
        #pragma unroll
        for (int i = 0; i < 4; i++) ar[i] = Pc[ty * 4 + i][r];
        #pragma unroll
        for (int i = 0; i < 4; i++)
            #pragma unroll
            for (int j = 0; j < 4; j++)
                acc[i][j] += ar[i] * Ovl[r][tx * 4 + j];
    }
    #pragma unroll
    for (int i = 0; i < 4; i++) {
        int gi = i0 + ty * 4 + i;
        if (gi >= NSURF) continue;
        int orow = surf_idx[gi];
        #pragma unroll
        for (int j = 0; j < 4; j++) {
            int dd = tx * 4 + j;
            g_newf[orow * DIM + d0 + dd] =
                0.5f * acc[i][j] + g_o1[h * (L1 * DH) + (FLAP + gi) * DH + dd];
        }
    }
}

// feat_velo = Pv@out_velo (+ velo_first_lap rows<500) -> scatter
__global__ void feat_velo_k(const int* __restrict__ velo_idx)
{
    __shared__ float Pv_s[64][60];
    __shared__ float Ovl[60][64];
    int i0 = blockIdx.x * 64, h = blockIdx.y, d0 = h * 64;
    int tid = threadIdx.x, ty = tid >> 4, tx = tid & 15;
    for (int e = tid; e < 64 * 60; e += 256) {
        int r = e / 60, c = e % 60;
        int gi = i0 + r;
        Pv_s[r][c] = (gi < NVELO) ? g_Pv[gi * 60 + c] : 0.f;
    }
    for (int e = tid; e < 60 * 64; e += 256)
        Ovl[e >> 6][e & 63] = g_outvelo[(e >> 6) * DIM + d0 + (e & 63)];
    __syncthreads();
    float acc[4][4] = {};
    #pragma unroll
    for (int r = 0; r < 60; r++) {
        float ar[4];
        #pragma unroll
        for (int i = 0; i < 4; i++) ar[i] = Pv_s[ty * 4 + i][r];
        #pragma unroll
        for (int i = 0; i < 4; i++)
            #pragma unroll
            for (int j = 0; j < 4; j++)
                acc[i][j] += ar[i] * Ovl[r][tx * 4 + j];
    }
    #pragma unroll
    for (int i = 0; i < 4; i++) {
        int gi = i0 + ty * 4 + i;
        if (gi >= NVELO) continue;
        int orow = velo_idx[gi];
        #pragma unroll
        for (int j = 0; j < 4; j++) {
            int dd = tx * 4 + j;
            float v = acc[i][j];
            if (gi < FLAP) v += g_o1[h * (L1 * DH) + gi * DH + dd];
            g_newf[orow * DIM + d0 + dd] = v;
        }
    }
}

extern "C" void kernel_launch(void* const* d_in, const int* in_sizes, int n_in,
                              void* d_out, int out_size)
{
    (void)in_sizes; (void)n_in; (void)out_size;
    const float* x     = (const float*)d_in[0];
    const float* onion = (const float*)d_in[1];
    const float* W_fx  = (const float*)d_in[2];
    const float* b_fx  = (const float*)d_in[3];
    const float* W_x   = (const float*)d_in[4];
    const float* b_x   = (const float*)d_in[5];
    const float* Wq1   = (const float*)d_in[6];
    const float* Wk1   = (const float*)d_in[7];
    const float* Wv1   = (const float*)d_in[8];
    const float* Wq    = (const float*)d_in[9];
    const float* Wk    = (const float*)d_in[10];
    const float* Wv    = (const float*)d_in[11];
    const float* gamma = (const float*)d_in[12];
    const float* beta  = (const float*)d_in[13];
    const float* W_ws  = (const float*)d_in[14];
    const float* b_ws  = (const float*)d_in[15];
    const float* W_vv  = (const float*)d_in[16];
    const float* b_vv  = (const float*)d_in[17];
    const float* W_vc  = (const float*)d_in[18];
    const float* b_vc  = (const float*)d_in[19];
    const float* W_out = (const float*)d_in[20];
    const float* b_out = (const float*)d_in[21];
    const int* surf_idx = (const int*)d_in[22];
    const int* velo_idx = (const int*)d_in[23];
    /* d_in[24] = first_lap_idx (arange, unused) */
    const int* closest  = (const int*)d_in[25];
    const int* labels   = (const int*)d_in[26];
    float* out = (float*)d_out;

    float *p_fx, *p_xm, *p_newf, *p_Psc, *p_Pv, *p_Wsc, *p_bsc;
    cudaGetSymbolAddress((void**)&p_fx, g_fx);
    cudaGetSymbolAddress((void**)&p_xm, g_xm);
    cudaGetSymbolAddress((void**)&p_newf, g_newf);
    cudaGetSymbolAddress((void**)&p_Psc, g_Psc);
    cudaGetSymbolAddress((void**)&p_Pv, g_Pv);
    cudaGetSymbolAddress((void**)&p_Wsc, g_Wsc);
    cudaGetSymbolAddress((void**)&p_bsc, g_bsc);

    cudaFuncSetAttribute(flash1_kernel, cudaFuncAttributeMaxDynamicSharedMemorySize, FLASH_SMEM);
    cudaFuncSetAttribute(attn2_kernel, cudaFuncAttributeMaxDynamicSharedMemorySize, ATTN2_SMEM);

    dim3 g128(DIM / 128, (NPTS + 127) / 128);
    gemm128<<<g128, 256>>>(x, W_fx, b_fx, p_fx, NPTS);
    gemm128<<<g128, 256>>>(x, W_x, b_x, p_xm, NPTS);

    prep_kernel<<<(PREP_N + 255) / 256, 256>>>(onion, labels, closest, velo_idx, surf_idx,
                                               W_ws, b_ws, W_vc, b_vc);

    proj1_kernel<<<dim3((L1 + 63) / 64, HEADS), 256>>>(Wq1, Wk1, Wv1);
    flash1_kernel<<<dim3((L1 + 63) / 64, HEADS), 256, FLASH_SMEM>>>();

    pool_accum<<<dim3((NPT_TOT + ACC_CHUNK - 1) / ACC_CHUNK, DIM / 64), 256>>>();
    ln_kernel<<<1, DIM>>>(gamma, beta);
    attn2_kernel<<<HEADS, 256, ATTN2_SMEM>>>(Wq, Wk, Wv);
    mat_out_kernel<<<(VC * DIM + 255) / 256, 256>>>();

    // fused [W_ws|W_vc] (N=64) for surf rows; Pv (N=60) for velo rows
    gemm_bias<<<dim3(1, (NSURF + 63) / 64), 256>>>(p_xm, DIM, surf_idx, p_Wsc, 64, p_bsc, p_Psc, 64, NSURF, 64, DIM);
    gemm_bias<<<dim3(1, (NVELO + 63) / 64), 256>>>(p_xm, DIM, velo_idx, W_vv, VC, b_vv, p_Pv, VC, NVELO, VC, DIM);

    feat_surf_k<<<dim3((NSURF + 63) / 64, HEADS), 256>>>(surf_idx);
    feat_velo_k<<<dim3((NVELO + 63) / 64, HEADS), 256>>>(velo_idx);

    gemm128<<<g128, 256>>>(p_newf, W_out, b_out, out, NPTS);
}

// round 11
// speedup vs baseline: 1.9377x; 1.3528x over previous
#include <cuda_runtime.h>
#include <cuda_bf16.h>
#include <cstdint>

#define HEADS 8
#define DH 64
#define DIM 512
#define ONION 15
#define SC 4
#define NVELO 28504
#define NSURF 3682
#define NPTS 32186
#define SKEEP 3586
#define FLAP 500
#define NTOK 64
#define L1 4182
#define VC 60
#define NPT_TOT (NVELO + SKEEP)
#define PREP_N ((NTOK * DIM) > NPT_TOT ? (NTOK * DIM) : NPT_TOT)
#define ATT_SCALE 0.125f
#define LN_EPS 1e-5f
#define FLASH_SMEM (4 * 64 * 68 * 4)
#define ATTN2_SMEM (5 * 64 * 68 * 4)

// ---------------- scratch ----------------
__device__ float g_fx[NPTS * DIM];
__device__ float g_xm[NPTS * DIM];
__device__ float g_newf[NPTS * DIM];
__device__ float g_q1[HEADS * L1 * DH];
__device__ float g_k1[HEADS * L1 * DH];
__device__ float g_v1[HEADS * L1 * DH];
__device__ float g_o1[HEADS * L1 * DH];
__device__ int   g_tok1src[L1];
__device__ int   g_ptrow[NPT_TOT];
__device__ int   g_ptgrp[NPT_TOT];
__device__ float g_tokacc[NTOK * DIM];
__device__ float g_toknorm[NTOK * DIM];
__device__ float g_outtok[HEADS * NTOK * DH];
__device__ float g_outvelo[VC * DIM];
__device__ float g_outsurf[SC * DIM];
__device__ float g_Psc[NSURF * 64];
__device__ float g_Pv[NVELO * VC];
__device__ float g_Wsc[DIM * 64];
__device__ float g_bsc[64];
// split-bf16 planes
__device__ __nv_bfloat16 g_xh[NPTS * DIM];
__device__ __nv_bfloat16 g_xl[NPTS * DIM];
__device__ __nv_bfloat16 g_nfh[NPTS * DIM];
__device__ __nv_bfloat16 g_nfl[NPTS * DIM];
__device__ __nv_bfloat16 g_Wth[3 * DIM * DIM];  // transposed [N,K] hi
__device__ __nv_bfloat16 g_Wtl[3 * DIM * DIM];  // transposed [N,K] lo

// ---------------- sm_80-class PTX helpers (no arch-feature suffix) --------
__device__ __forceinline__ uint32_t smem_u32(const void* p) {
    uint32_t a;
    asm("{ .reg .u64 t; cvta.to.shared.u64 t, %1; cvt.u32.u64 %0, t; }" : "=r"(a) : "l"(p));
    return a;
}
#define CPA16(dst, src, sz) \
    asm volatile("cp.async.cg.shared.global [%0], [%1], 16, %2;" \
                 :: "r"(dst), "l"(src), "r"(sz) : "memory")
#define CPA_COMMIT() asm volatile("cp.async.commit_group;" ::: "memory")
#define CPA_WAIT0()  asm volatile("cp.async.wait_group 0;" ::: "memory")
#define LDSM4(r, addr) \
    asm volatile("ldmatrix.sync.aligned.m8n8.x4.shared.b16 {%0,%1,%2,%3}, [%4];" \
                 : "=r"((r)[0]), "=r"((r)[1]), "=r"((r)[2]), "=r"((r)[3]) : "r"(addr))
#define MMA16816(c, a, b0v, b1v) \
    asm volatile("mma.sync.aligned.m16n8k16.row.col.f32.bf16.bf16.f32 " \
                 "{%0,%1,%2,%3},{%4,%5,%6,%7},{%8,%9},{%0,%1,%2,%3};" \
                 : "+f"((c)[0]), "+f"((c)[1]), "+f"((c)[2]), "+f"((c)[3]) \
                 : "r"((a)[0]), "r"((a)[1]), "r"((a)[2]), "r"((a)[3]), "r"(b0v), "r"(b1v))

// ---------------------------------------------------------------------------
// split-bf16 HMMA GEMM: C[M,512] = (Ah+Al) @ (Bh+Bl)^T' + bias
// A global [M,K] planes; B global = transposed weight [N,K] planes.
// CTA tile 128x128, BK=32, 8 warps (4x2) of 32x64. Double-buffered cp.async.
// smem per buffer: AH|AL|BH|BL, each 128 rows x 32 bf16, row stride 80B.
// ---------------------------------------------------------------------------
#define PLANE_B 10240
#define BUF_B   (4 * PLANE_B)
#define GMMA_SMEM (2 * BUF_B)

__device__ __forceinline__ void fill_chunk(
    uint32_t sb, const __nv_bfloat16* __restrict__ Ah, const __nv_bfloat16* __restrict__ Al,
    const __nv_bfloat16* __restrict__ Bh, const __nv_bfloat16* __restrict__ Bl,
    int m0, int n0, int k0, int M, int tid)
{
    #pragma unroll
    for (int hf = 0; hf < 2; hf++) {
        int s = tid + hf * 256;          // 0..511
        int r = s >> 2, v = s & 3;       // row, 16B-vec within 32-k row
        uint32_t off = (uint32_t)(r * 80 + v * 16);
        int gm = m0 + r;
        int szA = (gm < M) ? 16 : 0;
        int gmc = (gm < M) ? gm : (M - 1);
        CPA16(sb + off,                 Ah + (size_t)gmc * DIM + k0 + v * 8, szA);
        CPA16(sb + PLANE_B + off,       Al + (size_t)gmc * DIM + k0 + v * 8, szA);
        CPA16(sb + 2 * PLANE_B + off,   Bh + (size_t)(n0 + r) * DIM + k0 + v * 8, 16);
        CPA16(sb + 3 * PLANE_B + off,   Bl + (size_t)(n0 + r) * DIM + k0 + v * 8, 16);
    }
}

__global__ void __launch_bounds__(256, 2) gemm_mma(
    const __nv_bfloat16* __restrict__ Ah, const __nv_bfloat16* __restrict__ Al,
    const __nv_bfloat16* __restrict__ Bth, const __nv_bfloat16* __restrict__ Btl,
    const float* __restrict__ bias, float* __restrict__ C, int M)
{
    extern __shared__ char smbuf[];
    uint32_t smb = smem_u32(smbuf);
    int tid = threadIdx.x, lane = tid & 31, wid = tid >> 5;
    int wy = wid & 3, wx = wid >> 2;           // warp tile: rows wy*32, cols wx*64
    int m0 = blockIdx.y * 128, n0 = blockIdx.x * 128;

    float acc[2][8][4] = {};
    uint32_t aBase = (uint32_t)((wy * 32 + (lane & 15)) * 80 + (lane >> 4) * 16);
    uint32_t bBase = (uint32_t)((wx * 64 + (lane & 15)) * 80 + (lane >> 4) * 16);

    fill_chunk(smb, Ah, Al, Bth, Btl, m0, n0, 0, M, tid);
    CPA_COMMIT();

    for (int ch = 0; ch < 16; ch++) {
        uint32_t sb = smb + (uint32_t)(ch & 1) * BUF_B;
        CPA_WAIT0();
        __syncthreads();
        if (ch < 15) {
            fill_chunk(smb + (uint32_t)((ch + 1) & 1) * BUF_B,
                       Ah, Al, Bth, Btl, m0, n0, (ch + 1) * 32, M, tid);
            CPA_COMMIT();
        }
        uint32_t AH = sb, AL = sb + PLANE_B, BH = sb + 2 * PLANE_B, BL = sb + 3 * PLANE_B;
        #pragma unroll
        for (int ks = 0; ks < 2; ks++) {
            uint32_t ko = (uint32_t)(ks * 32);
            uint32_t ah[2][4], al[2][4];
            LDSM4(ah[0], AH + aBase + ko);
            LDSM4(ah[1], AH + aBase + 1280 + ko);
            LDSM4(al[0], AL + aBase + ko);
            LDSM4(al[1], AL + aBase + 1280 + ko);
            #pragma unroll
            for (int np = 0; np < 4; np++) {
                uint32_t bh[4], bl[4];
                uint32_t boff = bBase + (uint32_t)(np * 16 * 80) + ko;
                LDSM4(bh, BH + boff);
                LDSM4(bl, BL + boff);
                #pragma unroll
                for (int mt = 0; mt < 2; mt++) {
                    float* c0 = acc[mt][np * 2];
                    float* c1 = acc[mt][np * 2 + 1];
                    MMA16816(c0, ah[mt], bh[0], bh[2]);
                    MMA16816(c0, ah[mt], bl[0], bl[2]);
                    MMA16816(c0, al[mt], bh[0], bh[2]);
                    MMA16816(c1, ah[mt], bh[1], bh[3]);
                    MMA16816(c1, ah[mt], bl[1], bl[3]);
                    MMA16816(c1, al[mt], bh[1], bh[3]);
                }
            }
        }
        __syncthreads();
    }

    int g = lane >> 2, tig = lane & 3;
    #pragma unroll
    for (int mt = 0; mt < 2; mt++) {
        int r0 = m0 + wy * 32 + mt * 16 + g;
        #pragma unroll
        for (int nt = 0; nt < 8; nt++) {
            int col = n0 + wx * 64 + nt * 8 + tig * 2;
            float2 b2 = *(const float2*)&bias[col];
            if (r0 < M) {
                float2 v = make_float2(acc[mt][nt][0] + b2.x, acc[mt][nt][1] + b2.y);
                *(float2*)&C[(size_t)r0 * DIM + col] = v;
            }
            if (r0 + 8 < M) {
                float2 v = make_float2(acc[mt][nt][2] + b2.x, acc[mt][nt][3] + b2.y);
                *(float2*)&C[(size_t)(r0 + 8) * DIM + col] = v;
            }
        }
    }
}

// fp32 -> (hi, lo) bf16 planes
__global__ void conv_split(const float* __restrict__ s,
                           __nv_bfloat16* __restrict__ h,
                           __nv_bfloat16* __restrict__ l, int n4)
{
    int i = blockIdx.x * 256 + threadIdx.x;
    if (i >= n4) return;
    float4 v = *(const float4*)&s[i * 4];
    float a[4] = {v.x, v.y, v.z, v.w};
    #pragma unroll
    for (int j = 0; j < 4; j++) {
        __nv_bfloat16 hh = __float2bfloat16(a[j]);
        h[i * 4 + j] = hh;
        l[i * 4 + j] = __float2bfloat16(a[j] - __bfloat162float(hh));
    }
}

// W[K,N] fp32 -> transposed [N,K] (hi, lo) bf16
__global__ void conv_wt(const float* __restrict__ W,
                        __nv_bfloat16* __restrict__ th,
                        __nv_bfloat16* __restrict__ tl)
{
    int i = blockIdx.x * 256 + threadIdx.x;
    if (i >= DIM * DIM) return;
    int k = i >> 9, n = i & 511;
    float v = W[i];
    __nv_bfloat16 hh = __float2bfloat16(v);
    th[n * DIM + k] = hh;
    tl[n * DIM + k] = __float2bfloat16(v - __bfloat162float(hh));
}

// ---------------------------------------------------------------------------
// small gathered GEMM (N<=64)
// ---------------------------------------------------------------------------
__global__ void gemm_bias(const float* __restrict__ A, int lda,
                          const int* __restrict__ rowidx,
                          const float* __restrict__ B, int ldb,
                          const float* __restrict__ bias,
                          float* __restrict__ C, int ldc,
                          int M, int N, int K)
{
    __shared__ float As[16][68];
    __shared__ float Bs[16][68];
    int m0 = blockIdx.y * 64, n0 = blockIdx.x * 64;
    int tid = threadIdx.x, ty = tid >> 4, tx = tid & 15;
    float acc[4][4] = {};
    for (int k0 = 0; k0 < K; k0 += 16) {
        #pragma unroll
        for (int e = tid; e < 1024; e += 256) {
            int r = e >> 4, k = e & 15;
            int gm = m0 + r, gk = k0 + k;
            float v = 0.f;
            if (gm < M && gk < K) {
                int row = rowidx ? rowidx[gm] : gm;
                v = A[row * lda + gk];
            }
            As[k][r] = v;
        }
        #pragma unroll
        for (int e = tid; e < 1024; e += 256) {
            int k = e >> 6, n = e & 63;
            int gk = k0 + k, gn = n0 + n;
            Bs[k][n] = (gk < K && gn < N) ? B[gk * ldb + gn] : 0.f;
        }
        __syncthreads();
        #pragma unroll
        for (int kk = 0; kk < 16; kk++) {
            float4 a4 = *(const float4*)&As[kk][ty * 4];
            float4 b4 = *(const float4*)&Bs[kk][tx * 4];
            float ar[4] = {a4.x, a4.y, a4.z, a4.w};
            float br[4] = {b4.x, b4.y, b4.z, b4.w};
            #pragma unroll
            for (int i = 0; i < 4; i++)
                #pragma unroll
                for (int j = 0; j < 4; j++)
                    acc[i][j] += ar[i] * br[j];
        }
        __syncthreads();
    }
    #pragma unroll
    for (int i = 0; i < 4; i++) {
        int gm = m0 + ty * 4 + i;
        if (gm >= M) continue;
        #pragma unroll
        for (int j = 0; j < 4; j++) {
            int gn = n0 + tx * 4 + j;
            if (gn < N) C[gm * ldc + gn] = acc[i][j] + bias[gn];
        }
    }
}

__global__ void prep_kernel(const float* __restrict__ onion,
                            const int* __restrict__ labels,
                            const int* __restrict__ closest,
                            const int* __restrict__ velo_idx,
                            const int* __restrict__ surf_idx,
                            const float* __restrict__ W_ws,
                            const float* __restrict__ b_ws,
                            const float* __restrict__ W_vc,
                            const float* __restrict__ b_vc)
{
    int i = blockIdx.x * 256 + threadIdx.x;
    if (i < L1) g_tok1src[i] = (i < FLAP) ? velo_idx[i] : surf_idx[i - FLAP];
    if (i < NTOK * DIM) g_tokacc[i] = 0.f;
    if (i < DIM * 64) {
        int k = i >> 6, n = i & 63;
        g_Wsc[i] = (n < SC) ? W_ws[k * SC + n] : W_vc[k * VC + n - SC];
    }
    if (i < 64) g_bsc[i] = (i < SC) ? b_ws[i] : b_vc[i - SC];
    if (i >= NPT_TOT) return;
    if (i < NVELO) {
        int lab = 0;
        #pragma unroll
        for (int l = 1; l < ONION; l++)
            if (onion[l * NVELO + i] > 0.5f) lab = l;
        g_ptrow[i] = velo_idx[i];
        g_ptgrp[i] = SC + lab * SC + labels[closest[i]];
    } else {
        int j = i - NVELO;
        int sr = (j < 16) ? j : j + 96;
        g_ptrow[i] = surf_idx[sr];
        g_ptgrp[i] = labels[j];
    }
}

__global__ void proj1_kernel(const float* __restrict__ Wq1,
                             const float* __restrict__ Wk1,
                             const float* __restrict__ Wv1)
{
    __shared__ float Ts[64][68];
    __shared__ float Ws[64][68];
    int h = blockIdx.y, t0 = blockIdx.x * 64;
    int tid = threadIdx.x, ty = tid >> 4, tx = tid & 15;
    #pragma unroll
    for (int e = tid; e < 4096; e += 256) {
        int t = e >> 6, d = e & 63;
        int gt = t0 + t;
        Ts[t][d] = (gt < L1) ? g_fx[g_tok1src[gt] * DIM + h * DH + d] : 0.f;
    }
    const float* Wm[3] = {Wq1, Wk1, Wv1};
    float* Om[3] = {g_q1, g_k1, g_v1};
    #pragma unroll
    for (int m = 0; m < 3; m++) {
        __syncthreads();
        #pragma unroll
        for (int e = tid; e < 4096; e += 256) Ws[e >> 6][e & 63] = Wm[m][e];
        __syncthreads();
        float acc[4][4] = {};
        #pragma unroll
        for (int x = 0; x < 64; x++) {
            float ar[4];
            #pragma unroll
            for (int i = 0; i < 4; i++) ar[i] = Ts[ty * 4 + i][x];
            float4 b4 = *(const float4*)&Ws[x][tx * 4];
            float br[4] = {b4.x, b4.y, b4.z, b4.w};
            #pragma unroll
            for (int i = 0; i < 4; i++)
                #pragma unroll
                for (int j = 0; j < 4; j++)
                    acc[i][j] += ar[i] * br[j];
        }
        #pragma unroll
        for (int i = 0; i < 4; i++) {
            int gt = t0 + ty * 4 + i;
            if (gt >= L1) continue;
            #pragma unroll
            for (int j = 0; j < 4; j++)
                Om[m][h * (L1 * DH) + gt * DH + tx * 4 + j] = acc[i][j];
        }
    }
}

__global__ void __launch_bounds__(256, 2) flash1_kernel()
{
    extern __shared__ float smem[];
    float (*Qs)[68] = (float(*)[68])smem;
    float (*Ks)[68] = Qs + 64;
    float (*Vs)[68] = Ks + 64;
    float (*Ss)[68] = Vs + 64;
    int h = blockIdx.y, q0 = blockIdx.x * 64;
    int tid = threadIdx.x, ty = tid >> 4, tx = tid & 15;
    const float* Qh = g_q1 + h * (L1 * DH);
    const float* Kh = g_k1 + h * (L1 * DH);
    const float* Vh = g_v1 + h * (L1 * DH);
    #pragma unroll
    for (int e = tid; e < 4096; e += 256) {
        int t = e >> 6, d = e & 63;
        int gt = q0 + t;
        Qs[d][t] = (gt < L1) ? Qh[gt * DH + d] : 0.f;
    }
    float m_i[4] = {-1e30f, -1e30f, -1e30f, -1e30f};
    float l_i[4] = {};
    float acc[4][4] = {};
    __syncthreads();
    for (int k0 = 0; k0 < L1; k0 += 64) {
        #pragma unroll
        for (int e = tid; e < 4096; e += 256) {
            int t = e >> 6, d = e & 63;
            int gt = k0 + t;
            float kv = 0.f, vv = 0.f;
            if (gt < L1) { kv = Kh[gt * DH + d]; vv = Vh[gt * DH + d]; }
            Ks[d][t] = kv;
            Vs[t][d] = vv;
        }
        __syncthreads();
        float s[4][4] = {};
        #pragma unroll
        for (int d = 0; d < 64; d++) {
            float4 a4 = *(const float4*)&Qs[d][ty * 4];
            float4 b4 = *(const float4*)&Ks[d][tx * 4];
            float ar[4] = {a4.x, a4.y, a4.z, a4.w};
            float br[4] = {b4.x, b4.y, b4.z, b4.w};
            #pragma unroll
            for (int i = 0; i < 4; i++)
                #pragma unroll
                for (int j = 0; j < 4; j++)
                    s[i][j] += ar[i] * br[j];
        }
        bool edge = (k0 + 64 > L1);
        #pragma unroll
        for (int i = 0; i < 4; i++) {
            #pragma unroll
            for (int j = 0; j < 4; j++) {
                float v = s[i][j] * ATT_SCALE;
                if (edge && (k0 + tx * 4 + j >= L1)) v = -1e30f;
                s[i][j] = v;
            }
            float rmax = fmaxf(fmaxf(s[i][0], s[i][1]), fmaxf(s[i][2], s[i][3]));
            #pragma unroll
            for (int o = 1; o < 16; o <<= 1)
                rmax = fmaxf(rmax, __shfl_xor_sync(0xffffffffu, rmax, o));
            float mnew = fmaxf(m_i[i], rmax);
            float corr = __expf(m_i[i] - mnew);
            m_i[i] = mnew;
            float rsum = 0.f;
            #pragma unroll
            for (int j = 0; j < 4; j++) {
                float p = __expf(s[i][j] - mnew);
                s[i][j] = p;
                rsum += p;
            }
            #pragma unroll
            for (int o = 1; o < 16; o <<= 1)
                rsum += __shfl_xor_sync(0xffffffffu, rsum, o);
            l_i[i] = l_i[i] * corr + rsum;
            #pragma unroll
            for (int j = 0; j < 4; j++) {
                acc[i][j] *= corr;
                Ss[ty * 4 + i][tx * 4 + j] = s[i][j];
            }
        }
        __syncthreads();
        #pragma unroll 16
        for (int kk = 0; kk < 64; kk++) {
            float4 b4 = *(const float4*)&Vs[kk][tx * 4];
            float br[4] = {b4.x, b4.y, b4.z, b4.w};
            float pr[4];
            #pragma unroll
            for (int i = 0; i < 4; i++) pr[i] = Ss[ty * 4 + i][kk];
            #pragma unroll
            for (int i = 0; i < 4; i++)
                #pragma unroll
                for (int j = 0; j < 4; j++)
                    acc[i][j] += pr[i] * br[j];
        }
        __syncthreads();
    }
    #pragma unroll
    for (int i = 0; i < 4; i++) {
        int gq = q0 + ty * 4 + i;
        if (gq >= L1) continue;
        float inv = 1.f / l_i[i];
        #pragma unroll
        for (int j = 0; j < 4; j++)
            g_o1[h * (L1 * DH) + gq * DH + tx * 4 + j] = acc[i][j] * inv;
    }
}

#define ACC_CHUNK 1024
__global__ void pool_accum()
{
    __shared__ float sa[64][64];
    int d0 = blockIdx.y * 64, p0 = blockIdx.x * ACC_CHUNK;
    int tid = threadIdx.x, dd = tid & 63, q4 = tid >> 6;
    #pragma unroll
    for (int e = tid; e < 4096; e += 256) ((float*)sa)[e] = 0.f;
    __syncthreads();
    int pend = min(p0 + ACC_CHUNK, NPT_TOT);
    for (int p = p0 + q4; p < pend; p += 4) {
        float v = g_fx[g_ptrow[p] * DIM + d0 + dd];
        atomicAdd(&sa[g_ptgrp[p]][dd], v);
    }
    __syncthreads();
    #pragma unroll
    for (int e = tid; e < 4096; e += 256) {
        int g = e >> 6, d = e & 63;
        float v = sa[g][d];
        if (v != 0.f) atomicAdd(&g_tokacc[g * DIM + d0 + d], v);
    }
}

__global__ void ln_kernel(const float* __restrict__ gamma,
                          const float* __restrict__ beta)
{
    int d = threadIdx.x;
    const float n_s = 1.f / (float)SKEEP, n_v = 1.f / (float)NVELO;
    float s = 0.f;
    #pragma unroll
    for (int t = 0; t < NTOK; t++)
        s += g_tokacc[t * DIM + d] * ((t < SC) ? n_s : n_v);
    float mu = s * (1.f / NTOK);
    float v2 = 0.f;
    #pragma unroll
    for (int t = 0; t < NTOK; t++) {
        float dv = g_tokacc[t * DIM + d] * ((t < SC) ? n_s : n_v) - mu;
        v2 += dv * dv;
    }
    float inv = rsqrtf(v2 * (1.f / NTOK) + LN_EPS);
    #pragma unroll
    for (int t = 0; t < NTOK; t++) {
        float val = g_tokacc[t * DIM + d] * ((t < SC) ? n_s : n_v);
        g_toknorm[t * DIM + d] = (val - mu) * inv * gamma[t] + beta[t];
    }
}

__global__ void attn2_kernel(const float* __restrict__ Wq,
                             const float* __restrict__ Wk,
                             const float* __restrict__ Wv)
{
    extern __shared__ float sm2[];
    float (*tk)[68] = (float(*)[68])sm2;
    float (*qs)[68] = tk + 64;
    float (*ks)[68] = qs + 64;
    float (*vs)[68] = ks + 64;
    float (*ss)[68] = vs + 64;
    int h = blockIdx.x, tid = threadIdx.x;
    #pragma unroll
    for (int e = tid; e < 4096; e += 256) {
        int t = e >> 6, d = e & 63;
        tk[t][d] = g_toknorm[t * DIM + h * DH + d];
    }
    __syncthreads();
    #pragma unroll
    for (int e = tid; e < 4096; e += 256) {
        int t = e >> 6, d = e & 63;
        float aq = 0.f, ak = 0.f, av = 0.f;
        for (int x = 0; x < 64; x++) {
            float tv = tk[t][x];
            aq += tv * Wq[x * 64 + d];
            ak += tv * Wk[x * 64 + d];
            av += tv * Wv[x * 64 + d];
        }
        qs[t][d] = aq; ks[t][d] = ak; vs[t][d] = av;
    }
    __syncthreads();
    #pragma unroll
    for (int e = tid; e < 4096; e += 256) {
        int t = e >> 6, u = e & 63;
        float sv = 0.f;
        for (int d = 0; d < 64; d++) sv += qs[t][d] * ks[u][d];
        ss[t][u] = sv * ATT_SCALE;
    }
    __syncthreads();
    if (tid < 64) {
        float mx = -1e30f;
        for (int j = 0; j < 64; j++) mx = fmaxf(mx, ss[tid][j]);
        float sum = 0.f;
        for (int j = 0; j < 64; j++) {
            float p = __expf(ss[tid][j] - mx);
            ss[tid][j] = p; sum += p;
        }
        float inv = 1.f / sum;
        for (int j = 0; j < 64; j++) ss[tid][j] *= inv;
    }
    __syncthreads();
    #pragma unroll
    for (int e = tid; e < 4096; e += 256) {
        int t = e >> 6, d = e & 63;
        float o = 0.f;
        for (int u = 0; u < 64; u++) o += ss[t][u] * vs[u][d];
        g_outtok[h * (NTOK * DH) + t * DH + d] = o;
    }
}

__global__ void mat_out_kernel()
{
    int i = blockIdx.x * 256 + threadIdx.x;
    if (i < VC * DIM) {
        int r = i >> 9, d = i & 511;
        g_outvelo[i] = g_outtok[(d >> 6) * 4096 + (SC + r) * 64 + (d & 63)];
    }
    if (i < SC * DIM)
        g_outsurf[i] = g_outtok[(i >> 8) * 4096 + (((i >> 6) & 3) << 6) + (i & 63)];
}

__global__ void feat_surf_k(const int* __restrict__ surf_idx)
{
    __shared__ float Pw[64][4];
    __shared__ float Pc[64][60];
    __shared__ float Osf[4][64];
    __shared__ float Ovl[60][64];
    int i0 = blockIdx.x * 64, h = blockIdx.y, d0 = h * 64;
    int tid = threadIdx.x, ty = tid >> 4, tx = tid & 15;
    for (int e = tid; e < 64 * 4; e += 256) {
        int r = e >> 2, c = e & 3;
        int gi = i0 + r;
        Pw[r][c] = (gi < NSURF) ? g_Psc[gi * 64 + c] : 0.f;
    }
    for (int e = tid; e < 64 * 60; e += 256) {
        int r = e / 60, c = e % 60;
        int gi = i0 + r;
        Pc[r][c] = (gi < NSURF) ? g_Psc[gi * 64 + 4 + c] : 0.f;
    }
    for (int e = tid; e < 4 * 64; e += 256)
        Osf[e >> 6][e & 63] = g_outsurf[(e >> 6) * DIM + d0 + (e & 63)];
    for (int e = tid; e < 60 * 64; e += 256)
        Ovl[e >> 6][e & 63] = g_outvelo[(e >> 6) * DIM + d0 + (e & 63)];
    __syncthreads();
    float acc[4][4] = {};
    #pragma unroll
    for (int c = 0; c < 4; c++) {
        float ar[4];
        #pragma unroll
        for (int i = 0; i < 4; i++) ar[i] = Pw[ty * 4 + i][c];
        #pragma unroll
        for (int i = 0; i < 4; i++)
            #pragma unroll
            for (int j = 0; j < 4; j++)
                acc[i][j] += ar[i] * Osf[c][tx * 4 + j];
    }
    #pragma unroll
    for (int r = 0; r < 60; r++) {
        float ar[4];
        #pragma unroll
        for (int i = 0; i < 4; i++) ar[i] = Pc[ty * 4 + i][r];
        #pragma unroll
        for (int i = 0; i < 4; i++)
            #pragma unroll
            for (int j = 0; j < 4; j++)
                acc[i][j] += ar[i] * Ovl[r][tx * 4 + j];
    }
    #pragma unroll
    for (int i = 0; i < 4; i++) {
        int gi = i0 + ty * 4 + i;
        if (gi >= NSURF) continue;
        int orow = surf_idx[gi];
        #pragma unroll
        for (int j = 0; j < 4; j++) {
            int dd = tx * 4 + j;
            g_newf[orow * DIM + d0 + dd] =
                0.5f * acc[i][j] + g_o1[h * (L1 * DH) + (FLAP + gi) * DH + dd];
        }
    }
}

__global__ void feat_velo_k(const int* __restrict__ velo_idx)
{
    __shared__ float Pv_s[64][60];
    __shared__ float Ovl[60][64];
    int i0 = blockIdx.x * 64, h = blockIdx.y, d0 = h * 64;
    int tid = threadIdx.x, ty = tid >> 4, tx = tid & 15;
    for (int e = tid; e < 64 * 60; e += 256) {
        int r = e / 60, c = e % 60;
        int gi = i0 + r;
        Pv_s[r][c] = (gi < NVELO) ? g_Pv[gi * 60 + c] : 0.f;
    }
    for (int e = tid; e < 60 * 64; e += 256)
        Ovl[e >> 6][e & 63] = g_outvelo[(e >> 6) * DIM + d0 + (e & 63)];
    __syncthreads();
    float acc[4][4] = {};
    #pragma unroll
    for (int r = 0; r < 60; r++) {
        float ar[4];
        #pragma unroll
        for (int i = 0; i < 4; i++) ar[i] = Pv_s[ty * 4 + i][r];
        #pragma unroll
        for (int i = 0; i < 4; i++)
            #pragma unroll
            for (int j = 0; j < 4; j++)
                acc[i][j] += ar[i] * Ovl[r][tx * 4 + j];
    }
    #pragma unroll
    for (int i = 0; i < 4; i++) {
        int gi = i0 + ty * 4 + i;
        if (gi >= NVELO) continue;
        int orow = velo_idx[gi];
        #pragma unroll
        for (int j = 0; j < 4; j++) {
            int dd = tx * 4 + j;
            float v = acc[i][j];
            if (gi < FLAP) v += g_o1[h * (L1 * DH) + gi * DH + dd];
            g_newf[orow * DIM + d0 + dd] = v;
        }
    }
}

extern "C" void kernel_launch(void* const* d_in, const int* in_sizes, int n_in,
                              void* d_out, int out_size)
{
    (void)in_sizes; (void)n_in; (void)out_size;
    const float* x     = (const float*)d_in[0];
    const float* onion = (const float*)d_in[1];
    const float* W_fx  = (const float*)d_in[2];
    const float* b_fx  = (const float*)d_in[3];
    const float* W_x   = (const float*)d_in[4];
    const float* b_x   = (const float*)d_in[5];
    const float* Wq1   = (const float*)d_in[6];
    const float* Wk1   = (const float*)d_in[7];
    const float* Wv1   = (const float*)d_in[8];
    const float* Wq    = (const float*)d_in[9];
    const float* Wk    = (const float*)d_in[10];
    const float* Wv    = (const float*)d_in[11];
    const float* gamma = (const float*)d_in[12];
    const float* beta  = (const float*)d_in[13];
    const float* W_ws  = (const float*)d_in[14];
    const float* b_ws  = (const float*)d_in[15];
    const float* W_vv  = (const float*)d_in[16];
    const float* b_vv  = (const float*)d_in[17];
    const float* W_vc  = (const float*)d_in[18];
    const float* b_vc  = (const float*)d_in[19];
    const float* W_out = (const float*)d_in[20];
    const float* b_out = (const float*)d_in[21];
    const int* surf_idx = (const int*)d_in[22];
    const int* velo_idx = (const int*)d_in[23];
    const int* closest  = (const int*)d_in[25];
    const int* labels   = (const int*)d_in[26];
    float* out = (float*)d_out;

    float *p_fx, *p_xm, *p_newf, *p_Psc, *p_Pv, *p_Wsc, *p_bsc;
    __nv_bfloat16 *p_xh, *p_xl, *p_nfh, *p_nfl, *p_Wth, *p_Wtl;
    cudaGetSymbolAddress((void**)&p_fx, g_fx);
    cudaGetSymbolAddress((void**)&p_xm, g_xm);
    cudaGetSymbolAddress((void**)&p_newf, g_newf);
    cudaGetSymbolAddress((void**)&p_Psc, g_Psc);
    cudaGetSymbolAddress((void**)&p_Pv, g_Pv);
    cudaGetSymbolAddress((void**)&p_Wsc, g_Wsc);
    cudaGetSymbolAddress((void**)&p_bsc, g_bsc);
    cudaGetSymbolAddress((void**)&p_xh, g_xh);
    cudaGetSymbolAddress((void**)&p_xl, g_xl);
    cudaGetSymbolAddress((void**)&p_nfh, g_nfh);
    cudaGetSymbolAddress((void**)&p_nfl, g_nfl);
    cudaGetSymbolAddress((void**)&p_Wth, g_Wth);
    cudaGetSymbolAddress((void**)&p_Wtl, g_Wtl);

    cudaFuncSetAttribute(flash1_kernel, cudaFuncAttributeMaxDynamicSharedMemorySize, FLASH_SMEM);
    cudaFuncSetAttribute(attn2_kernel, cudaFuncAttributeMaxDynamicSharedMemorySize, ATTN2_SMEM);
    cudaFuncSetAttribute(gemm_mma, cudaFuncAttributeMaxDynamicSharedMemorySize, GMMA_SMEM);

    const int NELEM4 = NPTS * DIM / 4;
    dim3 gTC(DIM / 128, (NPTS + 127) / 128);

    conv_split<<<(NELEM4 + 255) / 256, 256>>>(x, p_xh, p_xl, NELEM4);
    conv_wt<<<(DIM * DIM + 255) / 256, 256>>>(W_fx, p_Wth, p_Wtl);
    conv_wt<<<(DIM * DIM + 255) / 256, 256>>>(W_x, p_Wth + DIM * DIM, p_Wtl + DIM * DIM);
    conv_wt<<<(DIM * DIM + 255) / 256, 256>>>(W_out, p_Wth + 2 * DIM * DIM, p_Wtl + 2 * DIM * DIM);

    gemm_mma<<<gTC, 256, GMMA_SMEM>>>(p_xh, p_xl, p_Wth, p_Wtl, b_fx, p_fx, NPTS);
    gemm_mma<<<gTC, 256, GMMA_SMEM>>>(p_xh, p_xl, p_Wth + DIM * DIM, p_Wtl + DIM * DIM, b_x, p_xm, NPTS);

    prep_kernel<<<(PREP_N + 255) / 256, 256>>>(onion, labels, closest, velo_idx, surf_idx,
                                               W_ws, b_ws, W_vc, b_vc);

    proj1_kernel<<<dim3((L1 + 63) / 64, HEADS), 256>>>(Wq1, Wk1, Wv1);
    flash1_kernel<<<dim3((L1 + 63) / 64, HEADS), 256, FLASH_SMEM>>>();

    pool_accum<<<dim3((NPT_TOT + ACC_CHUNK - 1) / ACC_CHUNK, DIM / 64), 256>>>();
    ln_kernel<<<1, DIM>>>(gamma, beta);
    attn2_kernel<<<HEADS, 256, ATTN2_SMEM>>>(Wq, Wk, Wv);
    mat_out_kernel<<<(VC * DIM + 255) / 256, 256>>>();

    gemm_bias<<<dim3(1, (NSURF + 63) / 64), 256>>>(p_xm, DIM, surf_idx, p_Wsc, 64, p_bsc, p_Psc, 64, NSURF, 64, DIM);
    gemm_bias<<<dim3(1, (NVELO + 63) / 64), 256>>>(p_xm, DIM, velo_idx, W_vv, VC, b_vv, p_Pv, VC, NVELO, VC, DIM);

    feat_surf_k<<<dim3((NSURF + 63) / 64, HEADS), 256>>>(surf_idx);
    feat_velo_k<<<dim3((NVELO + 63) / 64, HEADS), 256>>>(velo_idx);

    conv_split<<<(NELEM4 + 255) / 256, 256>>>(p_newf, p_nfh, p_nfl, NELEM4);
    gemm_mma<<<gTC, 256, GMMA_SMEM>>>(p_nfh, p_nfl, p_Wth + 2 * DIM * DIM, p_Wtl + 2 * DIM * DIM, b_out, out, NPTS);
}

// round 12
// speedup vs baseline: 2.8554x; 1.4736x over previous
#include <cuda_runtime.h>
#include <cuda_bf16.h>
#include <cstdint>

#define HEADS 8
#define DH 64
#define DIM 512
#define ONION 15
#define SC 4
#define NVELO 28504
#define NSURF 3682
#define NPTS 32186
#define SKEEP 3586
#define FLAP 500
#define NTOK 64
#define L1 4182
#define VC 60
#define NPT_TOT (NVELO + SKEEP)
#define PREP_N ((NTOK * DIM) > NPT_TOT ? (NTOK * DIM) : NPT_TOT)
#define ATT_SCALE 0.125f
#define LN_EPS 1e-5f
#define ATTN2_SMEM (5 * 64 * 68 * 4)

// ---------------- scratch ----------------
__device__ float g_fx[NPTS * DIM];
__device__ float g_xm[NPTS * DIM];
__device__ float g_newf[NPTS * DIM];
__device__ float g_o1[HEADS * L1 * DH];
__device__ __nv_bfloat16 g_q1h[HEADS * L1 * DH];
__device__ __nv_bfloat16 g_q1l[HEADS * L1 * DH];
__device__ __nv_bfloat16 g_k1h[HEADS * L1 * DH];
__device__ __nv_bfloat16 g_k1l[HEADS * L1 * DH];
__device__ __nv_bfloat16 g_v1h[HEADS * L1 * DH];
__device__ __nv_bfloat16 g_v1l[HEADS * L1 * DH];
__device__ int   g_tok1src[L1];
__device__ int   g_ptrow[NPT_TOT];
__device__ int   g_ptgrp[NPT_TOT];
__device__ float g_tokacc[NTOK * DIM];
__device__ float g_toknorm[NTOK * DIM];
__device__ float g_outtok[HEADS * NTOK * DH];
__device__ float g_outvelo[VC * DIM];
__device__ float g_outsurf[SC * DIM];
__device__ float g_Psc[NSURF * 64];
__device__ float g_Pv[NVELO * VC];
__device__ float g_Wsc[DIM * 64];
__device__ float g_bsc[64];
__device__ __nv_bfloat16 g_xh[NPTS * DIM];
__device__ __nv_bfloat16 g_xl[NPTS * DIM];
__device__ __nv_bfloat16 g_nfh[NPTS * DIM];
__device__ __nv_bfloat16 g_nfl[NPTS * DIM];
__device__ __nv_bfloat16 g_Wth[3 * DIM * DIM];
__device__ __nv_bfloat16 g_Wtl[3 * DIM * DIM];

// ---------------- sm_80-class PTX helpers --------
__device__ __forceinline__ uint32_t smem_u32(const void* p) {
    uint32_t a;
    asm("{ .reg .u64 t; cvta.to.shared.u64 t, %1; cvt.u32.u64 %0, t; }" : "=r"(a) : "l"(p));
    return a;
}
#define CPA16(dst, src, sz) \
    asm volatile("cp.async.cg.shared.global [%0], [%1], 16, %2;" \
                 :: "r"(dst), "l"(src), "r"(sz) : "memory")
#define CPA_COMMIT() asm volatile("cp.async.commit_group;" ::: "memory")
#define CPA_WAIT0()  asm volatile("cp.async.wait_group 0;" ::: "memory")
#define CPA_WAIT1()  asm volatile("cp.async.wait_group 1;" ::: "memory")
#define LDSM4(r, addr) \
    asm volatile("ldmatrix.sync.aligned.m8n8.x4.shared.b16 {%0,%1,%2,%3}, [%4];" \
                 : "=r"((r)[0]), "=r"((r)[1]), "=r"((r)[2]), "=r"((r)[3]) : "r"(addr))
#define LDSM4T(r, addr) \
    asm volatile("ldmatrix.sync.aligned.m8n8.x4.trans.shared.b16 {%0,%1,%2,%3}, [%4];" \
                 : "=r"((r)[0]), "=r"((r)[1]), "=r"((r)[2]), "=r"((r)[3]) : "r"(addr))
#define MMA16816(c, a, b0v, b1v) \
    asm volatile("mma.sync.aligned.m16n8k16.row.col.f32.bf16.bf16.f32 " \
                 "{%0,%1,%2,%3},{%4,%5,%6,%7},{%8,%9},{%0,%1,%2,%3};" \
                 : "+f"((c)[0]), "+f"((c)[1]), "+f"((c)[2]), "+f"((c)[3]) \
                 : "r"((a)[0]), "r"((a)[1]), "r"((a)[2]), "r"((a)[3]), "r"(b0v), "r"(b1v))
// pack two f32 -> bf16x2 (lo in low half)
__device__ __forceinline__ uint32_t pk2(float lo, float hi) {
    uint32_t r;
    asm("cvt.rn.bf16x2.f32 %0, %1, %2;" : "=r"(r) : "f"(hi), "f"(lo));
    return r;
}

// ---------------------------------------------------------------------------
// split-bf16 HMMA GEMM (unchanged from R11)
// ---------------------------------------------------------------------------
#define PLANE_B 10240
#define BUF_B   (4 * PLANE_B)
#define GMMA_SMEM (2 * BUF_B)

__device__ __forceinline__ void fill_chunk(
    uint32_t sb, const __nv_bfloat16* __restrict__ Ah, const __nv_bfloat16* __restrict__ Al,
    const __nv_bfloat16* __restrict__ Bh, const __nv_bfloat16* __restrict__ Bl,
    int m0, int n0, int k0, int M, int tid)
{
    #pragma unroll
    for (int hf = 0; hf < 2; hf++) {
        int s = tid + hf * 256;
        int r = s >> 2, v = s & 3;
        uint32_t off = (uint32_t)(r * 80 + v * 16);
        int gm = m0 + r;
        int szA = (gm < M) ? 16 : 0;
        int gmc = (gm < M) ? gm : (M - 1);
        CPA16(sb + off,               Ah + (size_t)gmc * DIM + k0 + v * 8, szA);
        CPA16(sb + PLANE_B + off,     Al + (size_t)gmc * DIM + k0 + v * 8, szA);
        CPA16(sb + 2 * PLANE_B + off, Bh + (size_t)(n0 + r) * DIM + k0 + v * 8, 16);
        CPA16(sb + 3 * PLANE_B + off, Bl + (size_t)(n0 + r) * DIM + k0 + v * 8, 16);
    }
}

__global__ void __launch_bounds__(256, 2) gemm_mma(
    const __nv_bfloat16* __restrict__ Ah, const __nv_bfloat16* __restrict__ Al,
    const __nv_bfloat16* __restrict__ Bth, const __nv_bfloat16* __restrict__ Btl,
    const float* __restrict__ bias, float* __restrict__ C, int M)
{
    extern __shared__ char smbuf[];
    uint32_t smb = smem_u32(smbuf);
    int tid = threadIdx.x, lane = tid & 31, wid = tid >> 5;
    int wy = wid & 3, wx = wid >> 2;
    int m0 = blockIdx.y * 128, n0 = blockIdx.x * 128;

    float acc[2][8][4] = {};
    uint32_t aBase = (uint32_t)((wy * 32 + (lane & 15)) * 80 + (lane >> 4) * 16);
    uint32_t bBase = (uint32_t)((wx * 64 + (lane & 15)) * 80 + (lane >> 4) * 16);

    fill_chunk(smb, Ah, Al, Bth, Btl, m0, n0, 0, M, tid);
    CPA_COMMIT();

    for (int ch = 0; ch < 16; ch++) {
        uint32_t sb = smb + (uint32_t)(ch & 1) * BUF_B;
        CPA_WAIT0();
        __syncthreads();
        if (ch < 15) {
            fill_chunk(smb + (uint32_t)((ch + 1) & 1) * BUF_B,
                       Ah, Al, Bth, Btl, m0, n0, (ch + 1) * 32, M, tid);
            CPA_COMMIT();
        }
        uint32_t AH = sb, AL = sb + PLANE_B, BH = sb + 2 * PLANE_B, BL = sb + 3 * PLANE_B;
        #pragma unroll
        for (int ks = 0; ks < 2; ks++) {
            uint32_t ko = (uint32_t)(ks * 32);
            uint32_t ah[2][4], al[2][4];
            LDSM4(ah[0], AH + aBase + ko);
            LDSM4(ah[1], AH + aBase + 1280 + ko);
            LDSM4(al[0], AL + aBase + ko);
            LDSM4(al[1], AL + aBase + 1280 + ko);
            #pragma unroll
            for (int np = 0; np < 4; np++) {
                uint32_t bh[4], bl[4];
                uint32_t boff = bBase + (uint32_t)(np * 16 * 80) + ko;
                LDSM4(bh, BH + boff);
                LDSM4(bl, BL + boff);
                #pragma unroll
                for (int mt = 0; mt < 2; mt++) {
                    float* c0 = acc[mt][np * 2];
                    float* c1 = acc[mt][np * 2 + 1];
                    MMA16816(c0, ah[mt], bh[0], bh[2]);
                    MMA16816(c0, ah[mt], bl[0], bl[2]);
                    MMA16816(c0, al[mt], bh[0], bh[2]);
                    MMA16816(c1, ah[mt], bh[1], bh[3]);
                    MMA16816(c1, ah[mt], bl[1], bl[3]);
                    MMA16816(c1, al[mt], bh[1], bh[3]);
                }
            }
        }
        __syncthreads();
    }

    int g = lane >> 2, tig = lane & 3;
    #pragma unroll
    for (int mt = 0; mt < 2; mt++) {
        int r0 = m0 + wy * 32 + mt * 16 + g;
        #pragma unroll
        for (int nt = 0; nt < 8; nt++) {
            int col = n0 + wx * 64 + nt * 8 + tig * 2;
            float2 b2 = *(const float2*)&bias[col];
            if (r0 < M) {
                float2 v = make_float2(acc[mt][nt][0] + b2.x, acc[mt][nt][1] + b2.y);
                *(float2*)&C[(size_t)r0 * DIM + col] = v;
            }
            if (r0 + 8 < M) {
                float2 v = make_float2(acc[mt][nt][2] + b2.x, acc[mt][nt][3] + b2.y);
                *(float2*)&C[(size_t)(r0 + 8) * DIM + col] = v;
            }
        }
    }
}

__global__ void conv_split(const float* __restrict__ s,
                           __nv_bfloat16* __restrict__ h,
                           __nv_bfloat16* __restrict__ l, int n4)
{
    int i = blockIdx.x * 256 + threadIdx.x;
    if (i >= n4) return;
    float4 v = *(const float4*)&s[i * 4];
    float a[4] = {v.x, v.y, v.z, v.w};
    #pragma unroll
    for (int j = 0; j < 4; j++) {
        __nv_bfloat16 hh = __float2bfloat16(a[j]);
        h[i * 4 + j] = hh;
        l[i * 4 + j] = __float2bfloat16(a[j] - __bfloat162float(hh));
    }
}

__global__ void conv_wt(const float* __restrict__ W,
                        __nv_bfloat16* __restrict__ th,
                        __nv_bfloat16* __restrict__ tl)
{
    int i = blockIdx.x * 256 + threadIdx.x;
    if (i >= DIM * DIM) return;
    int k = i >> 9, n = i & 511;
    float v = W[i];
    __nv_bfloat16 hh = __float2bfloat16(v);
    th[n * DIM + k] = hh;
    tl[n * DIM + k] = __float2bfloat16(v - __bfloat162float(hh));
}

// ---------------------------------------------------------------------------
// small gathered GEMM (N<=64)
// ---------------------------------------------------------------------------
__global__ void gemm_bias(const float* __restrict__ A, int lda,
                          const int* __restrict__ rowidx,
                          const float* __restrict__ B, int ldb,
                          const float* __restrict__ bias,
                          float* __restrict__ C, int ldc,
                          int M, int N, int K)
{
    __shared__ float As[16][68];
    __shared__ float Bs[16][68];
    int m0 = blockIdx.y * 64, n0 = blockIdx.x * 64;
    int tid = threadIdx.x, ty = tid >> 4, tx = tid & 15;
    float acc[4][4] = {};
    for (int k0 = 0; k0 < K; k0 += 16) {
        #pragma unroll
        for (int e = tid; e < 1024; e += 256) {
            int r = e >> 4, k = e & 15;
            int gm = m0 + r, gk = k0 + k;
            float v = 0.f;
            if (gm < M && gk < K) {
                int row = rowidx ? rowidx[gm] : gm;
                v = A[row * lda + gk];
            }
            As[k][r] = v;
        }
        #pragma unroll
        for (int e = tid; e < 1024; e += 256) {
            int k = e >> 6, n = e & 63;
            int gk = k0 + k, gn = n0 + n;
            Bs[k][n] = (gk < K && gn < N) ? B[gk * ldb + gn] : 0.f;
        }
        __syncthreads();
        #pragma unroll
        for (int kk = 0; kk < 16; kk++) {
            float4 a4 = *(const float4*)&As[kk][ty * 4];
            float4 b4 = *(const float4*)&Bs[kk][tx * 4];
            float ar[4] = {a4.x, a4.y, a4.z, a4.w};
            float br[4] = {b4.x, b4.y, b4.z, b4.w};
            #pragma unroll
            for (int i = 0; i < 4; i++)
                #pragma unroll
                for (int j = 0; j < 4; j++)
                    acc[i][j] += ar[i] * br[j];
        }
        __syncthreads();
    }
    #pragma unroll
    for (int i = 0; i < 4; i++) {
        int gm = m0 + ty * 4 + i;
        if (gm >= M) continue;
        #pragma unroll
        for (int j = 0; j < 4; j++) {
            int gn = n0 + tx * 4 + j;
            if (gn < N) C[gm * ldc + gn] = acc[i][j] + bias[gn];
        }
    }
}

__global__ void prep_kernel(const float* __restrict__ onion,
                            const int* __restrict__ labels,
                            const int* __restrict__ closest,
                            const int* __restrict__ velo_idx,
                            const int* __restrict__ surf_idx,
                            const float* __restrict__ W_ws,
                            const float* __restrict__ b_ws,
                            const float* __restrict__ W_vc,
                            const float* __restrict__ b_vc)
{
    int i = blockIdx.x * 256 + threadIdx.x;
    if (i < L1) g_tok1src[i] = (i < FLAP) ? velo_idx[i] : surf_idx[i - FLAP];
    if (i < NTOK * DIM) g_tokacc[i] = 0.f;
    if (i < DIM * 64) {
        int k = i >> 6, n = i & 63;
        g_Wsc[i] = (n < SC) ? W_ws[k * SC + n] : W_vc[k * VC + n - SC];
    }
    if (i < 64) g_bsc[i] = (i < SC) ? b_ws[i] : b_vc[i - SC];
    if (i >= NPT_TOT) return;
    if (i < NVELO) {
        int lab = 0;
        #pragma unroll
        for (int l = 1; l < ONION; l++)
            if (onion[l * NVELO + i] > 0.5f) lab = l;
        g_ptrow[i] = velo_idx[i];
        g_ptgrp[i] = SC + lab * SC + labels[closest[i]];
    } else {
        int j = i - NVELO;
        int sr = (j < 16) ? j : j + 96;
        g_ptrow[i] = surf_idx[sr];
        g_ptgrp[i] = labels[j];
    }
}

// q/k/v projection -> split bf16 planes (scale folded into q)
__global__ void proj1_kernel(const float* __restrict__ Wq1,
                             const float* __restrict__ Wk1,
                             const float* __restrict__ Wv1)
{
    __shared__ float Ts[64][68];
    __shared__ float Ws[64][68];
    int h = blockIdx.y, t0 = blockIdx.x * 64;
    int tid = threadIdx.x, ty = tid >> 4, tx = tid & 15;
    #pragma unroll
    for (int e = tid; e < 4096; e += 256) {
        int t = e >> 6, d = e & 63;
        int gt = t0 + t;
        Ts[t][d] = (gt < L1) ? g_fx[g_tok1src[gt] * DIM + h * DH + d] : 0.f;
    }
    const float* Wm[3] = {Wq1, Wk1, Wv1};
    __nv_bfloat16* Oh[3] = {g_q1h, g_k1h, g_v1h};
    __nv_bfloat16* Ol[3] = {g_q1l, g_k1l, g_v1l};
    #pragma unroll
    for (int m = 0; m < 3; m++) {
        __syncthreads();
        #pragma unroll
        for (int e = tid; e < 4096; e += 256) Ws[e >> 6][e & 63] = Wm[m][e];
        __syncthreads();
        float acc[4][4] = {};
        #pragma unroll
        for (int x = 0; x < 64; x++) {
            float ar[4];
            #pragma unroll
            for (int i = 0; i < 4; i++) ar[i] = Ts[ty * 4 + i][x];
            float4 b4 = *(const float4*)&Ws[x][tx * 4];
            float br[4] = {b4.x, b4.y, b4.z, b4.w};
            #pragma unroll
            for (int i = 0; i < 4; i++)
                #pragma unroll
                for (int j = 0; j < 4; j++)
                    acc[i][j] += ar[i] * br[j];
        }
        float sc = (m == 0) ? ATT_SCALE : 1.f;
        #pragma unroll
        for (int i = 0; i < 4; i++) {
            int gt = t0 + ty * 4 + i;
            if (gt >= L1) continue;
            size_t base = (size_t)h * (L1 * DH) + (size_t)gt * DH + tx * 4;
            #pragma unroll
            for (int j = 0; j < 4; j++) {
                float f = acc[i][j] * sc;
                __nv_bfloat16 hh = __float2bfloat16(f);
                Oh[m][base + j] = hh;
                Ol[m][base + j] = __float2bfloat16(f - __bfloat162float(hh));
            }
        }
    }
}

// ---------------------------------------------------------------------------
// flash attention with mma.sync, split-bf16 QK and PV.
// CTA: 256 threads (8 warps), 128 queries (16 rows/warp), K-tile 64.
// smem buffers: per buffer 4 planes [64 rows x 144B stride]: KH|KL|VH|VL.
// Q staged once in buffer1, fragments held in registers.
// ---------------------------------------------------------------------------
#define FL_STRIDE 144
#define FL_PLANE (64 * FL_STRIDE)          // 9216
#define FL_BUF (4 * FL_PLANE)              // 36864
#define FL_SMEM (2 * FL_BUF)               // 73728
#define NKT ((L1 + 63) / 64)               // 66

__device__ __forceinline__ void fl_fill(uint32_t buf, int h, int kt, int tid)
{
    const __nv_bfloat16* pl[4];
    pl[0] = g_k1h; pl[1] = g_k1l; pl[2] = g_v1h; pl[3] = g_v1l;
    #pragma unroll
    for (int i = 0; i < 8; i++) {
        int s = tid + i * 256;           // 0..2047
        int plane = s >> 9;
        int e = s & 511;
        int r = e >> 3, v = e & 7;
        int kk = kt * 64 + r;
        int sz = (kk < L1) ? 16 : 0;
        int kkc = (kk < L1) ? kk : (L1 - 1);
        CPA16(buf + plane * FL_PLANE + r * FL_STRIDE + v * 16,
              pl[plane] + (size_t)h * (L1 * DH) + (size_t)kkc * DH + v * 8, sz);
    }
}

__global__ void __launch_bounds__(256, 1) flashmma_kernel()
{
    extern __shared__ char sm[];
    uint32_t smb = smem_u32(sm);
    int tid = threadIdx.x, lane = tid & 31, w = tid >> 5;
    int h = blockIdx.y, q0 = blockIdx.x * 128;
    int g = lane >> 2, tq = lane & 3;

    // stage Q (2 planes, 128 rows) into buffer1
    {
        const __nv_bfloat16* qp[2] = {g_q1h, g_q1l};
        uint32_t qbuf = smb + FL_BUF;
        #pragma unroll
        for (int i = 0; i < 8; i++) {
            int s = tid + i * 256;
            int plane = s >> 10;
            int e = s & 1023;
            int r = e >> 3, v = e & 7;
            int gq = q0 + r;
            int sz = (gq < L1) ? 16 : 0;
            int gqc = (gq < L1) ? gq : (L1 - 1);
            CPA16(qbuf + plane * (128 * FL_STRIDE) + r * FL_STRIDE + v * 16,
                  qp[plane] + (size_t)h * (L1 * DH) + (size_t)gqc * DH + v * 8, sz);
        }
        CPA_COMMIT();
    }
    // prologue K/V tile 0 -> buffer0
    fl_fill(smb, h, 0, tid);
    CPA_COMMIT();

    CPA_WAIT1();          // Q ready
    __syncthreads();
    uint32_t qh[4][4], ql[4][4];
    {
        uint32_t qbuf = smb + FL_BUF;
        uint32_t qa = qbuf + (uint32_t)((w * 16 + (lane & 15)) * FL_STRIDE + (lane >> 4) * 16);
        #pragma unroll
        for (int kc = 0; kc < 4; kc++) {
            LDSM4(qh[kc], qa + kc * 32);
            LDSM4(ql[kc], qa + 128 * FL_STRIDE + kc * 32);
        }
    }
    __syncthreads();      // all warps done reading Q; buffer1 reusable

    float o[4][2][4] = {};
    float m0f = -1e30f, m1f = -1e30f, l0f = 0.f, l1f = 0.f;

    for (int kt = 0; kt < NKT; kt++) {
        uint32_t cur = smb + (uint32_t)(kt & 1) * FL_BUF;
        if (kt + 1 < NKT) {
            fl_fill(smb + (uint32_t)((kt + 1) & 1) * FL_BUF, h, kt + 1, tid);
            CPA_COMMIT();
            CPA_WAIT1();
        } else {
            CPA_WAIT0();
        }
        __syncthreads();

        // ---- S = Q K^T (3-term split) ----
        float s[4][2][4];
        #pragma unroll
        for (int nb = 0; nb < 4; nb++)
            #pragma unroll
            for (int ng = 0; ng < 2; ng++)
                #pragma unroll
                for (int e = 0; e < 4; e++) s[nb][ng][e] = 0.f;
        uint32_t kBase = cur + (uint32_t)((lane & 15) * FL_STRIDE + (lane >> 4) * 16);
        #pragma unroll
        for (int nb = 0; nb < 4; nb++) {
            #pragma unroll
            for (int kc = 0; kc < 4; kc++) {
                uint32_t bh[4], bl[4];
                uint32_t off = (uint32_t)(nb * 16 * FL_STRIDE + kc * 32);
                LDSM4(bh, kBase + off);
                LDSM4(bl, kBase + FL_PLANE + off);
                MMA16816(s[nb][0], qh[kc], bh[0], bh[2]);
                MMA16816(s[nb][0], qh[kc], bl[0], bl[2]);
                MMA16816(s[nb][0], ql[kc], bh[0], bh[2]);
                MMA16816(s[nb][1], qh[kc], bh[1], bh[3]);
                MMA16816(s[nb][1], qh[kc], bl[1], bl[3]);
                MMA16816(s[nb][1], ql[kc], bh[1], bh[3]);
            }
        }
        // ---- mask last tile ----
        int ktb = kt * 64;
        if (ktb + 64 > L1) {
            #pragma unroll
            for (int nb = 0; nb < 4; nb++)
                #pragma unroll
                for (int ng = 0; ng < 2; ng++) {
                    int kk0 = ktb + nb * 16 + ng * 8 + tq * 2;
                    if (kk0 >= L1)     { s[nb][ng][0] = -1e30f; s[nb][ng][2] = -1e30f; }
                    if (kk0 + 1 >= L1) { s[nb][ng][1] = -1e30f; s[nb][ng][3] = -1e30f; }
                }
        }
        // ---- online softmax on fragments ----
        float mx0 = m0f, mx1 = m1f;
        #pragma unroll
        for (int nb = 0; nb < 4; nb++)
            #pragma unroll
            for (int ng = 0; ng < 2; ng++) {
                mx0 = fmaxf(mx0, fmaxf(s[nb][ng][0], s[nb][ng][1]));
                mx1 = fmaxf(mx1, fmaxf(s[nb][ng][2], s[nb][ng][3]));
            }
        mx0 = fmaxf(mx0, __shfl_xor_sync(0xffffffffu, mx0, 1));
        mx0 = fmaxf(mx0, __shfl_xor_sync(0xffffffffu, mx0, 2));
        mx1 = fmaxf(mx1, __shfl_xor_sync(0xffffffffu, mx1, 1));
        mx1 = fmaxf(mx1, __shfl_xor_sync(0xffffffffu, mx1, 2));
        float c0 = __expf(m0f - mx0), c1 = __expf(m1f - mx1);
        m0f = mx0; m1f = mx1;
        float rs0 = 0.f, rs1 = 0.f;
        #pragma unroll
        for (int nb = 0; nb < 4; nb++)
            #pragma unroll
            for (int ng = 0; ng < 2; ng++) {
                float p0 = __expf(s[nb][ng][0] - mx0);
                float p1 = __expf(s[nb][ng][1] - mx0);
                float p2 = __expf(s[nb][ng][2] - mx1);
                float p3 = __expf(s[nb][ng][3] - mx1);
                s[nb][ng][0] = p0; s[nb][ng][1] = p1;
                s[nb][ng][2] = p2; s[nb][ng][3] = p3;
                rs0 += p0 + p1; rs1 += p2 + p3;
            }
        rs0 += __shfl_xor_sync(0xffffffffu, rs0, 1);
        rs0 += __shfl_xor_sync(0xffffffffu, rs0, 2);
        rs1 += __shfl_xor_sync(0xffffffffu, rs1, 1);
        rs1 += __shfl_xor_sync(0xffffffffu, rs1, 2);
        l0f = l0f * c0 + rs0;
        l1f = l1f * c1 + rs1;
        #pragma unroll
        for (int nd = 0; nd < 4; nd++)
            #pragma unroll
            for (int ng = 0; ng < 2; ng++) {
                o[nd][ng][0] *= c0; o[nd][ng][1] *= c0;
                o[nd][ng][2] *= c1; o[nd][ng][3] *= c1;
            }
        // ---- O += P V (3-term split) ----
        uint32_t vBase = cur + 2 * FL_PLANE +
            (uint32_t)(((lane & 7) + ((lane >> 4) & 1) * 8) * FL_STRIDE + ((lane >> 3) & 1) * 16);
        #pragma unroll
        for (int nbk = 0; nbk < 4; nbk++) {
            uint32_t pah[4], pal[4];
            #pragma unroll
            for (int hv = 0; hv < 2; hv++)
                #pragma unroll
                for (int pr = 0; pr < 2; pr++) {
                    float a0 = s[nbk][hv][pr * 2], a1 = s[nbk][hv][pr * 2 + 1];
                    uint32_t hp = pk2(a0, a1);
                    __nv_bfloat162 hb = *(__nv_bfloat162*)&hp;
                    float lo0 = a0 - __bfloat162float(hb.x);
                    float lo1 = a1 - __bfloat162float(hb.y);
                    pah[hv * 2 + pr] = hp;
                    pal[hv * 2 + pr] = pk2(lo0, lo1);
                }
            #pragma unroll
            for (int nd = 0; nd < 4; nd++) {
                uint32_t vbh[4], vbl[4];
                uint32_t off = (uint32_t)(nbk * 16 * FL_STRIDE + nd * 32);
                LDSM4T(vbh, vBase + off);
                LDSM4T(vbl, vBase + FL_PLANE + off);
                MMA16816(o[nd][0], pah, vbh[0], vbh[2]);
                MMA16816(o[nd][0], pah, vbl[0], vbl[2]);
                MMA16816(o[nd][0], pal, vbh[0], vbh[2]);
                MMA16816(o[nd][1], pah, vbh[1], vbh[3]);
                MMA16816(o[nd][1], pah, vbl[1], vbl[3]);
                MMA16816(o[nd][1], pal, vbh[1], vbh[3]);
            }
        }
        __syncthreads();
    }

    float i0 = 1.f / l0f, i1 = 1.f / l1f;
    int r0 = q0 + w * 16 + g, r1 = r0 + 8;
    #pragma unroll
    for (int nd = 0; nd < 4; nd++)
        #pragma unroll
        for (int ng = 0; ng < 2; ng++) {
            int col = nd * 16 + ng * 8 + tq * 2;
            if (r0 < L1) {
                float2 v = make_float2(o[nd][ng][0] * i0, o[nd][ng][1] * i0);
                *(float2*)&g_o1[(size_t)h * (L1 * DH) + (size_t)r0 * DH + col] = v;
            }
            if (r1 < L1) {
                float2 v = make_float2(o[nd][ng][2] * i1, o[nd][ng][3] * i1);
                *(float2*)&g_o1[(size_t)h * (L1 * DH) + (size_t)r1 * DH + col] = v;
            }
        }
}

#define ACC_CHUNK 1024
__global__ void pool_accum()
{
    __shared__ float sa[64][64];
    int d0 = blockIdx.y * 64, p0 = blockIdx.x * ACC_CHUNK;
    int tid = threadIdx.x, dd = tid & 63, q4 = tid >> 6;
    #pragma unroll
    for (int e = tid; e < 4096; e += 256) ((float*)sa)[e] = 0.f;
    __syncthreads();
    int pend = min(p0 + ACC_CHUNK, NPT_TOT);
    for (int p = p0 + q4; p < pend; p += 4) {
        float v = g_fx[g_ptrow[p] * DIM + d0 + dd];
        atomicAdd(&sa[g_ptgrp[p]][dd], v);
    }
    __syncthreads();
    #pragma unroll
    for (int e = tid; e < 4096; e += 256) {
        int g = e >> 6, d = e & 63;
        float v = sa[g][d];
        if (v != 0.f) atomicAdd(&g_tokacc[g * DIM + d0 + d], v);
    }
}

__global__ void ln_kernel(const float* __restrict__ gamma,
                          const float* __restrict__ beta)
{
    int d = threadIdx.x;
    const float n_s = 1.f / (float)SKEEP, n_v = 1.f / (float)NVELO;
    float s = 0.f;
    #pragma unroll
    for (int t = 0; t < NTOK; t++)
        s += g_tokacc[t * DIM + d] * ((t < SC) ? n_s : n_v);
    float mu = s * (1.f / NTOK);
    float v2 = 0.f;
    #pragma unroll
    for (int t = 0; t < NTOK; t++) {
        float dv = g_tokacc[t * DIM + d] * ((t < SC) ? n_s : n_v) - mu;
        v2 += dv * dv;
    }
    float inv = rsqrtf(v2 * (1.f / NTOK) + LN_EPS);
    #pragma unroll
    for (int t = 0; t < NTOK; t++) {
        float val = g_tokacc[t * DIM + d] * ((t < SC) ? n_s : n_v);
        g_toknorm[t * DIM + d] = (val - mu) * inv * gamma[t] + beta[t];
    }
}

__global__ void attn2_kernel(const float* __restrict__ Wq,
                             const float* __restrict__ Wk,
                             const float* __restrict__ Wv)
{
    extern __shared__ float sm2[];
    float (*tk)[68] = (float(*)[68])sm2;
    float (*qs)[68] = tk + 64;
    float (*ks)[68] = qs + 64;
    float (*vs)[68] = ks + 64;
    float (*ss)[68] = vs + 64;
    int h = blockIdx.x, tid = threadIdx.x;
    #pragma unroll
    for (int e = tid; e < 4096; e += 256) {
        int t = e >> 6, d = e & 63;
        tk[t][d] = g_toknorm[t * DIM + h * DH + d];
    }
    __syncthreads();
    #pragma unroll
    for (int e = tid; e < 4096; e += 256) {
        int t = e >> 6, d = e & 63;
        float aq = 0.f, ak = 0.f, av = 0.f;
        for (int x = 0; x < 64; x++) {
            float tv = tk[t][x];
            aq += tv * Wq[x * 64 + d];
            ak += tv * Wk[x * 64 + d];
            av += tv * Wv[x * 64 + d];
        }
        qs[t][d] = aq; ks[t][d] = ak; vs[t][d] = av;
    }
    __syncthreads();
    #pragma unroll
    for (int e = tid; e < 4096; e += 256) {
        int t = e >> 6, u = e & 63;
        float sv = 0.f;
        for (int d = 0; d < 64; d++) sv += qs[t][d] * ks[u][d];
        ss[t][u] = sv * ATT_SCALE;
    }
    __syncthreads();
    if (tid < 64) {
        float mx = -1e30f;
        for (int j = 0; j < 64; j++) mx = fmaxf(mx, ss[tid][j]);
        float sum = 0.f;
        for (int j = 0; j < 64; j++) {
            float p = __expf(ss[tid][j] - mx);
            ss[tid][j] = p; sum += p;
        }
        float inv = 1.f / sum;
        for (int j = 0; j < 64; j++) ss[tid][j] *= inv;
    }
    __syncthreads();
    #pragma unroll
    for (int e = tid; e < 4096; e += 256) {
        int t = e >> 6, d = e & 63;
        float o = 0.f;
        for (int u = 0; u < 64; u++) o += ss[t][u] * vs[u][d];
        g_outtok[h * (NTOK * DH) + t * DH + d] = o;
    }
}

__global__ void mat_out_kernel()
{
    int i = blockIdx.x * 256 + threadIdx.x;
    if (i < VC * DIM) {
        int r = i >> 9, d = i & 511;
        g_outvelo[i] = g_outtok[(d >> 6) * 4096 + (SC + r) * 64 + (d & 63)];
    }
    if (i < SC * DIM)
        g_outsurf[i] = g_outtok[(i >> 8) * 4096 + (((i >> 6) & 3) << 6) + (i & 63)];
}

__global__ void feat_surf_k(const int* __restrict__ surf_idx)
{
    __shared__ float Pw[64][4];
    __shared__ float Pc[64][60];
    __shared__ float Osf[4][64];
    __shared__ float Ovl[60][64];
    int i0 = blockIdx.x * 64, h = blockIdx.y, d0 = h * 64;
    int tid = threadIdx.x, ty = tid >> 4, tx = tid & 15;
    for (int e = tid; e < 64 * 4; e += 256) {
        int r = e >> 2, c = e & 3;
        int gi = i0 + r;
        Pw[r][c] = (gi < NSURF) ? g_Psc[gi * 64 + c] : 0.f;
    }
    for (int e = tid; e < 64 * 60; e += 256) {
        int r = e / 60, c = e % 60;
        int gi = i0 + r;
        Pc[r][c] = (gi < NSURF) ? g_Psc[gi * 64 + 4 + c] : 0.f;
    }
    for (int e = tid; e < 4 * 64; e += 256)
        Osf[e >> 6][e & 63] = g_outsurf[(e >> 6) * DIM + d0 + (e & 63)];
    for (int e = tid; e < 60 * 64; e += 256)
        Ovl[e >> 6][e & 63] = g_outvelo[(e >> 6) * DIM + d0 + (e & 63)];
    __syncthreads();
    float acc[4][4] = {};
    #pragma unroll
    for (int c = 0; c < 4; c++) {
        float ar[4];
        #pragma unroll
        for (int i = 0; i < 4; i++) ar[i] = Pw[ty * 4 + i][c];
        #pragma unroll
        for (int i = 0; i < 4; i++)
            #pragma unroll
            for (int j = 0; j < 4; j++)
                acc[i][j] += ar[i] * Osf[c][tx * 4 + j];
    }
    #pragma unroll
    for (int r = 0; r < 60; r++) {
        float ar[4];
        #pragma unroll
        for (int i = 0; i < 4; i++) ar[i] = Pc[ty * 4 + i][r];
        #pragma unroll
        for (int i = 0; i < 4; i++)
            #pragma unroll
            for (int j = 0; j < 4; j++)
                acc[i][j] += ar[i] * Ovl[r][tx * 4 + j];
    }
    #pragma unroll
    for (int i = 0; i < 4; i++) {
        int gi = i0 + ty * 4 + i;
        if (gi >= NSURF) continue;
        int orow = surf_idx[gi];
        #pragma unroll
        for (int j = 0; j < 4; j++) {
            int dd = tx * 4 + j;
            g_newf[orow * DIM + d0 + dd] =
                0.5f * acc[i][j] + g_o1[h * (L1 * DH) + (FLAP + gi) * DH + dd];
        }
    }
}

__global__ void feat_velo_k(const int* __restrict__ velo_idx)
{
    __shared__ float Pv_s[64][60];
    __shared__ float Ovl[60][64];
    int i0 = blockIdx.x * 64, h = blockIdx.y, d0 = h * 64;
    int tid = threadIdx.x, ty = tid >> 4, tx = tid & 15;
    for (int e = tid; e < 64 * 60; e += 256) {
        int r = e / 60, c = e % 60;
        int gi = i0 + r;
        Pv_s[r][c] = (gi < NVELO) ? g_Pv[gi * 60 + c] : 0.f;
    }
    for (int e = tid; e < 60 * 64; e += 256)
        Ovl[e >> 6][e & 63] = g_outvelo[(e >> 6) * DIM + d0 + (e & 63)];
    __syncthreads();
    float acc[4][4] = {};
    #pragma unroll
    for (int r = 0; r < 60; r++) {
        float ar[4];
        #pragma unroll
        for (int i = 0; i < 4; i++) ar[i] = Pv_s[ty * 4 + i][r];
        #pragma unroll
        for (int i = 0; i < 4; i++)
            #pragma unroll
            for (int j = 0; j < 4; j++)
                acc[i][j] += ar[i] * Ovl[r][tx * 4 + j];
    }
    #pragma unroll
    for (int i = 0; i < 4; i++) {
        int gi = i0 + ty * 4 + i;
        if (gi >= NVELO) continue;
        int orow = velo_idx[gi];
        #pragma unroll
        for (int j = 0; j < 4; j++) {
            int dd = tx * 4 + j;
            float v = acc[i][j];
            if (gi < FLAP) v += g_o1[h * (L1 * DH) + gi * DH + dd];
            g_newf[orow * DIM + d0 + dd] = v;
        }
    }
}

extern "C" void kernel_launch(void* const* d_in, const int* in_sizes, int n_in,
                              void* d_out, int out_size)
{
    (void)in_sizes; (void)n_in; (void)out_size;
    const float* x     = (const float*)d_in[0];
    const float* onion = (const float*)d_in[1];
    const float* W_fx  = (const float*)d_in[2];
    const float* b_fx  = (const float*)d_in[3];
    const float* W_x   = (const float*)d_in[4];
    const float* b_x   = (const float*)d_in[5];
    const float* Wq1   = (const float*)d_in[6];
    const float* Wk1   = (const float*)d_in[7];
    const float* Wv1   = (const float*)d_in[8];
    const float* Wq    = (const float*)d_in[9];
    const float* Wk    = (const float*)d_in[10];
    const float* Wv    = (const float*)d_in[11];
    const float* gamma = (const float*)d_in[12];
    const float* beta  = (const float*)d_in[13];
    const float* W_ws  = (const float*)d_in[14];
    const float* b_ws  = (const float*)d_in[15];
    const float* W_vv  = (const float*)d_in[16];
    const float* b_vv  = (const float*)d_in[17];
    const float* W_vc  = (const float*)d_in[18];
    const float* b_vc  = (const float*)d_in[19];
    const float* W_out = (const float*)d_in[20];
    const float* b_out = (const float*)d_in[21];
    const int* surf_idx = (const int*)d_in[22];
    const int* velo_idx = (const int*)d_in[23];
    const int* closest  = (const int*)d_in[25];
    const int* labels   = (const int*)d_in[26];
    float* out = (float*)d_out;

    float *p_fx, *p_xm, *p_newf, *p_Psc, *p_Pv, *p_Wsc, *p_bsc;
    __nv_bfloat16 *p_xh, *p_xl, *p_nfh, *p_nfl, *p_Wth, *p_Wtl;
    cudaGetSymbolAddress((void**)&p_fx, g_fx);
    cudaGetSymbolAddress((void**)&p_xm, g_xm);
    cudaGetSymbolAddress((void**)&p_newf, g_newf);
    cudaGetSymbolAddress((void**)&p_Psc, g_Psc);
    cudaGetSymbolAddress((void**)&p_Pv, g_Pv);
    cudaGetSymbolAddress((void**)&p_Wsc, g_Wsc);
    cudaGetSymbolAddress((void**)&p_bsc, g_bsc);
    cudaGetSymbolAddress((void**)&p_xh, g_xh);
    cudaGetSymbolAddress((void**)&p_xl, g_xl);
    cudaGetSymbolAddress((void**)&p_nfh, g_nfh);
    cudaGetSymbolAddress((void**)&p_nfl, g_nfl);
    cudaGetSymbolAddress((void**)&p_Wth, g_Wth);
    cudaGetSymbolAddress((void**)&p_Wtl, g_Wtl);

    cudaFuncSetAttribute(attn2_kernel, cudaFuncAttributeMaxDynamicSharedMemorySize, ATTN2_SMEM);
    cudaFuncSetAttribute(gemm_mma, cudaFuncAttributeMaxDynamicSharedMemorySize, GMMA_SMEM);
    cudaFuncSetAttribute(flashmma_kernel, cudaFuncAttributeMaxDynamicSharedMemorySize, FL_SMEM);

    const int NELEM4 = NPTS * DIM / 4;
    dim3 gTC(DIM / 128, (NPTS + 127) / 128);

    conv_split<<<(NELEM4 + 255) / 256, 256>>>(x, p_xh, p_xl, NELEM4);
    conv_wt<<<(DIM * DIM + 255) / 256, 256>>>(W_fx, p_Wth, p_Wtl);
    conv_wt<<<(DIM * DIM + 255) / 256, 256>>>(W_x, p_Wth + DIM * DIM, p_Wtl + DIM * DIM);
    conv_wt<<<(DIM * DIM + 255) / 256, 256>>>(W_out, p_Wth + 2 * DIM * DIM, p_Wtl + 2 * DIM * DIM);

    gemm_mma<<<gTC, 256, GMMA_SMEM>>>(p_xh, p_xl, p_Wth, p_Wtl, b_fx, p_fx, NPTS);
    gemm_mma<<<gTC, 256, GMMA_SMEM>>>(p_xh, p_xl, p_Wth + DIM * DIM, p_Wtl + DIM * DIM, b_x, p_xm, NPTS);

    prep_kernel<<<(PREP_N + 255) / 256, 256>>>(onion, labels, closest, velo_idx, surf_idx,
                                               W_ws, b_ws, W_vc, b_vc);

    proj1_kernel<<<dim3((L1 + 63) / 64, HEADS), 256>>>(Wq1, Wk1, Wv1);
    flashmma_kernel<<<dim3((L1 + 127) / 128, HEADS), 256, FL_SMEM>>>();

    pool_accum<<<dim3((NPT_TOT + ACC_CHUNK - 1) / ACC_CHUNK, DIM / 64), 256>>>();
    ln_kernel<<<1, DIM>>>(gamma, beta);
    attn2_kernel<<<HEADS, 256, ATTN2_SMEM>>>(Wq, Wk, Wv);
    mat_out_kernel<<<(VC * DIM + 255) / 256, 256>>>();

    gemm_bias<<<dim3(1, (NSURF + 63) / 64), 256>>>(p_xm, DIM, surf_idx, p_Wsc, 64, p_bsc, p_Psc, 64, NSURF, 64, DIM);
    gemm_bias<<<dim3(1, (NVELO + 63) / 64), 256>>>(p_xm, DIM, velo_idx, W_vv, VC, b_vv, p_Pv, VC, NVELO, VC, DIM);

    feat_surf_k<<<dim3((NSURF + 63) / 64, HEADS), 256>>>(surf_idx);
    feat_velo_k<<<dim3((NVELO + 63) / 64, HEADS), 256>>>(velo_idx);

    conv_split<<<(NELEM4 + 255) / 256, 256>>>(p_newf, p_nfh, p_nfl, NELEM4);
    gemm_mma<<<gTC, 256, GMMA_SMEM>>>(p_nfh, p_nfl, p_Wth + 2 * DIM * DIM, p_Wtl + 2 * DIM * DIM, b_out, out, NPTS);
}

// round 13
// speedup vs baseline: 3.1650x; 1.1084x over previous
#include <cuda_runtime.h>
#include <cuda_bf16.h>
#include <cstdint>

#define HEADS 8
#define DH 64
#define DIM 512
#define ONION 15
#define SC 4
#define NVELO 28504
#define NSURF 3682
#define NPTS 32186
#define SKEEP 3586
#define FLAP 500
#define NTOK 64
#define L1 4182
#define VC 60
#define NPT_TOT (NVELO + SKEEP)
#define PREP_N ((NTOK * DIM) > NPT_TOT ? (NTOK * DIM) : NPT_TOT)
#define ATT_SCALE 0.125f
#define LN_EPS 1e-5f
#define ATTN2_SMEM (5 * 64 * 68 * 4)

// ---------------- scratch ----------------
__device__ float g_fx[NPTS * DIM];
__device__ float g_o1[HEADS * L1 * DH];
__device__ __nv_bfloat16 g_q1h[HEADS * L1 * DH];
__device__ __nv_bfloat16 g_q1l[HEADS * L1 * DH];
__device__ __nv_bfloat16 g_k1h[HEADS * L1 * DH];
__device__ __nv_bfloat16 g_k1l[HEADS * L1 * DH];
__device__ __nv_bfloat16 g_v1h[HEADS * L1 * DH];
__device__ __nv_bfloat16 g_v1l[HEADS * L1 * DH];
__device__ int   g_tok1src[L1];
__device__ int   g_ptrow[NPT_TOT];
__device__ int   g_ptgrp[NPT_TOT];
__device__ float g_tokacc[NTOK * DIM];
__device__ float g_toknorm[NTOK * DIM];
__device__ float g_outtok[HEADS * NTOK * DH];
__device__ float g_osc[NTOK * DIM];           // composite token matrix (4 surf + 60 velo)
__device__ float g_Wsc[DIM * 64];
__device__ float g_bsc[64];
__device__ __nv_bfloat16 g_xh[NPTS * DIM];
__device__ __nv_bfloat16 g_xl[NPTS * DIM];
__device__ __nv_bfloat16 g_xmh[NPTS * DIM];   // xm split planes (no fp32 xm)
__device__ __nv_bfloat16 g_xml[NPTS * DIM];
__device__ __nv_bfloat16 g_nfh[NPTS * DIM];   // newf split planes
__device__ __nv_bfloat16 g_nfl[NPTS * DIM];
__device__ __nv_bfloat16 g_Wth[3 * DIM * DIM];
__device__ __nv_bfloat16 g_Wtl[3 * DIM * DIM];
__device__ __nv_bfloat16 g_Wcth[2 * DIM * DIM];  // composite feature weights (transposed planes)
__device__ __nv_bfloat16 g_Wctl[2 * DIM * DIM];
__device__ float g_bc[2 * DIM];                  // composite biases

// ---------------- sm_80-class PTX helpers --------
__device__ __forceinline__ uint32_t smem_u32(const void* p) {
    uint32_t a;
    asm("{ .reg .u64 t; cvta.to.shared.u64 t, %1; cvt.u32.u64 %0, t; }" : "=r"(a) : "l"(p));
    return a;
}
#define CPA16(dst, src, sz) \
    asm volatile("cp.async.cg.shared.global [%0], [%1], 16, %2;" \
                 :: "r"(dst), "l"(src), "r"(sz) : "memory")
#define CPA_COMMIT() asm volatile("cp.async.commit_group;" ::: "memory")
#define CPA_WAIT0()  asm volatile("cp.async.wait_group 0;" ::: "memory")
#define CPA_WAIT1()  asm volatile("cp.async.wait_group 1;" ::: "memory")
#define LDSM4(r, addr) \
    asm volatile("ldmatrix.sync.aligned.m8n8.x4.shared.b16 {%0,%1,%2,%3}, [%4];" \
                 : "=r"((r)[0]), "=r"((r)[1]), "=r"((r)[2]), "=r"((r)[3]) : "r"(addr))
#define LDSM4T(r, addr) \
    asm volatile("ldmatrix.sync.aligned.m8n8.x4.trans.shared.b16 {%0,%1,%2,%3}, [%4];" \
                 : "=r"((r)[0]), "=r"((r)[1]), "=r"((r)[2]), "=r"((r)[3]) : "r"(addr))
#define MMA16816(c, a, b0v, b1v) \
    asm volatile("mma.sync.aligned.m16n8k16.row.col.f32.bf16.bf16.f32 " \
                 "{%0,%1,%2,%3},{%4,%5,%6,%7},{%8,%9},{%0,%1,%2,%3};" \
                 : "+f"((c)[0]), "+f"((c)[1]), "+f"((c)[2]), "+f"((c)[3]) \
                 : "r"((a)[0]), "r"((a)[1]), "r"((a)[2]), "r"((a)[3]), "r"(b0v), "r"(b1v))
__device__ __forceinline__ uint32_t pk2(float lo, float hi) {
    uint32_t r;
    asm("cvt.rn.bf16x2.f32 %0, %1, %2;" : "=r"(r) : "f"(hi), "f"(lo));
    return r;
}
__device__ __forceinline__ uint32_t splitpair(float v0, float v1, uint32_t& lopack) {
    uint32_t hp = pk2(v0, v1);
    __nv_bfloat162 hb = *(__nv_bfloat162*)&hp;
    lopack = pk2(v0 - __bfloat162float(hb.x), v1 - __bfloat162float(hb.y));
    return hp;
}

// ---------------------------------------------------------------------------
// split-bf16 HMMA GEMM; epilogue: fp32 OR split-bf16 planes
// ---------------------------------------------------------------------------
#define PLANE_B 10240
#define BUF_B   (4 * PLANE_B)
#define GMMA_SMEM (2 * BUF_B)

__device__ __forceinline__ void fill_chunk(
    uint32_t sb, const __nv_bfloat16* __restrict__ Ah, const __nv_bfloat16* __restrict__ Al,
    const __nv_bfloat16* __restrict__ Bh, const __nv_bfloat16* __restrict__ Bl,
    const int* __restrict__ rowidx,
    int m0, int n0, int k0, int M, int tid)
{
    #pragma unroll
    for (int hf = 0; hf < 2; hf++) {
        int s = tid + hf * 256;
        int r = s >> 2, v = s & 3;
        uint32_t off = (uint32_t)(r * 80 + v * 16);
        int gm = m0 + r;
        int szA = (gm < M) ? 16 : 0;
        int gmc = (gm < M) ? gm : (M - 1);
        int arow = rowidx ? rowidx[gmc] : gmc;
        CPA16(sb + off,               Ah + (size_t)arow * DIM + k0 + v * 8, szA);
        CPA16(sb + PLANE_B + off,     Al + (size_t)arow * DIM + k0 + v * 8, szA);
        CPA16(sb + 2 * PLANE_B + off, Bh + (size_t)(n0 + r) * DIM + k0 + v * 8, 16);
        CPA16(sb + 3 * PLANE_B + off, Bl + (size_t)(n0 + r) * DIM + k0 + v * 8, 16);
    }
}

// core mainloop shared by both GEMMs
__device__ __forceinline__ void mma_mainloop(
    uint32_t smb, const __nv_bfloat16* Ah, const __nv_bfloat16* Al,
    const __nv_bfloat16* Bth, const __nv_bfloat16* Btl,
    const int* rowidx, int m0, int n0, int M, int tid, int lane, int wy, int wx,
    float acc[2][8][4])
{
    uint32_t aBase = (uint32_t)((wy * 32 + (lane & 15)) * 80 + (lane >> 4) * 16);
    uint32_t bBase = (uint32_t)((wx * 64 + (lane & 15)) * 80 + (lane >> 4) * 16);
    fill_chunk(smb, Ah, Al, Bth, Btl, rowidx, m0, n0, 0, M, tid);
    CPA_COMMIT();
    for (int ch = 0; ch < 16; ch++) {
        uint32_t sb = smb + (uint32_t)(ch & 1) * BUF_B;
        CPA_WAIT0();
        __syncthreads();
        if (ch < 15) {
            fill_chunk(smb + (uint32_t)((ch + 1) & 1) * BUF_B,
                       Ah, Al, Bth, Btl, rowidx, m0, n0, (ch + 1) * 32, M, tid);
            CPA_COMMIT();
        }
        uint32_t AH = sb, AL = sb + PLANE_B, BH = sb + 2 * PLANE_B, BL = sb + 3 * PLANE_B;
        #pragma unroll
        for (int ks = 0; ks < 2; ks++) {
            uint32_t ko = (uint32_t)(ks * 32);
            uint32_t ah[2][4], al[2][4];
            LDSM4(ah[0], AH + aBase + ko);
            LDSM4(ah[1], AH + aBase + 1280 + ko);
            LDSM4(al[0], AL + aBase + ko);
            LDSM4(al[1], AL + aBase + 1280 + ko);
            #pragma unroll
            for (int np = 0; np < 4; np++) {
                uint32_t bh[4], bl[4];
                uint32_t boff = bBase + (uint32_t)(np * 16 * 80) + ko;
                LDSM4(bh, BH + boff);
                LDSM4(bl, BL + boff);
                #pragma unroll
                for (int mt = 0; mt < 2; mt++) {
                    float* c0 = acc[mt][np * 2];
                    float* c1 = acc[mt][np * 2 + 1];
                    MMA16816(c0, ah[mt], bh[0], bh[2]);
                    MMA16816(c0, ah[mt], bl[0], bl[2]);
                    MMA16816(c0, al[mt], bh[0], bh[2]);
                    MMA16816(c1, ah[mt], bh[1], bh[3]);
                    MMA16816(c1, ah[mt], bl[1], bl[3]);
                    MMA16816(c1, al[mt], bh[1], bh[3]);
                }
            }
        }
        __syncthreads();
    }
}

__global__ void __launch_bounds__(256, 2) gemm_mma(
    const __nv_bfloat16* __restrict__ Ah, const __nv_bfloat16* __restrict__ Al,
    const __nv_bfloat16* __restrict__ Bth, const __nv_bfloat16* __restrict__ Btl,
    const float* __restrict__ bias, float* __restrict__ Cf,
    __nv_bfloat16* __restrict__ Ch, __nv_bfloat16* __restrict__ Cl, int M)
{
    extern __shared__ char smbuf[];
    uint32_t smb = smem_u32(smbuf);
    int tid = threadIdx.x, lane = tid & 31, wid = tid >> 5;
    int wy = wid & 3, wx = wid >> 2;
    int m0 = blockIdx.y * 128, n0 = blockIdx.x * 128;
    float acc[2][8][4] = {};
    mma_mainloop(smb, Ah, Al, Bth, Btl, nullptr, m0, n0, M, tid, lane, wy, wx, acc);

    int g = lane >> 2, tig = lane & 3;
    #pragma unroll
    for (int mt = 0; mt < 2; mt++) {
        int r0 = m0 + wy * 32 + mt * 16 + g;
        #pragma unroll
        for (int nt = 0; nt < 8; nt++) {
            int col = n0 + wx * 64 + nt * 8 + tig * 2;
            float2 b2 = *(const float2*)&bias[col];
            float v00 = acc[mt][nt][0] + b2.x, v01 = acc[mt][nt][1] + b2.y;
            float v10 = acc[mt][nt][2] + b2.x, v11 = acc[mt][nt][3] + b2.y;
            if (Cf) {
                if (r0 < M)     *(float2*)&Cf[(size_t)r0 * DIM + col] = make_float2(v00, v01);
                if (r0 + 8 < M) *(float2*)&Cf[(size_t)(r0 + 8) * DIM + col] = make_float2(v10, v11);
            } else {
                uint32_t lo;
                if (r0 < M) {
                    uint32_t hi = splitpair(v00, v01, lo);
                    *(uint32_t*)&Ch[(size_t)r0 * DIM + col] = hi;
                    *(uint32_t*)&Cl[(size_t)r0 * DIM + col] = lo;
                }
                if (r0 + 8 < M) {
                    uint32_t hi = splitpair(v10, v11, lo);
                    *(uint32_t*)&Ch[(size_t)(r0 + 8) * DIM + col] = hi;
                    *(uint32_t*)&Cl[(size_t)(r0 + 8) * DIM + col] = lo;
                }
            }
        }
    }
}

// feature GEMM: A = gathered xm planes, B = composite weight planes.
// epilogue: + bcomp + o1 residual, scatter split-bf16 into newf planes.
__global__ void __launch_bounds__(256, 2) gemm_feat(
    const __nv_bfloat16* __restrict__ Bth, const __nv_bfloat16* __restrict__ Btl,
    const float* __restrict__ bcomp, const int* __restrict__ rowidx,
    int M, int o1_off, int o1_always)
{
    extern __shared__ char smbuf[];
    uint32_t smb = smem_u32(smbuf);
    int tid = threadIdx.x, lane = tid & 31, wid = tid >> 5;
    int wy = wid & 3, wx = wid >> 2;
    int m0 = blockIdx.y * 128, n0 = blockIdx.x * 128;
    float acc[2][8][4] = {};
    mma_mainloop(smb, g_xmh, g_xml, Bth, Btl, rowidx, m0, n0, M, tid, lane, wy, wx, acc);

    int g = lane >> 2, tig = lane & 3;
    #pragma unroll
    for (int mt = 0; mt < 2; mt++) {
        int gi0 = m0 + wy * 32 + mt * 16 + g;
        int gi1 = gi0 + 8;
        int or0 = (gi0 < M) ? rowidx[gi0] : 0;
        int or1 = (gi1 < M) ? rowidx[gi1] : 0;
        bool a0 = o1_always || (gi0 < FLAP);
        bool a1 = o1_always || (gi1 < FLAP);
        #pragma unroll
        for (int nt = 0; nt < 8; nt++) {
            int col = n0 + wx * 64 + nt * 8 + tig * 2;
            int h = col >> 6, dd = col & 63;
            float2 b2 = *(const float2*)&bcomp[col];
            uint32_t lo;
            if (gi0 < M) {
                float v0 = acc[mt][nt][0] + b2.x, v1 = acc[mt][nt][1] + b2.y;
                if (a0) {
                    const float* o1p = &g_o1[((size_t)h * L1 + (o1_off + gi0)) * DH + dd];
                    v0 += o1p[0]; v1 += o1p[1];
                }
                uint32_t hi = splitpair(v0, v1, lo);
                *(uint32_t*)&g_nfh[(size_t)or0 * DIM + col] = hi;
                *(uint32_t*)&g_nfl[(size_t)or0 * DIM + col] = lo;
            }
            if (gi1 < M) {
                float v0 = acc[mt][nt][2] + b2.x, v1 = acc[mt][nt][3] + b2.y;
                if (a1) {
                    const float* o1p = &g_o1[((size_t)h * L1 + (o1_off + gi1)) * DH + dd];
                    v0 += o1p[0]; v1 += o1p[1];
                }
                uint32_t hi = splitpair(v0, v1, lo);
                *(uint32_t*)&g_nfh[(size_t)or1 * DIM + col] = hi;
                *(uint32_t*)&g_nfl[(size_t)or1 * DIM + col] = lo;
            }
        }
    }
}

__global__ void conv_split(const float* __restrict__ s,
                           __nv_bfloat16* __restrict__ h,
                           __nv_bfloat16* __restrict__ l, int n4)
{
    int i = blockIdx.x * 256 + threadIdx.x;
    if (i >= n4) return;
    float4 v = *(const float4*)&s[i * 4];
    float a[4] = {v.x, v.y, v.z, v.w};
    #pragma unroll
    for (int j = 0; j < 4; j++) {
        __nv_bfloat16 hh = __float2bfloat16(a[j]);
        h[i * 4 + j] = hh;
        l[i * 4 + j] = __float2bfloat16(a[j] - __bfloat162float(hh));
    }
}

__global__ void conv_wt(const float* __restrict__ W,
                        __nv_bfloat16* __restrict__ th,
                        __nv_bfloat16* __restrict__ tl)
{
    int i = blockIdx.x * 256 + threadIdx.x;
    if (i >= DIM * DIM) return;
    int k = i >> 9, n = i & 511;
    float v = W[i];
    __nv_bfloat16 hh = __float2bfloat16(v);
    th[n * DIM + k] = hh;
    tl[n * DIM + k] = __float2bfloat16(v - __bfloat162float(hh));
}

// composite: Wc[k][n] = scale * sum_c A[k][c] * O[c][n]; row k==DIM is the bias
__global__ void comp_kernel(const float* __restrict__ A, int ldA,
                            const float* __restrict__ bias,
                            const float* __restrict__ O, int C, float scale,
                            __nv_bfloat16* __restrict__ Bth,
                            __nv_bfloat16* __restrict__ Btl,
                            float* __restrict__ bc)
{
    int id = blockIdx.x * 256 + threadIdx.x;
    if (id >= (DIM + 1) * DIM) return;
    int k = id >> 9, n = id & 511;
    float acc = 0.f;
    if (k < DIM) {
        for (int c = 0; c < C; c++) acc += A[k * ldA + c] * O[c * DIM + n];
        acc *= scale;
        __nv_bfloat16 hh = __float2bfloat16(acc);
        Bth[n * DIM + k] = hh;
        Btl[n * DIM + k] = __float2bfloat16(acc - __bfloat162float(hh));
    } else {
        for (int c = 0; c < C; c++) acc += bias[c] * O[c * DIM + n];
        bc[n] = acc * scale;
    }
}

__global__ void prep_kernel(const float* __restrict__ onion,
                            const int* __restrict__ labels,
                            const int* __restrict__ closest,
                            const int* __restrict__ velo_idx,
                            const int* __restrict__ surf_idx,
                            const float* __restrict__ W_ws,
                            const float* __restrict__ b_ws,
                            const float* __restrict__ W_vc,
                            const float* __restrict__ b_vc)
{
    int i = blockIdx.x * 256 + threadIdx.x;
    if (i < L1) g_tok1src[i] = (i < FLAP) ? velo_idx[i] : surf_idx[i - FLAP];
    if (i < NTOK * DIM) g_tokacc[i] = 0.f;
    if (i < DIM * 64) {
        int k = i >> 6, n = i & 63;
        g_Wsc[i] = (n < SC) ? W_ws[k * SC + n] : W_vc[k * VC + n - SC];
    }
    if (i < 64) g_bsc[i] = (i < SC) ? b_ws[i] : b_vc[i - SC];
    if (i >= NPT_TOT) return;
    if (i < NVELO) {
        int lab = 0;
        #pragma unroll
        for (int l = 1; l < ONION; l++)
            if (onion[l * NVELO + i] > 0.5f) lab = l;
        g_ptrow[i] = velo_idx[i];
        g_ptgrp[i] = SC + lab * SC + labels[closest[i]];
    } else {
        int j = i - NVELO;
        int sr = (j < 16) ? j : j + 96;
        g_ptrow[i] = surf_idx[sr];
        g_ptgrp[i] = labels[j];
    }
}

__global__ void proj1_kernel(const float* __restrict__ Wq1,
                             const float* __restrict__ Wk1,
                             const float* __restrict__ Wv1)
{
    __shared__ float Ts[64][68];
    __shared__ float Ws[64][68];
    int h = blockIdx.y, t0 = blockIdx.x * 64;
    int tid = threadIdx.x, ty = tid >> 4, tx = tid & 15;
    #pragma unroll
    for (int e = tid; e < 4096; e += 256) {
        int t = e >> 6, d = e & 63;
        int gt = t0 + t;
        Ts[t][d] = (gt < L1) ? g_fx[g_tok1src[gt] * DIM + h * DH + d] : 0.f;
    }
    const float* Wm[3] = {Wq1, Wk1, Wv1};
    __nv_bfloat16* Oh[3] = {g_q1h, g_k1h, g_v1h};
    __nv_bfloat16* Ol[3] = {g_q1l, g_k1l, g_v1l};
    #pragma unroll
    for (int m = 0; m < 3; m++) {
        __syncthreads();
        #pragma unroll
        for (int e = tid; e < 4096; e += 256) Ws[e >> 6][e & 63] = Wm[m][e];
        __syncthreads();
        float acc[4][4] = {};
        #pragma unroll
        for (int x = 0; x < 64; x++) {
            float ar[4];
            #pragma unroll
            for (int i = 0; i < 4; i++) ar[i] = Ts[ty * 4 + i][x];
            float4 b4 = *(const float4*)&Ws[x][tx * 4];
            float br[4] = {b4.x, b4.y, b4.z, b4.w};
            #pragma unroll
            for (int i = 0; i < 4; i++)
                #pragma unroll
                for (int j = 0; j < 4; j++)
                    acc[i][j] += ar[i] * br[j];
        }
        float sc = (m == 0) ? ATT_SCALE : 1.f;
        #pragma unroll
        for (int i = 0; i < 4; i++) {
            int gt = t0 + ty * 4 + i;
            if (gt >= L1) continue;
            size_t base = (size_t)h * (L1 * DH) + (size_t)gt * DH + tx * 4;
            #pragma unroll
            for (int j = 0; j < 4; j++) {
                float f = acc[i][j] * sc;
                __nv_bfloat16 hh = __float2bfloat16(f);
                Oh[m][base + j] = hh;
                Ol[m][base + j] = __float2bfloat16(f - __bfloat162float(hh));
            }
        }
    }
}

// ---------------------------------------------------------------------------
// flash attention (unchanged from R12)
// ---------------------------------------------------------------------------
#define FL_STRIDE 144
#define FL_PLANE (64 * FL_STRIDE)
#define FL_BUF (4 * FL_PLANE)
#define FL_SMEM (2 * FL_BUF)
#define NKT ((L1 + 63) / 64)

__device__ __forceinline__ void fl_fill(uint32_t buf, int h, int kt, int tid)
{
    const __nv_bfloat16* pl[4];
    pl[0] = g_k1h; pl[1] = g_k1l; pl[2] = g_v1h; pl[3] = g_v1l;
    #pragma unroll
    for (int i = 0; i < 8; i++) {
        int s = tid + i * 256;
        int plane = s >> 9;
        int e = s & 511;
        int r = e >> 3, v = e & 7;
        int kk = kt * 64 + r;
        int sz = (kk < L1) ? 16 : 0;
        int kkc = (kk < L1) ? kk : (L1 - 1);
        CPA16(buf + plane * FL_PLANE + r * FL_STRIDE + v * 16,
              pl[plane] + (size_t)h * (L1 * DH) + (size_t)kkc * DH + v * 8, sz);
    }
}

__global__ void __launch_bounds__(256, 1) flashmma_kernel()
{
    extern __shared__ char sm[];
    uint32_t smb = smem_u32(sm);
    int tid = threadIdx.x, lane = tid & 31, w = tid >> 5;
    int h = blockIdx.y, q0 = blockIdx.x * 128;
    int g = lane >> 2, tq = lane & 3;

    {
        const __nv_bfloat16* qp[2] = {g_q1h, g_q1l};
        uint32_t qbuf = smb + FL_BUF;
        #pragma unroll
        for (int i = 0; i < 8; i++) {
            int s = tid + i * 256;
            int plane = s >> 10;
            int e = s & 1023;
            int r = e >> 3, v = e & 7;
            int gq = q0 + r;
            int sz = (gq < L1) ? 16 : 0;
            int gqc = (gq < L1) ? gq : (L1 - 1);
            CPA16(qbuf + plane * (128 * FL_STRIDE) + r * FL_STRIDE + v * 16,
                  qp[plane] + (size_t)h * (L1 * DH) + (size_t)gqc * DH + v * 8, sz);
        }
        CPA_COMMIT();
    }
    fl_fill(smb, h, 0, tid);
    CPA_COMMIT();

    CPA_WAIT1();
    __syncthreads();
    uint32_t qh[4][4], ql[4][4];
    {
        uint32_t qbuf = smb + FL_BUF;
        uint32_t qa = qbuf + (uint32_t)((w * 16 + (lane & 15)) * FL_STRIDE + (lane >> 4) * 16);
        #pragma unroll
        for (int kc = 0; kc < 4; kc++) {
            LDSM4(qh[kc], qa + kc * 32);
            LDSM4(ql[kc], qa + 128 * FL_STRIDE + kc * 32);
        }
    }
    __syncthreads();

    float o[4][2][4] = {};
    float m0f = -1e30f, m1f = -1e30f, l0f = 0.f, l1f = 0.f;

    for (int kt = 0; kt < NKT; kt++) {
        uint32_t cur = smb + (uint32_t)(kt & 1) * FL_BUF;
        if (kt + 1 < NKT) {
            fl_fill(smb + (uint32_t)((kt + 1) & 1) * FL_BUF, h, kt + 1, tid);
            CPA_COMMIT();
            CPA_WAIT1();
        } else {
            CPA_WAIT0();
        }
        __syncthreads();

        float s[4][2][4];
        #pragma unroll
        for (int nb = 0; nb < 4; nb++)
            #pragma unroll
            for (int ng = 0; ng < 2; ng++)
                #pragma unroll
                for (int e = 0; e < 4; e++) s[nb][ng][e] = 0.f;
        uint32_t kBase = cur + (uint32_t)((lane & 15) * FL_STRIDE + (lane >> 4) * 16);
        #pragma unroll
        for (int nb = 0; nb < 4; nb++) {
            #pragma unroll
            for (int kc = 0; kc < 4; kc++) {
                uint32_t bh[4], bl[4];
                uint32_t off = (uint32_t)(nb * 16 * FL_STRIDE + kc * 32);
                LDSM4(bh, kBase + off);
                LDSM4(bl, kBase + FL_PLANE + off);
                MMA16816(s[nb][0], qh[kc], bh[0], bh[2]);
                MMA16816(s[nb][0], qh[kc], bl[0], bl[2]);
                MMA16816(s[nb][0], ql[kc], bh[0], bh[2]);
                MMA16816(s[nb][1], qh[kc], bh[1], bh[3]);
                MMA16816(s[nb][1], qh[kc], bl[1], bl[3]);
                MMA16816(s[nb][1], ql[kc], bh[1], bh[3]);
            }
        }
        int ktb = kt * 64;
        if (ktb + 64 > L1) {
            #pragma unroll
            for (int nb = 0; nb < 4; nb++)
                #pragma unroll
                for (int ng = 0; ng < 2; ng++) {
                    int kk0 = ktb + nb * 16 + ng * 8 + tq * 2;
                    if (kk0 >= L1)     { s[nb][ng][0] = -1e30f; s[nb][ng][2] = -1e30f; }
                    if (kk0 + 1 >= L1) { s[nb][ng][1] = -1e30f; s[nb][ng][3] = -1e30f; }
                }
        }
        float mx0 = m0f, mx1 = m1f;
        #pragma unroll
        for (int nb = 0; nb < 4; nb++)
            #pragma unroll
            for (int ng = 0; ng < 2; ng++) {
                mx0 = fmaxf(mx0, fmaxf(s[nb][ng][0], s[nb][ng][1]));
                mx1 = fmaxf(mx1, fmaxf(s[nb][ng][2], s[nb][ng][3]));
            }
        mx0 = fmaxf(mx0, __shfl_xor_sync(0xffffffffu, mx0, 1));
        mx0 = fmaxf(mx0, __shfl_xor_sync(0xffffffffu, mx0, 2));
        mx1 = fmaxf(mx1, __shfl_xor_sync(0xffffffffu, mx1, 1));
        mx1 = fmaxf(mx1, __shfl_xor_sync(0xffffffffu, mx1, 2));
        float c0 = __expf(m0f - mx0), c1 = __expf(m1f - mx1);
        m0f = mx0; m1f = mx1;
        float rs0 = 0.f, rs1 = 0.f;
        #pragma unroll
        for (int nb = 0; nb < 4; nb++)
            #pragma unroll
            for (int ng = 0; ng < 2; ng++) {
                float p0 = __expf(s[nb][ng][0] - mx0);
                float p1 = __expf(s[nb][ng][1] - mx0);
                float p2 = __expf(s[nb][ng][2] - mx1);
                float p3 = __expf(s[nb][ng][3] - mx1);
                s[nb][ng][0] = p0; s[nb][ng][1] = p1;
                s[nb][ng][2] = p2; s[nb][ng][3] = p3;
                rs0 += p0 + p1; rs1 += p2 + p3;
            }
        rs0 += __shfl_xor_sync(0xffffffffu, rs0, 1);
        rs0 += __shfl_xor_sync(0xffffffffu, rs0, 2);
        rs1 += __shfl_xor_sync(0xffffffffu, rs1, 1);
        rs1 += __shfl_xor_sync(0xffffffffu, rs1, 2);
        l0f = l0f * c0 + rs0;
        l1f = l1f * c1 + rs1;
        #pragma unroll
        for (int nd = 0; nd < 4; nd++)
            #pragma unroll
            for (int ng = 0; ng < 2; ng++) {
                o[nd][ng][0] *= c0; o[nd][ng][1] *= c0;
                o[nd][ng][2] *= c1; o[nd][ng][3] *= c1;
            }
        uint32_t vBase = cur + 2 * FL_PLANE +
            (uint32_t)(((lane & 7) + ((lane >> 4) & 1) * 8) * FL_STRIDE + ((lane >> 3) & 1) * 16);
        #pragma unroll
        for (int nbk = 0; nbk < 4; nbk++) {
            uint32_t pah[4], pal[4];
            #pragma unroll
            for (int hv = 0; hv < 2; hv++)
                #pragma unroll
                for (int pr = 0; pr < 2; pr++) {
                    float a0 = s[nbk][hv][pr * 2], a1 = s[nbk][hv][pr * 2 + 1];
                    uint32_t lo;
                    uint32_t hp = splitpair(a0, a1, lo);
                    pah[hv * 2 + pr] = hp;
                    pal[hv * 2 + pr] = lo;
                }
            #pragma unroll
            for (int nd = 0; nd < 4; nd++) {
                uint32_t vbh[4], vbl[4];
                uint32_t off = (uint32_t)(nbk * 16 * FL_STRIDE + nd * 32);
                LDSM4T(vbh, vBase + off);
                LDSM4T(vbl, vBase + FL_PLANE + off);
                MMA16816(o[nd][0], pah, vbh[0], vbh[2]);
                MMA16816(o[nd][0], pah, vbl[0], vbl[2]);
                MMA16816(o[nd][0], pal, vbh[0], vbh[2]);
                MMA16816(o[nd][1], pah, vbh[1], vbh[3]);
                MMA16816(o[nd][1], pah, vbl[1], vbl[3]);
                MMA16816(o[nd][1], pal, vbh[1], vbh[3]);
            }
        }
        __syncthreads();
    }

    float i0 = 1.f / l0f, i1 = 1.f / l1f;
    int r0 = q0 + w * 16 + g, r1 = r0 + 8;
    #pragma unroll
    for (int nd = 0; nd < 4; nd++)
        #pragma unroll
        for (int ng = 0; ng < 2; ng++) {
            int col = nd * 16 + ng * 8 + tq * 2;
            if (r0 < L1) {
                float2 v = make_float2(o[nd][ng][0] * i0, o[nd][ng][1] * i0);
                *(float2*)&g_o1[(size_t)h * (L1 * DH) + (size_t)r0 * DH + col] = v;
            }
            if (r1 < L1) {
                float2 v = make_float2(o[nd][ng][2] * i1, o[nd][ng][3] * i1);
                *(float2*)&g_o1[(size_t)h * (L1 * DH) + (size_t)r1 * DH + col] = v;
            }
        }
}

#define ACC_CHUNK 1024
__global__ void pool_accum()
{
    __shared__ float sa[64][64];
    int d0 = blockIdx.y * 64, p0 = blockIdx.x * ACC_CHUNK;
    int tid = threadIdx.x, dd = tid & 63, q4 = tid >> 6;
    #pragma unroll
    for (int e = tid; e < 4096; e += 256) ((float*)sa)[e] = 0.f;
    __syncthreads();
    int pend = min(p0 + ACC_CHUNK, NPT_TOT);
    for (int p = p0 + q4; p < pend; p += 4) {
        float v = g_fx[g_ptrow[p] * DIM + d0 + dd];
        atomicAdd(&sa[g_ptgrp[p]][dd], v);
    }
    __syncthreads();
    #pragma unroll
    for (int e = tid; e < 4096; e += 256) {
        int g = e >> 6, d = e & 63;
        float v = sa[g][d];
        if (v != 0.f) atomicAdd(&g_tokacc[g * DIM + d0 + d], v);
    }
}

__global__ void ln_kernel(const float* __restrict__ gamma,
                          const float* __restrict__ beta)
{
    int d = threadIdx.x;
    const float n_s = 1.f / (float)SKEEP, n_v = 1.f / (float)NVELO;
    float s = 0.f;
    #pragma unroll
    for (int t = 0; t < NTOK; t++)
        s += g_tokacc[t * DIM + d] * ((t < SC) ? n_s : n_v);
    float mu = s * (1.f / NTOK);
    float v2 = 0.f;
    #pragma unroll
    for (int t = 0; t < NTOK; t++) {
        float dv = g_tokacc[t * DIM + d] * ((t < SC) ? n_s : n_v) - mu;
        v2 += dv * dv;
    }
    float inv = rsqrtf(v2 * (1.f / NTOK) + LN_EPS);
    #pragma unroll
    for (int t = 0; t < NTOK; t++) {
        float val = g_tokacc[t * DIM + d] * ((t < SC) ? n_s : n_v);
        g_toknorm[t * DIM + d] = (val - mu) * inv * gamma[t] + beta[t];
    }
}

__global__ void attn2_kernel(const float* __restrict__ Wq,
                             const float* __restrict__ Wk,
                             const float* __restrict__ Wv)
{
    extern __shared__ float sm2[];
    float (*tk)[68] = (float(*)[68])sm2;
    float (*qs)[68] = tk + 64;
    float (*ks)[68] = qs + 64;
    float (*vs)[68] = ks + 64;
    float (*ss)[68] = vs + 64;
    int h = blockIdx.x, tid = threadIdx.x;
    #pragma unroll
    for (int e = tid; e < 4096; e += 256) {
        int t = e >> 6, d = e & 63;
        tk[t][d] = g_toknorm[t * DIM + h * DH + d];
    }
    __syncthreads();
    #pragma unroll
    for (int e = tid; e < 4096; e += 256) {
        int t = e >> 6, d = e & 63;
        float aq = 0.f, ak = 0.f, av = 0.f;
        for (int x = 0; x < 64; x++) {
            float tv = tk[t][x];
            aq += tv * Wq[x * 64 + d];
            ak += tv * Wk[x * 64 + d];
            av += tv * Wv[x * 64 + d];
        }
        qs[t][d] = aq; ks[t][d] = ak; vs[t][d] = av;
    }
    __syncthreads();
    #pragma unroll
    for (int e = tid; e < 4096; e += 256) {
        int t = e >> 6, u = e & 63;
        float sv = 0.f;
        for (int d = 0; d < 64; d++) sv += qs[t][d] * ks[u][d];
        ss[t][u] = sv * ATT_SCALE;
    }
    __syncthreads();
    if (tid < 64) {
        float mx = -1e30f;
        for (int j = 0; j < 64; j++) mx = fmaxf(mx, ss[tid][j]);
        float sum = 0.f;
        for (int j = 0; j < 64; j++) {
            float p = __expf(ss[tid][j] - mx);
            ss[tid][j] = p; sum += p;
        }
        float inv = 1.f / sum;
        for (int j = 0; j < 64; j++) ss[tid][j] *= inv;
    }
    __syncthreads();
    #pragma unroll
    for (int e = tid; e < 4096; e += 256) {
        int t = e >> 6, d = e & 63;
        float o = 0.f;
        for (int u = 0; u < 64; u++) o += ss[t][u] * vs[u][d];
        g_outtok[h * (NTOK * DH) + t * DH + d] = o;
    }
}

// build composite token matrix: rows 0-3 = out_surf (flat-reshape), 4-63 = out_velo
__global__ void mat_out_kernel()
{
    int i = blockIdx.x * 256 + threadIdx.x;
    if (i >= NTOK * DIM) return;
    int t = i >> 9, d = i & 511;
    float v;
    if (t < SC) {
        int f = t * 512 + d;
        v = g_outtok[(f >> 8) * 4096 + (((f >> 6) & 3) << 6) + (f & 63)];
    } else {
        int r = t - SC;
        v = g_outtok[(d >> 6) * 4096 + (SC + r) * 64 + (d & 63)];
    }
    g_osc[i] = v;
}

extern "C" void kernel_launch(void* const* d_in, const int* in_sizes, int n_in,
                              void* d_out, int out_size)
{
    (void)in_sizes; (void)n_in; (void)out_size;
    const float* x     = (const float*)d_in[0];
    const float* onion = (const float*)d_in[1];
    const float* W_fx  = (const float*)d_in[2];
    const float* b_fx  = (const float*)d_in[3];
    const float* W_x   = (const float*)d_in[4];
    const float* b_x   = (const float*)d_in[5];
    const float* Wq1   = (const float*)d_in[6];
    const float* Wk1   = (const float*)d_in[7];
    const float* Wv1   = (const float*)d_in[8];
    const float* Wq    = (const float*)d_in[9];
    const float* Wk    = (const float*)d_in[10];
    const float* Wv    = (const float*)d_in[11];
    const float* gamma = (const float*)d_in[12];
    const float* beta  = (const float*)d_in[13];
    const float* W_ws  = (const float*)d_in[14];
    const float* b_ws  = (const float*)d_in[15];
    const float* W_vv  = (const float*)d_in[16];
    const float* b_vv  = (const float*)d_in[17];
    const float* W_vc  = (const float*)d_in[18];
    const float* b_vc  = (const float*)d_in[19];
    const float* W_out = (const float*)d_in[20];
    const float* b_out = (const float*)d_in[21];
    const int* surf_idx = (const int*)d_in[22];
    const int* velo_idx = (const int*)d_in[23];
    const int* closest  = (const int*)d_in[25];
    const int* labels   = (const int*)d_in[26];
    float* out = (float*)d_out;

    float *p_fx, *p_Wsc, *p_bsc, *p_osc, *p_bc;
    __nv_bfloat16 *p_xh, *p_xl, *p_xmh, *p_xml, *p_nfh, *p_nfl, *p_Wth, *p_Wtl, *p_Wcth, *p_Wctl;
    cudaGetSymbolAddress((void**)&p_fx, g_fx);
    cudaGetSymbolAddress((void**)&p_Wsc, g_Wsc);
    cudaGetSymbolAddress((void**)&p_bsc, g_bsc);
    cudaGetSymbolAddress((void**)&p_osc, g_osc);
    cudaGetSymbolAddress((void**)&p_bc, g_bc);
    cudaGetSymbolAddress((void**)&p_xh, g_xh);
    cudaGetSymbolAddress((void**)&p_xl, g_xl);
    cudaGetSymbolAddress((void**)&p_xmh, g_xmh);
    cudaGetSymbolAddress((void**)&p_xml, g_xml);
    cudaGetSymbolAddress((void**)&p_nfh, g_nfh);
    cudaGetSymbolAddress((void**)&p_nfl, g_nfl);
    cudaGetSymbolAddress((void**)&p_Wth, g_Wth);
    cudaGetSymbolAddress((void**)&p_Wtl, g_Wtl);
    cudaGetSymbolAddress((void**)&p_Wcth, g_Wcth);
    cudaGetSymbolAddress((void**)&p_Wctl, g_Wctl);

    cudaFuncSetAttribute(attn2_kernel, cudaFuncAttributeMaxDynamicSharedMemorySize, ATTN2_SMEM);
    cudaFuncSetAttribute(gemm_mma, cudaFuncAttributeMaxDynamicSharedMemorySize, GMMA_SMEM);
    cudaFuncSetAttribute(gemm_feat, cudaFuncAttributeMaxDynamicSharedMemorySize, GMMA_SMEM);
    cudaFuncSetAttribute(flashmma_kernel, cudaFuncAttributeMaxDynamicSharedMemorySize, FL_SMEM);

    const int NELEM4 = NPTS * DIM / 4;
    dim3 gTC(DIM / 128, (NPTS + 127) / 128);

    conv_split<<<(NELEM4 + 255) / 256, 256>>>(x, p_xh, p_xl, NELEM4);
    conv_wt<<<(DIM * DIM + 255) / 256, 256>>>(W_fx, p_Wth, p_Wtl);
    conv_wt<<<(DIM * DIM + 255) / 256, 256>>>(W_x, p_Wth + DIM * DIM, p_Wtl + DIM * DIM);
    conv_wt<<<(DIM * DIM + 255) / 256, 256>>>(W_out, p_Wth + 2 * DIM * DIM, p_Wtl + 2 * DIM * DIM);

    gemm_mma<<<gTC, 256, GMMA_SMEM>>>(p_xh, p_xl, p_Wth, p_Wtl, b_fx, p_fx, nullptr, nullptr, NPTS);
    gemm_mma<<<gTC, 256, GMMA_SMEM>>>(p_xh, p_xl, p_Wth + DIM * DIM, p_Wtl + DIM * DIM, b_x,
                                      nullptr, p_xmh, p_xml, NPTS);

    prep_kernel<<<(PREP_N + 255) / 256, 256>>>(onion, labels, closest, velo_idx, surf_idx,
                                               W_ws, b_ws, W_vc, b_vc);

    proj1_kernel<<<dim3((L1 + 63) / 64, HEADS), 256>>>(Wq1, Wk1, Wv1);
    flashmma_kernel<<<dim3((L1 + 127) / 128, HEADS), 256, FL_SMEM>>>();

    pool_accum<<<dim3((NPT_TOT + ACC_CHUNK - 1) / ACC_CHUNK, DIM / 64), 256>>>();
    ln_kernel<<<1, DIM>>>(gamma, beta);
    attn2_kernel<<<HEADS, 256, ATTN2_SMEM>>>(Wq, Wk, Wv);
    mat_out_kernel<<<(NTOK * DIM + 255) / 256, 256>>>();

    int compBlocks = ((DIM + 1) * DIM + 255) / 256;
    comp_kernel<<<compBlocks, 256>>>(p_Wsc, 64, p_bsc, p_osc, 64, 0.5f,
                                     p_Wcth, p_Wctl, p_bc);
    comp_kernel<<<compBlocks, 256>>>(W_vv, VC, b_vv, p_osc + SC * DIM, VC, 1.0f,
                                     p_Wcth + DIM * DIM, p_Wctl + DIM * DIM, p_bc + DIM);

    gemm_feat<<<dim3(DIM / 128, (NSURF + 127) / 128), 256, GMMA_SMEM>>>(
        p_Wcth, p_Wctl, p_bc, surf_idx, NSURF, FLAP, 1);
    gemm_feat<<<dim3(DIM / 128, (NVELO + 127) / 128), 256, GMMA_SMEM>>>(
        p_Wcth + DIM * DIM, p_Wctl + DIM * DIM, p_bc + DIM, velo_idx, NVELO, 0, 0);

    gemm_mma<<<gTC, 256, GMMA_SMEM>>>(p_nfh, p_nfl, p_Wth + 2 * DIM * DIM, p_Wtl + 2 * DIM * DIM,
                                      b_out, out, nullptr, nullptr, NPTS);
}

// round 14
// speedup vs baseline: 3.7727x; 1.1920x over previous
#include <cuda_runtime.h>
#include <cuda_bf16.h>
#include <cuda_fp16.h>
#include <cstdint>

#define HEADS 8
#define DH 64
#define DIM 512
#define ONION 15
#define SC 4
#define NVELO 28504
#define NSURF 3682
#define NPTS 32186
#define SKEEP 3586
#define FLAP 500
#define NTOK 64
#define L1 4182
#define VC 60
#define NPT_TOT (NVELO + SKEEP)
#define PREP_N ((NTOK * DIM) > NPT_TOT ? (NTOK * DIM) : NPT_TOT)
#define ATT_SCALE 0.125f
#define LN_EPS 1e-5f
#define ATTN2_SMEM (5 * 64 * 68 * 4)

// ---------------- scratch ----------------
__device__ float g_fx[NPTS * DIM];
__device__ float g_o1[HEADS * L1 * DH];
__device__ __half g_q1f[HEADS * L1 * DH];
__device__ __half g_k1f[HEADS * L1 * DH];
__device__ __half g_v1f[HEADS * L1 * DH];
__device__ int   g_tok1src[L1];
__device__ int   g_ptrow[NPT_TOT];
__device__ int   g_ptgrp[NPT_TOT];
__device__ float g_tokacc[NTOK * DIM];
__device__ float g_toknorm[NTOK * DIM];
__device__ float g_outtok[HEADS * NTOK * DH];
__device__ float g_osc[NTOK * DIM];
__device__ float g_Wsc[DIM * 64];
__device__ float g_bsc[64];
__device__ __nv_bfloat16 g_xh[NPTS * DIM];
__device__ __nv_bfloat16 g_xl[NPTS * DIM];
__device__ __nv_bfloat16 g_xmh[NPTS * DIM];
__device__ __nv_bfloat16 g_xml[NPTS * DIM];
__device__ __nv_bfloat16 g_nfh[NPTS * DIM];
__device__ __nv_bfloat16 g_nfl[NPTS * DIM];
__device__ __nv_bfloat16 g_Wth[3 * DIM * DIM];
__device__ __nv_bfloat16 g_Wtl[3 * DIM * DIM];
__device__ __nv_bfloat16 g_Wcth[2 * DIM * DIM];
__device__ __nv_bfloat16 g_Wctl[2 * DIM * DIM];
__device__ float g_bc[2 * DIM];

// ---------------- helpers --------
__device__ __forceinline__ uint32_t smem_u32(const void* p) {
    uint32_t a;
    asm("{ .reg .u64 t; cvta.to.shared.u64 t, %1; cvt.u32.u64 %0, t; }" : "=r"(a) : "l"(p));
    return a;
}
#define CPA16(dst, src, sz) \
    asm volatile("cp.async.cg.shared.global [%0], [%1], 16, %2;" \
                 :: "r"(dst), "l"(src), "r"(sz) : "memory")
#define CPA_COMMIT() asm volatile("cp.async.commit_group;" ::: "memory")
#define CPA_WAIT0()  asm volatile("cp.async.wait_group 0;" ::: "memory")
#define CPA_WAIT1()  asm volatile("cp.async.wait_group 1;" ::: "memory")
#define LDSM4(r, addr) \
    asm volatile("ldmatrix.sync.aligned.m8n8.x4.shared.b16 {%0,%1,%2,%3}, [%4];" \
                 : "=r"((r)[0]), "=r"((r)[1]), "=r"((r)[2]), "=r"((r)[3]) : "r"(addr))
#define LDSM4T(r, addr) \
    asm volatile("ldmatrix.sync.aligned.m8n8.x4.trans.shared.b16 {%0,%1,%2,%3}, [%4];" \
                 : "=r"((r)[0]), "=r"((r)[1]), "=r"((r)[2]), "=r"((r)[3]) : "r"(addr))
#define MMA16816(c, a, b0v, b1v) \
    asm volatile("mma.sync.aligned.m16n8k16.row.col.f32.bf16.bf16.f32 " \
                 "{%0,%1,%2,%3},{%4,%5,%6,%7},{%8,%9},{%0,%1,%2,%3};" \
                 : "+f"((c)[0]), "+f"((c)[1]), "+f"((c)[2]), "+f"((c)[3]) \
                 : "r"((a)[0]), "r"((a)[1]), "r"((a)[2]), "r"((a)[3]), "r"(b0v), "r"(b1v))
#define MMAH16816(c, a, b0v, b1v) \
    asm volatile("mma.sync.aligned.m16n8k16.row.col.f32.f16.f16.f32 " \
                 "{%0,%1,%2,%3},{%4,%5,%6,%7},{%8,%9},{%0,%1,%2,%3};" \
                 : "+f"((c)[0]), "+f"((c)[1]), "+f"((c)[2]), "+f"((c)[3]) \
                 : "r"((a)[0]), "r"((a)[1]), "r"((a)[2]), "r"((a)[3]), "r"(b0v), "r"(b1v))
__device__ __forceinline__ uint32_t pk2(float lo, float hi) {
    uint32_t r;
    asm("cvt.rn.bf16x2.f32 %0, %1, %2;" : "=r"(r) : "f"(hi), "f"(lo));
    return r;
}
__device__ __forceinline__ uint32_t pk2h(float lo, float hi) {
    uint32_t r;
    asm("cvt.rn.f16x2.f32 %0, %1, %2;" : "=r"(r) : "f"(hi), "f"(lo));
    return r;
}
__device__ __forceinline__ uint32_t splitpair(float v0, float v1, uint32_t& lopack) {
    uint32_t hp = pk2(v0, v1);
    __nv_bfloat162 hb = *(__nv_bfloat162*)&hp;
    lopack = pk2(v0 - __bfloat162float(hb.x), v1 - __bfloat162float(hb.y));
    return hp;
}

// ---------------------------------------------------------------------------
// split-bf16 HMMA GEMM (unchanged)
// ---------------------------------------------------------------------------
#define PLANE_B 10240
#define BUF_B   (4 * PLANE_B)
#define GMMA_SMEM (2 * BUF_B)

__device__ __forceinline__ void fill_chunk(
    uint32_t sb, const __nv_bfloat16* __restrict__ Ah, const __nv_bfloat16* __restrict__ Al,
    const __nv_bfloat16* __restrict__ Bh, const __nv_bfloat16* __restrict__ Bl,
    const int* __restrict__ rowidx,
    int m0, int n0, int k0, int M, int tid)
{
    #pragma unroll
    for (int hf = 0; hf < 2; hf++) {
        int s = tid + hf * 256;
        int r = s >> 2, v = s & 3;
        uint32_t off = (uint32_t)(r * 80 + v * 16);
        int gm = m0 + r;
        int szA = (gm < M) ? 16 : 0;
        int gmc = (gm < M) ? gm : (M - 1);
        int arow = rowidx ? rowidx[gmc] : gmc;
        CPA16(sb + off,               Ah + (size_t)arow * DIM + k0 + v * 8, szA);
        CPA16(sb + PLANE_B + off,     Al + (size_t)arow * DIM + k0 + v * 8, szA);
        CPA16(sb + 2 * PLANE_B + off, Bh + (size_t)(n0 + r) * DIM + k0 + v * 8, 16);
        CPA16(sb + 3 * PLANE_B + off, Bl + (size_t)(n0 + r) * DIM + k0 + v * 8, 16);
    }
}

__device__ __forceinline__ void mma_mainloop(
    uint32_t smb, const __nv_bfloat16* Ah, const __nv_bfloat16* Al,
    const __nv_bfloat16* Bth, const __nv_bfloat16* Btl,
    const int* rowidx, int m0, int n0, int M, int tid, int lane, int wy, int wx,
    float acc[2][8][4])
{
    uint32_t aBase = (uint32_t)((wy * 32 + (lane & 15)) * 80 + (lane >> 4) * 16);
    uint32_t bBase = (uint32_t)((wx * 64 + (lane & 15)) * 80 + (lane >> 4) * 16);
    fill_chunk(smb, Ah, Al, Bth, Btl, rowidx, m0, n0, 0, M, tid);
    CPA_COMMIT();
    for (int ch = 0; ch < 16; ch++) {
        uint32_t sb = smb + (uint32_t)(ch & 1) * BUF_B;
        CPA_WAIT0();
        __syncthreads();
        if (ch < 15) {
            fill_chunk(smb + (uint32_t)((ch + 1) & 1) * BUF_B,
                       Ah, Al, Bth, Btl, rowidx, m0, n0, (ch + 1) * 32, M, tid);
            CPA_COMMIT();
        }
        uint32_t AH = sb, AL = sb + PLANE_B, BH = sb + 2 * PLANE_B, BL = sb + 3 * PLANE_B;
        #pragma unroll
        for (int ks = 0; ks < 2; ks++) {
            uint32_t ko = (uint32_t)(ks * 32);
            uint32_t ah[2][4], al[2][4];
            LDSM4(ah[0], AH + aBase + ko);
            LDSM4(ah[1], AH + aBase + 1280 + ko);
            LDSM4(al[0], AL + aBase + ko);
            LDSM4(al[1], AL + aBase + 1280 + ko);
            #pragma unroll
            for (int np = 0; np < 4; np++) {
                uint32_t bh[4], bl[4];
                uint32_t boff = bBase + (uint32_t)(np * 16 * 80) + ko;
                LDSM4(bh, BH + boff);
                LDSM4(bl, BL + boff);
                #pragma unroll
                for (int mt = 0; mt < 2; mt++) {
                    float* c0 = acc[mt][np * 2];
                    float* c1 = acc[mt][np * 2 + 1];
                    MMA16816(c0, ah[mt], bh[0], bh[2]);
                    MMA16816(c0, ah[mt], bl[0], bl[2]);
                    MMA16816(c0, al[mt], bh[0], bh[2]);
                    MMA16816(c1, ah[mt], bh[1], bh[3]);
                    MMA16816(c1, ah[mt], bl[1], bl[3]);
                    MMA16816(c1, al[mt], bh[1], bh[3]);
                }
            }
        }
        __syncthreads();
    }
}

__global__ void __launch_bounds__(256, 2) gemm_mma(
    const __nv_bfloat16* __restrict__ Ah, const __nv_bfloat16* __restrict__ Al,
    const __nv_bfloat16* __restrict__ Bth, const __nv_bfloat16* __restrict__ Btl,
    const float* __restrict__ bias, float* __restrict__ Cf,
    __nv_bfloat16* __restrict__ Ch, __nv_bfloat16* __restrict__ Cl, int M)
{
    extern __shared__ char smbuf[];
    uint32_t smb = smem_u32(smbuf);
    int tid = threadIdx.x, lane = tid & 31, wid = tid >> 5;
    int wy = wid & 3, wx = wid >> 2;
    int m0 = blockIdx.y * 128, n0 = blockIdx.x * 128;
    float acc[2][8][4] = {};
    mma_mainloop(smb, Ah, Al, Bth, Btl, nullptr, m0, n0, M, tid, lane, wy, wx, acc);

    int g = lane >> 2, tig = lane & 3;
    #pragma unroll
    for (int mt = 0; mt < 2; mt++) {
        int r0 = m0 + wy * 32 + mt * 16 + g;
        #pragma unroll
        for (int nt = 0; nt < 8; nt++) {
            int col = n0 + wx * 64 + nt * 8 + tig * 2;
            float2 b2 = *(const float2*)&bias[col];
            float v00 = acc[mt][nt][0] + b2.x, v01 = acc[mt][nt][1] + b2.y;
            float v10 = acc[mt][nt][2] + b2.x, v11 = acc[mt][nt][3] + b2.y;
            if (Cf) {
                if (r0 < M)     *(float2*)&Cf[(size_t)r0 * DIM + col] = make_float2(v00, v01);
                if (r0 + 8 < M) *(float2*)&Cf[(size_t)(r0 + 8) * DIM + col] = make_float2(v10, v11);
            } else {
                uint32_t lo;
                if (r0 < M) {
                    uint32_t hi = splitpair(v00, v01, lo);
                    *(uint32_t*)&Ch[(size_t)r0 * DIM + col] = hi;
                    *(uint32_t*)&Cl[(size_t)r0 * DIM + col] = lo;
                }
                if (r0 + 8 < M) {
                    uint32_t hi = splitpair(v10, v11, lo);
                    *(uint32_t*)&Ch[(size_t)(r0 + 8) * DIM + col] = hi;
                    *(uint32_t*)&Cl[(size_t)(r0 + 8) * DIM + col] = lo;
                }
            }
        }
    }
}

__global__ void __launch_bounds__(256, 2) gemm_feat(
    const __nv_bfloat16* __restrict__ Bth, const __nv_bfloat16* __restrict__ Btl,
    const float* __restrict__ bcomp, const int* __restrict__ rowidx,
    int M, int o1_off, int o1_always)
{
    extern __shared__ char smbuf[];
    uint32_t smb = smem_u32(smbuf);
    int tid = threadIdx.x, lane = tid & 31, wid = tid >> 5;
    int wy = wid & 3, wx = wid >> 2;
    int m0 = blockIdx.y * 128, n0 = blockIdx.x * 128;
    float acc[2][8][4] = {};
    mma_mainloop(smb, g_xmh, g_xml, Bth, Btl, rowidx, m0, n0, M, tid, lane, wy, wx, acc);

    int g = lane >> 2, tig = lane & 3;
    #pragma unroll
    for (int mt = 0; mt < 2; mt++) {
        int gi0 = m0 + wy * 32 + mt * 16 + g;
        int gi1 = gi0 + 8;
        int or0 = (gi0 < M) ? rowidx[gi0] : 0;
        int or1 = (gi1 < M) ? rowidx[gi1] : 0;
        bool a0 = o1_always || (gi0 < FLAP);
        bool a1 = o1_always || (gi1 < FLAP);
        #pragma unroll
        for (int nt = 0; nt < 8; nt++) {
            int col = n0 + wx * 64 + nt * 8 + tig * 2;
            int h = col >> 6, dd = col & 63;
            float2 b2 = *(const float2*)&bcomp[col];
            uint32_t lo;
            if (gi0 < M) {
                float v0 = acc[mt][nt][0] + b2.x, v1 = acc[mt][nt][1] + b2.y;
                if (a0) {
                    const float* o1p = &g_o1[((size_t)h * L1 + (o1_off + gi0)) * DH + dd];
                    v0 += o1p[0]; v1 += o1p[1];
                }
                uint32_t hi = splitpair(v0, v1, lo);
                *(uint32_t*)&g_nfh[(size_t)or0 * DIM + col] = hi;
                *(uint32_t*)&g_nfl[(size_t)or0 * DIM + col] = lo;
            }
            if (gi1 < M) {
                float v0 = acc[mt][nt][2] + b2.x, v1 = acc[mt][nt][3] + b2.y;
                if (a1) {
                    const float* o1p = &g_o1[((size_t)h * L1 + (o1_off + gi1)) * DH + dd];
                    v0 += o1p[0]; v1 += o1p[1];
                }
                uint32_t hi = splitpair(v0, v1, lo);
                *(uint32_t*)&g_nfh[(size_t)or1 * DIM + col] = hi;
                *(uint32_t*)&g_nfl[(size_t)or1 * DIM + col] = lo;
            }
        }
    }
}

// conv_split also builds tok1src (so proj1 no longer depends on prep)
__global__ void conv_split(const float* __restrict__ s,
                           __nv_bfloat16* __restrict__ h,
                           __nv_bfloat16* __restrict__ l, int n4,
                           const int* __restrict__ velo_idx,
                           const int* __restrict__ surf_idx)
{
    int i = blockIdx.x * 256 + threadIdx.x;
    if (velo_idx && i < L1)
        g_tok1src[i] = (i < FLAP) ? velo_idx[i] : surf_idx[i - FLAP];
    if (i >= n4) return;
    float4 v = *(const float4*)&s[i * 4];
    float a[4] = {v.x, v.y, v.z, v.w};
    #pragma unroll
    for (int j = 0; j < 4; j++) {
        __nv_bfloat16 hh = __float2bfloat16(a[j]);
        h[i * 4 + j] = hh;
        l[i * 4 + j] = __float2bfloat16(a[j] - __bfloat162float(hh));
    }
}

// 3 weights transposed+split in one launch
__global__ void conv_wt3(const float* __restrict__ W0, const float* __restrict__ W1,
                         const float* __restrict__ W2)
{
    int i = blockIdx.x * 256 + threadIdx.x;
    if (i >= 3 * DIM * DIM) return;
    int w = i / (DIM * DIM), r = i % (DIM * DIM);
    const float* W = (w == 0) ? W0 : ((w == 1) ? W1 : W2);
    int k = r >> 9, n = r & 511;
    float v = W[r];
    __nv_bfloat16 hh = __float2bfloat16(v);
    g_Wth[w * DIM * DIM + n * DIM + k] = hh;
    g_Wtl[w * DIM * DIM + n * DIM + k] = __float2bfloat16(v - __bfloat162float(hh));
}

__global__ void comp_kernel(const float* __restrict__ A, int ldA,
                            const float* __restrict__ bias,
                            const float* __restrict__ O, int C, float scale,
                            __nv_bfloat16* __restrict__ Bth,
                            __nv_bfloat16* __restrict__ Btl,
                            float* __restrict__ bc)
{
    int id = blockIdx.x * 256 + threadIdx.x;
    if (id >= (DIM + 1) * DIM) return;
    int k = id >> 9, n = id & 511;
    float acc = 0.f;
    if (k < DIM) {
        for (int c = 0; c < C; c++) acc += A[k * ldA + c] * O[c * DIM + n];
        acc *= scale;
        __nv_bfloat16 hh = __float2bfloat16(acc);
        Bth[n * DIM + k] = hh;
        Btl[n * DIM + k] = __float2bfloat16(acc - __bfloat162float(hh));
    } else {
        for (int c = 0; c < C; c++) acc += bias[c] * O[c * DIM + n];
        bc[n] = acc * scale;
    }
}

__global__ void prep_kernel(const float* __restrict__ onion,
                            const int* __restrict__ labels,
                            const int* __restrict__ closest,
                            const int* __restrict__ velo_idx,
                            const int* __restrict__ surf_idx,
                            const float* __restrict__ W_ws,
                            const float* __restrict__ b_ws,
                            const float* __restrict__ W_vc,
                            const float* __restrict__ b_vc)
{
    int i = blockIdx.x * 256 + threadIdx.x;
    if (i < NTOK * DIM) g_tokacc[i] = 0.f;
    if (i < DIM * 64) {
        int k = i >> 6, n = i & 63;
        g_Wsc[i] = (n < SC) ? W_ws[k * SC + n] : W_vc[k * VC + n - SC];
    }
    if (i < 64) g_bsc[i] = (i < SC) ? b_ws[i] : b_vc[i - SC];
    if (i >= NPT_TOT) return;
    if (i < NVELO) {
        int lab = 0;
        #pragma unroll
        for (int l = 1; l < ONION; l++)
            if (onion[l * NVELO + i] > 0.5f) lab = l;
        g_ptrow[i] = velo_idx[i];
        g_ptgrp[i] = SC + lab * SC + labels[closest[i]];
    } else {
        int j = i - NVELO;
        int sr = (j < 16) ? j : j + 96;
        g_ptrow[i] = surf_idx[sr];
        g_ptgrp[i] = labels[j];
    }
}

// q/k/v projection -> fp16 planes (scale folded into q)
__global__ void proj1_kernel(const float* __restrict__ Wq1,
                             const float* __restrict__ Wk1,
                             const float* __restrict__ Wv1)
{
    __shared__ float Ts[64][68];
    __shared__ float Ws[64][68];
    int h = blockIdx.y, t0 = blockIdx.x * 64;
    int tid = threadIdx.x, ty = tid >> 4, tx = tid & 15;
    #pragma unroll
    for (int e = tid; e < 4096; e += 256) {
        int t = e >> 6, d = e & 63;
        int gt = t0 + t;
        Ts[t][d] = (gt < L1) ? g_fx[g_tok1src[gt] * DIM + h * DH + d] : 0.f;
    }
    const float* Wm[3] = {Wq1, Wk1, Wv1};
    __half* Of[3] = {g_q1f, g_k1f, g_v1f};
    #pragma unroll
    for (int m = 0; m < 3; m++) {
        __syncthreads();
        #pragma unroll
        for (int e = tid; e < 4096; e += 256) Ws[e >> 6][e & 63] = Wm[m][e];
        __syncthreads();
        float acc[4][4] = {};
        #pragma unroll
        for (int x = 0; x < 64; x++) {
            float ar[4];
            #pragma unroll
            for (int i = 0; i < 4; i++) ar[i] = Ts[ty * 4 + i][x];
            float4 b4 = *(const float4*)&Ws[x][tx * 4];
            float br[4] = {b4.x, b4.y, b4.z, b4.w};
            #pragma unroll
            for (int i = 0; i < 4; i++)
                #pragma unroll
                for (int j = 0; j < 4; j++)
                    acc[i][j] += ar[i] * br[j];
        }
        float sc = (m == 0) ? ATT_SCALE : 1.f;
        #pragma unroll
        for (int i = 0; i < 4; i++) {
            int gt = t0 + ty * 4 + i;
            if (gt >= L1) continue;
            size_t base = (size_t)h * (L1 * DH) + (size_t)gt * DH + tx * 4;
            #pragma unroll
            for (int j = 0; j < 4; j++)
                Of[m][base + j] = __float2half(acc[i][j] * sc);
        }
    }
}

// ---------------------------------------------------------------------------
// flash attention: fp16 single-term MMA (logits tiny -> error negligible).
// CTA: 256 threads, 128 queries, K-tile 64; 2 CTAs/SM.
// smem: [buf0: K|V][buf1: K|V][Q]  (planes 64x144B, Q 128x144B)
// ---------------------------------------------------------------------------
#define FL_STRIDE 144
#define FL_PLANE (64 * FL_STRIDE)          // 9216
#define FL_BUF (2 * FL_PLANE)              // 18432
#define FL_QOFF (2 * FL_BUF)               // 36864
#define FL_SMEM (FL_QOFF + 128 * FL_STRIDE) // 55296
#define NKT ((L1 + 63) / 64)

__device__ __forceinline__ void fl_fill(uint32_t buf, int h, int kt, int tid)
{
    #pragma unroll
    for (int i = 0; i < 4; i++) {
        int s = tid + i * 256;           // 0..1023
        int plane = s >> 9;              // 0:K 1:V
        int e = s & 511;
        int r = e >> 3, v = e & 7;
        int kk = kt * 64 + r;
        int sz = (kk < L1) ? 16 : 0;
        int kkc = (kk < L1) ? kk : (L1 - 1);
        const __half* src = plane ? g_v1f : g_k1f;
        CPA16(buf + plane * FL_PLANE + r * FL_STRIDE + v * 16,
              src + (size_t)h * (L1 * DH) + (size_t)kkc * DH + v * 8, sz);
    }
}

__global__ void __launch_bounds__(256, 2) flashmma_kernel()
{
    extern __shared__ char sm[];
    uint32_t smb = smem_u32(sm);
    int tid = threadIdx.x, lane = tid & 31, w = tid >> 5;
    int h = blockIdx.y, q0 = blockIdx.x * 128;
    int g = lane >> 2, tq = lane & 3;

    // stage Q (fp16, 128 rows)
    {
        uint32_t qbuf = smb + FL_QOFF;
        #pragma unroll
        for (int i = 0; i < 4; i++) {
            int s = tid + i * 256;       // 0..1023
            int r = s >> 3, v = s & 7;
            int gq = q0 + r;
            int sz = (gq < L1) ? 16 : 0;
            int gqc = (gq < L1) ? gq : (L1 - 1);
            CPA16(qbuf + r * FL_STRIDE + v * 16,
                  g_q1f + (size_t)h * (L1 * DH) + (size_t)gqc * DH + v * 8, sz);
        }
        CPA_COMMIT();
    }
    fl_fill(smb, h, 0, tid);
    CPA_COMMIT();

    CPA_WAIT1();
    __syncthreads();
    uint32_t qh[4][4];
    {
        uint32_t qa = smb + FL_QOFF + (uint32_t)((w * 16 + (lane & 15)) * FL_STRIDE + (lane >> 4) * 16);
        #pragma unroll
        for (int kc = 0; kc < 4; kc++) LDSM4(qh[kc], qa + kc * 32);
    }

    float o[4][2][4] = {};
    float m0f = -1e30f, m1f = -1e30f, l0f = 0.f, l1f = 0.f;

    for (int kt = 0; kt < NKT; kt++) {
        uint32_t cur = smb + (uint32_t)(kt & 1) * FL_BUF;
        if (kt + 1 < NKT) {
            fl_fill(smb + (uint32_t)((kt + 1) & 1) * FL_BUF, h, kt + 1, tid);
            CPA_COMMIT();
            CPA_WAIT1();
        } else {
            CPA_WAIT0();
        }
        __syncthreads();

        // S = Q K^T (fp16)
        float s[4][2][4];
        #pragma unroll
        for (int nb = 0; nb < 4; nb++)
            #pragma unroll
            for (int ng = 0; ng < 2; ng++)
                #pragma unroll
                for (int e = 0; e < 4; e++) s[nb][ng][e] = 0.f;
        uint32_t kBase = cur + (uint32_t)((lane & 15) * FL_STRIDE + (lane >> 4) * 16);
        #pragma unroll
        for (int nb = 0; nb < 4; nb++) {
            #pragma unroll
            for (int kc = 0; kc < 4; kc++) {
                uint32_t bh[4];
                LDSM4(bh, kBase + (uint32_t)(nb * 16 * FL_STRIDE + kc * 32));
                MMAH16816(s[nb][0], qh[kc], bh[0], bh[2]);
                MMAH16816(s[nb][1], qh[kc], bh[1], bh[3]);
            }
        }
        int ktb = kt * 64;
        if (ktb + 64 > L1) {
            #pragma unroll
            for (int nb = 0; nb < 4; nb++)
                #pragma unroll
                for (int ng = 0; ng < 2; ng++) {
                    int kk0 = ktb + nb * 16 + ng * 8 + tq * 2;
                    if (kk0 >= L1)     { s[nb][ng][0] = -1e30f; s[nb][ng][2] = -1e30f; }
                    if (kk0 + 1 >= L1) { s[nb][ng][1] = -1e30f; s[nb][ng][3] = -1e30f; }
                }
        }
        // online softmax
        float mx0 = m0f, mx1 = m1f;
        #pragma unroll
        for (int nb = 0; nb < 4; nb++)
            #pragma unroll
            for (int ng = 0; ng < 2; ng++) {
                mx0 = fmaxf(mx0, fmaxf(s[nb][ng][0], s[nb][ng][1]));
                mx1 = fmaxf(mx1, fmaxf(s[nb][ng][2], s[nb][ng][3]));
            }
        mx0 = fmaxf(mx0, __shfl_xor_sync(0xffffffffu, mx0, 1));
        mx0 = fmaxf(mx0, __shfl_xor_sync(0xffffffffu, mx0, 2));
        mx1 = fmaxf(mx1, __shfl_xor_sync(0xffffffffu, mx1, 1));
        mx1 = fmaxf(mx1, __shfl_xor_sync(0xffffffffu, mx1, 2));
        float c0 = __expf(m0f - mx0), c1 = __expf(m1f - mx1);
        m0f = mx0; m1f = mx1;
        float rs0 = 0.f, rs1 = 0.f;
        #pragma unroll
        for (int nb = 0; nb < 4; nb++)
            #pragma unroll
            for (int ng = 0; ng < 2; ng++) {
                float p0 = __expf(s[nb][ng][0] - mx0);
                float p1 = __expf(s[nb][ng][1] - mx0);
                float p2 = __expf(s[nb][ng][2] - mx1);
                float p3 = __expf(s[nb][ng][3] - mx1);
                s[nb][ng][0] = p0; s[nb][ng][1] = p1;
                s[nb][ng][2] = p2; s[nb][ng][3] = p3;
                rs0 += p0 + p1; rs1 += p2 + p3;
            }
        rs0 += __shfl_xor_sync(0xffffffffu, rs0, 1);
        rs0 += __shfl_xor_sync(0xffffffffu, rs0, 2);
        rs1 += __shfl_xor_sync(0xffffffffu, rs1, 1);
        rs1 += __shfl_xor_sync(0xffffffffu, rs1, 2);
        l0f = l0f * c0 + rs0;
        l1f = l1f * c1 + rs1;
        #pragma unroll
        for (int nd = 0; nd < 4; nd++)
            #pragma unroll
            for (int ng = 0; ng < 2; ng++) {
                o[nd][ng][0] *= c0; o[nd][ng][1] *= c0;
                o[nd][ng][2] *= c1; o[nd][ng][3] *= c1;
            }
        // O += P V (fp16)
        uint32_t vBase = cur + FL_PLANE +
            (uint32_t)(((lane & 7) + ((lane >> 4) & 1) * 8) * FL_STRIDE + ((lane >> 3) & 1) * 16);
        #pragma unroll
        for (int nbk = 0; nbk < 4; nbk++) {
            uint32_t pa[4];
            #pragma unroll
            for (int hv = 0; hv < 2; hv++)
                #pragma unroll
                for (int pr = 0; pr < 2; pr++)
                    pa[hv * 2 + pr] = pk2h(s[nbk][hv][pr * 2], s[nbk][hv][pr * 2 + 1]);
            #pragma unroll
            for (int nd = 0; nd < 4; nd++) {
                uint32_t vb[4];
                LDSM4T(vb, vBase + (uint32_t)(nbk * 16 * FL_STRIDE + nd * 32));
                MMAH16816(o[nd][0], pa, vb[0], vb[2]);
                MMAH16816(o[nd][1], pa, vb[1], vb[3]);
            }
        }
        __syncthreads();
    }

    float i0 = 1.f / l0f, i1 = 1.f / l1f;
    int r0 = q0 + w * 16 + g, r1 = r0 + 8;
    #pragma unroll
    for (int nd = 0; nd < 4; nd++)
        #pragma unroll
        for (int ng = 0; ng < 2; ng++) {
            int col = nd * 16 + ng * 8 + tq * 2;
            if (r0 < L1) {
                float2 v = make_float2(o[nd][ng][0] * i0, o[nd][ng][1] * i0);
                *(float2*)&g_o1[(size_t)h * (L1 * DH) + (size_t)r0 * DH + col] = v;
            }
            if (r1 < L1) {
                float2 v = make_float2(o[nd][ng][2] * i1, o[nd][ng][3] * i1);
                *(float2*)&g_o1[(size_t)h * (L1 * DH) + (size_t)r1 * DH + col] = v;
            }
        }
}

#define ACC_CHUNK 1024
__global__ void pool_accum()
{
    __shared__ float sa[64][64];
    int d0 = blockIdx.y * 64, p0 = blockIdx.x * ACC_CHUNK;
    int tid = threadIdx.x, dd = tid & 63, q4 = tid >> 6;
    #pragma unroll
    for (int e = tid; e < 4096; e += 256) ((float*)sa)[e] = 0.f;
    __syncthreads();
    int pend = min(p0 + ACC_CHUNK, NPT_TOT);
    for (int p = p0 + q4; p < pend; p += 4) {
        float v = g_fx[g_ptrow[p] * DIM + d0 + dd];
        atomicAdd(&sa[g_ptgrp[p]][dd], v);
    }
    __syncthreads();
    #pragma unroll
    for (int e = tid; e < 4096; e += 256) {
        int g = e >> 6, d = e & 63;
        float v = sa[g][d];
        if (v != 0.f) atomicAdd(&g_tokacc[g * DIM + d0 + d], v);
    }
}

__global__ void ln_kernel(const float* __restrict__ gamma,
                          const float* __restrict__ beta)
{
    int d = threadIdx.x;
    const float n_s = 1.f / (float)SKEEP, n_v = 1.f / (float)NVELO;
    float s = 0.f;
    #pragma unroll
    for (int t = 0; t < NTOK; t++)
        s += g_tokacc[t * DIM + d] * ((t < SC) ? n_s : n_v);
    float mu = s * (1.f / NTOK);
    float v2 = 0.f;
    #pragma unroll
    for (int t = 0; t < NTOK; t++) {
        float dv = g_tokacc[t * DIM + d] * ((t < SC) ? n_s : n_v) - mu;
        v2 += dv * dv;
    }
    float inv = rsqrtf(v2 * (1.f / NTOK) + LN_EPS);
    #pragma unroll
    for (int t = 0; t < NTOK; t++) {
        float val = g_tokacc[t * DIM + d] * ((t < SC) ? n_s : n_v);
        g_toknorm[t * DIM + d] = (val - mu) * inv * gamma[t] + beta[t];
    }
}

__global__ void attn2_kernel(const float* __restrict__ Wq,
                             const float* __restrict__ Wk,
                             const float* __restrict__ Wv)
{
    extern __shared__ float sm2[];
    float (*tk)[68] = (float(*)[68])sm2;
    float (*qs)[68] = tk + 64;
    float (*ks)[68] = qs + 64;
    float (*vs)[68] = ks + 64;
    float (*ss)[68] = vs + 64;
    int h = blockIdx.x, tid = threadIdx.x;
    #pragma unroll
    for (int e = tid; e < 4096; e += 256) {
        int t = e >> 6, d = e & 63;
        tk[t][d] = g_toknorm[t * DIM + h * DH + d];
    }
    __syncthreads();
    #pragma unroll
    for (int e = tid; e < 4096; e += 256) {
        int t = e >> 6, d = e & 63;
        float aq = 0.f, ak = 0.f, av = 0.f;
        for (int x = 0; x < 64; x++) {
            float tv = tk[t][x];
            aq += tv * Wq[x * 64 + d];
            ak += tv * Wk[x * 64 + d];
            av += tv * Wv[x * 64 + d];
        }
        qs[t][d] = aq; ks[t][d] = ak; vs[t][d] = av;
    }
    __syncthreads();
    #pragma unroll
    for (int e = tid; e < 4096; e += 256) {
        int t = e >> 6, u = e & 63;
        float sv = 0.f;
        for (int d = 0; d < 64; d++) sv += qs[t][d] * ks[u][d];
        ss[t][u] = sv * ATT_SCALE;
    }
    __syncthreads();
    if (tid < 64) {
        float mx = -1e30f;
        for (int j = 0; j < 64; j++) mx = fmaxf(mx, ss[tid][j]);
        float sum = 0.f;
        for (int j = 0; j < 64; j++) {
            float p = __expf(ss[tid][j] - mx);
            ss[tid][j] = p; sum += p;
        }
        float inv = 1.f / sum;
        for (int j = 0; j < 64; j++) ss[tid][j] *= inv;
    }
    __syncthreads();
    #pragma unroll
    for (int e = tid; e < 4096; e += 256) {
        int t = e >> 6, d = e & 63;
        float o = 0.f;
        for (int u = 0; u < 64; u++) o += ss[t][u] * vs[u][d];
        g_outtok[h * (NTOK * DH) + t * DH + d] = o;
    }
}

__global__ void mat_out_kernel()
{
    int i = blockIdx.x * 256 + threadIdx.x;
    if (i >= NTOK * DIM) return;
    int t = i >> 9, d = i & 511;
    float v;
    if (t < SC) {
        int f = t * 512 + d;
        v = g_outtok[(f >> 8) * 4096 + (((f >> 6) & 3) << 6) + (f & 63)];
    } else {
        int r = t - SC;
        v = g_outtok[(d >> 6) * 4096 + (SC + r) * 64 + (d & 63)];
    }
    g_osc[i] = v;
}

extern "C" void kernel_launch(void* const* d_in, const int* in_sizes, int n_in,
                              void* d_out, int out_size)
{
    (void)in_sizes; (void)n_in; (void)out_size;
    const float* x     = (const float*)d_in[0];
    const float* onion = (const float*)d_in[1];
    const float* W_fx  = (const float*)d_in[2];
    const float* b_fx  = (const float*)d_in[3];
    const float* W_x   = (const float*)d_in[4];
    const float* b_x   = (const float*)d_in[5];
    const float* Wq1   = (const float*)d_in[6];
    const float* Wk1   = (const float*)d_in[7];
    const float* Wv1   = (const float*)d_in[8];
    const float* Wq    = (const float*)d_in[9];
    const float* Wk    = (const float*)d_in[10];
    const float* Wv    = (const float*)d_in[11];
    const float* gamma = (const float*)d_in[12];
    const float* beta  = (const float*)d_in[13];
    const float* W_ws  = (const float*)d_in[14];
    const float* b_ws  = (const float*)d_in[15];
    const float* W_vv  = (const float*)d_in[16];
    const float* b_vv  = (const float*)d_in[17];
    const float* W_vc  = (const float*)d_in[18];
    const float* b_vc  = (const float*)d_in[19];
    const float* W_out = (const float*)d_in[20];
    const float* b_out = (const float*)d_in[21];
    const int* surf_idx = (const int*)d_in[22];
    const int* velo_idx = (const int*)d_in[23];
    const int* closest  = (const int*)d_in[25];
    const int* labels   = (const int*)d_in[26];
    float* out = (float*)d_out;

    float *p_fx, *p_Wsc, *p_bsc, *p_osc, *p_bc;
    __nv_bfloat16 *p_xh, *p_xl, *p_xmh, *p_xml, *p_nfh, *p_nfl, *p_Wth, *p_Wtl, *p_Wcth, *p_Wctl;
    cudaGetSymbolAddress((void**)&p_fx, g_fx);
    cudaGetSymbolAddress((void**)&p_Wsc, g_Wsc);
    cudaGetSymbolAddress((void**)&p_bsc, g_bsc);
    cudaGetSymbolAddress((void**)&p_osc, g_osc);
    cudaGetSymbolAddress((void**)&p_bc, g_bc);
    cudaGetSymbolAddress((void**)&p_xh, g_xh);
    cudaGetSymbolAddress((void**)&p_xl, g_xl);
    cudaGetSymbolAddress((void**)&p_xmh, g_xmh);
    cudaGetSymbolAddress((void**)&p_xml, g_xml);
    cudaGetSymbolAddress((void**)&p_nfh, g_nfh);
    cudaGetSymbolAddress((void**)&p_nfl, g_nfl);
    cudaGetSymbolAddress((void**)&p_Wth, g_Wth);
    cudaGetSymbolAddress((void**)&p_Wtl, g_Wtl);
    cudaGetSymbolAddress((void**)&p_Wcth, g_Wcth);
    cudaGetSymbolAddress((void**)&p_Wctl, g_Wctl);

    cudaFuncSetAttribute(attn2_kernel, cudaFuncAttributeMaxDynamicSharedMemorySize, ATTN2_SMEM);
    cudaFuncSetAttribute(gemm_mma, cudaFuncAttributeMaxDynamicSharedMemorySize, GMMA_SMEM);
    cudaFuncSetAttribute(gemm_feat, cudaFuncAttributeMaxDynamicSharedMemorySize, GMMA_SMEM);
    cudaFuncSetAttribute(flashmma_kernel, cudaFuncAttributeMaxDynamicSharedMemorySize, FL_SMEM);

    const int NELEM4 = NPTS * DIM / 4;
    dim3 gTC(DIM / 128, (NPTS + 127) / 128);

    conv_split<<<(NELEM4 + 255) / 256, 256>>>(x, p_xh, p_xl, NELEM4, velo_idx, surf_idx);
    conv_wt3<<<(3 * DIM * DIM + 255) / 256, 256>>>(W_fx, W_x, W_out);

    gemm_mma<<<gTC, 256, GMMA_SMEM>>>(p_xh, p_xl, p_Wth, p_Wtl, b_fx, p_fx, nullptr, nullptr, NPTS);

    proj1_kernel<<<dim3((L1 + 63) / 64, HEADS), 256>>>(Wq1, Wk1, Wv1);
    flashmma_kernel<<<dim3((L1 + 127) / 128, HEADS), 256, FL_SMEM>>>();

    gemm_mma<<<gTC, 256, GMMA_SMEM>>>(p_xh, p_xl, p_Wth + DIM * DIM, p_Wtl + DIM * DIM, b_x,
                                      nullptr, p_xmh, p_xml, NPTS);

    prep_kernel<<<(PREP_N + 255) / 256, 256>>>(onion, labels, closest, velo_idx, surf_idx,
                                               W_ws, b_ws, W_vc, b_vc);

    pool_accum<<<dim3((NPT_TOT + ACC_CHUNK - 1) / ACC_CHUNK, DIM / 64), 256>>>();
    ln_kernel<<<1, DIM>>>(gamma, beta);
    attn2_kernel<<<HEADS, 256, ATTN2_SMEM>>>(Wq, Wk, Wv);
    mat_out_kernel<<<(NTOK * DIM + 255) / 256, 256>>>();

    int compBlocks = ((DIM + 1) * DIM + 255) / 256;
    comp_kernel<<<compBlocks, 256>>>(p_Wsc, 64, p_bsc, p_osc, 64, 0.5f,
                                     p_Wcth, p_Wctl, p_bc);
    comp_kernel<<<compBlocks, 256>>>(W_vv, VC, b_vv, p_osc + SC * DIM, VC, 1.0f,
                                     p_Wcth + DIM * DIM, p_Wctl + DIM * DIM, p_bc + DIM);

    gemm_feat<<<dim3(DIM / 128, (NSURF + 127) / 128), 256, GMMA_SMEM>>>(
        p_Wcth, p_Wctl, p_bc, surf_idx, NSURF, FLAP, 1);
    gemm_feat<<<dim3(DIM / 128, (NVELO + 127) / 128), 256, GMMA_SMEM>>>(
        p_Wcth + DIM * DIM, p_Wctl + DIM * DIM, p_bc + DIM, velo_idx, NVELO, 0, 0);

    gemm_mma<<<gTC, 256, GMMA_SMEM>>>(p_nfh, p_nfl, p_Wth + 2 * DIM * DIM, p_Wtl + 2 * DIM * DIM,
                                      b_out, out, nullptr, nullptr, NPTS);
}

// round 15
// speedup vs baseline: 3.9076x; 1.0358x over previous
#include <cuda_runtime.h>
#include <cuda_bf16.h>
#include <cuda_fp16.h>
#include <cstdint>

#define HEADS 8
#define DH 64
#define DIM 512
#define ONION 15
#define SC 4
#define NVELO 28504
#define NSURF 3682
#define NPTS 32186
#define SKEEP 3586
#define FLAP 500
#define NTOK 64
#define L1 4182
#define VC 60
#define NPT_TOT (NVELO + SKEEP)
#define PREP_N ((NTOK * DIM) > NPT_TOT ? (NTOK * DIM) : NPT_TOT)
#define ATT_SCALE 0.125f
#define LOG2E 1.4426950408889634f
#define LN_EPS 1e-5f
#define ATTN2_SMEM (5 * 64 * 68 * 4)

// ---------------- scratch ----------------
__device__ float g_fx[NPTS * DIM];
__device__ float g_o1[HEADS * L1 * DH];
__device__ __half g_q1f[HEADS * L1 * DH];
__device__ __half g_k1f[HEADS * L1 * DH];
__device__ __half g_v1f[HEADS * L1 * DH];
__device__ int   g_tok1src[L1];
__device__ int   g_ptrow[NPT_TOT];
__device__ int   g_ptgrp[NPT_TOT];
__device__ float g_tokacc[NTOK * DIM];
__device__ float g_toknorm[NTOK * DIM];
__device__ float g_outtok[HEADS * NTOK * DH];
__device__ float g_osc[NTOK * DIM];
__device__ float g_Wsc[DIM * 64];
__device__ float g_bsc[64];
__device__ __nv_bfloat16 g_xh[NPTS * DIM];
__device__ __nv_bfloat16 g_xl[NPTS * DIM];
__device__ __nv_bfloat16 g_xmh[NPTS * DIM];
__device__ __nv_bfloat16 g_xml[NPTS * DIM];
__device__ __nv_bfloat16 g_nfh[NPTS * DIM];
__device__ __nv_bfloat16 g_nfl[NPTS * DIM];
__device__ __nv_bfloat16 g_Wth[3 * DIM * DIM];
__device__ __nv_bfloat16 g_Wtl[3 * DIM * DIM];
__device__ __nv_bfloat16 g_Wcth[2 * DIM * DIM];
__device__ __nv_bfloat16 g_Wctl[2 * DIM * DIM];
__device__ float g_bc[2 * DIM];
__device__ float g_bcat[2 * DIM];   // [b_fx | b_x]

// ---------------- helpers --------
__device__ __forceinline__ uint32_t smem_u32(const void* p) {
    uint32_t a;
    asm("{ .reg .u64 t; cvta.to.shared.u64 t, %1; cvt.u32.u64 %0, t; }" : "=r"(a) : "l"(p));
    return a;
}
#define CPA16(dst, src, sz) \
    asm volatile("cp.async.cg.shared.global [%0], [%1], 16, %2;" \
                 :: "r"(dst), "l"(src), "r"(sz) : "memory")
#define CPA_COMMIT() asm volatile("cp.async.commit_group;" ::: "memory")
#define CPA_WAIT0()  asm volatile("cp.async.wait_group 0;" ::: "memory")
#define CPA_WAIT1()  asm volatile("cp.async.wait_group 1;" ::: "memory")
#define LDSM4(r, addr) \
    asm volatile("ldmatrix.sync.aligned.m8n8.x4.shared.b16 {%0,%1,%2,%3}, [%4];" \
                 : "=r"((r)[0]), "=r"((r)[1]), "=r"((r)[2]), "=r"((r)[3]) : "r"(addr))
#define LDSM4T(r, addr) \
    asm volatile("ldmatrix.sync.aligned.m8n8.x4.trans.shared.b16 {%0,%1,%2,%3}, [%4];" \
                 : "=r"((r)[0]), "=r"((r)[1]), "=r"((r)[2]), "=r"((r)[3]) : "r"(addr))
#define MMA16816(c, a, b0v, b1v) \
    asm volatile("mma.sync.aligned.m16n8k16.row.col.f32.bf16.bf16.f32 " \
                 "{%0,%1,%2,%3},{%4,%5,%6,%7},{%8,%9},{%0,%1,%2,%3};" \
                 : "+f"((c)[0]), "+f"((c)[1]), "+f"((c)[2]), "+f"((c)[3]) \
                 : "r"((a)[0]), "r"((a)[1]), "r"((a)[2]), "r"((a)[3]), "r"(b0v), "r"(b1v))
#define MMAH16816(c, a, b0v, b1v) \
    asm volatile("mma.sync.aligned.m16n8k16.row.col.f32.f16.f16.f32 " \
                 "{%0,%1,%2,%3},{%4,%5,%6,%7},{%8,%9},{%0,%1,%2,%3};" \
                 : "+f"((c)[0]), "+f"((c)[1]), "+f"((c)[2]), "+f"((c)[3]) \
                 : "r"((a)[0]), "r"((a)[1]), "r"((a)[2]), "r"((a)[3]), "r"(b0v), "r"(b1v))
__device__ __forceinline__ uint32_t pk2(float lo, float hi) {
    uint32_t r;
    asm("cvt.rn.bf16x2.f32 %0, %1, %2;" : "=r"(r) : "f"(hi), "f"(lo));
    return r;
}
__device__ __forceinline__ uint32_t pk2h(float lo, float hi) {
    uint32_t r;
    asm("cvt.rn.f16x2.f32 %0, %1, %2;" : "=r"(r) : "f"(hi), "f"(lo));
    return r;
}
__device__ __forceinline__ uint32_t splitpair(float v0, float v1, uint32_t& lopack) {
    uint32_t hp = pk2(v0, v1);
    __nv_bfloat162 hb = *(__nv_bfloat162*)&hp;
    lopack = pk2(v0 - __bfloat162float(hb.x), v1 - __bfloat162float(hb.y));
    return hp;
}

// ---------------------------------------------------------------------------
// split-bf16 HMMA GEMM machinery
// ---------------------------------------------------------------------------
#define PLANE_B 10240
#define BUF_B   (4 * PLANE_B)
#define GMMA_SMEM (2 * BUF_B)

__device__ __forceinline__ void fill_chunk(
    uint32_t sb, const __nv_bfloat16* __restrict__ Ah, const __nv_bfloat16* __restrict__ Al,
    const __nv_bfloat16* __restrict__ Bh, const __nv_bfloat16* __restrict__ Bl,
    const int* __restrict__ rowidx,
    int m0, int n0, int k0, int M, int tid)
{
    #pragma unroll
    for (int hf = 0; hf < 2; hf++) {
        int s = tid + hf * 256;
        int r = s >> 2, v = s & 3;
        uint32_t off = (uint32_t)(r * 80 + v * 16);
        int gm = m0 + r;
        int szA = (gm < M) ? 16 : 0;
        int gmc = (gm < M) ? gm : (M - 1);
        int arow = rowidx ? rowidx[gmc] : gmc;
        CPA16(sb + off,               Ah + (size_t)arow * DIM + k0 + v * 8, szA);
        CPA16(sb + PLANE_B + off,     Al + (size_t)arow * DIM + k0 + v * 8, szA);
        CPA16(sb + 2 * PLANE_B + off, Bh + (size_t)(n0 + r) * DIM + k0 + v * 8, 16);
        CPA16(sb + 3 * PLANE_B + off, Bl + (size_t)(n0 + r) * DIM + k0 + v * 8, 16);
    }
}

__device__ __forceinline__ void mma_mainloop(
    uint32_t smb, const __nv_bfloat16* Ah, const __nv_bfloat16* Al,
    const __nv_bfloat16* Bth, const __nv_bfloat16* Btl,
    const int* rowidx, int m0, int n0, int M, int tid, int lane, int wy, int wx,
    float acc[2][8][4])
{
    uint32_t aBase = (uint32_t)((wy * 32 + (lane & 15)) * 80 + (lane >> 4) * 16);
    uint32_t bBase = (uint32_t)((wx * 64 + (lane & 15)) * 80 + (lane >> 4) * 16);
    fill_chunk(smb, Ah, Al, Bth, Btl, rowidx, m0, n0, 0, M, tid);
    CPA_COMMIT();
    for (int ch = 0; ch < 16; ch++) {
        uint32_t sb = smb + (uint32_t)(ch & 1) * BUF_B;
        CPA_WAIT0();
        __syncthreads();
        if (ch < 15) {
            fill_chunk(smb + (uint32_t)((ch + 1) & 1) * BUF_B,
                       Ah, Al, Bth, Btl, rowidx, m0, n0, (ch + 1) * 32, M, tid);
            CPA_COMMIT();
        }
        uint32_t AH = sb, AL = sb + PLANE_B, BH = sb + 2 * PLANE_B, BL = sb + 3 * PLANE_B;
        #pragma unroll
        for (int ks = 0; ks < 2; ks++) {
            uint32_t ko = (uint32_t)(ks * 32);
            uint32_t ah[2][4], al[2][4];
            LDSM4(ah[0], AH + aBase + ko);
            LDSM4(ah[1], AH + aBase + 1280 + ko);
            LDSM4(al[0], AL + aBase + ko);
            LDSM4(al[1], AL + aBase + 1280 + ko);
            #pragma unroll
            for (int np = 0; np < 4; np++) {
                uint32_t bh[4], bl[4];
                uint32_t boff = bBase + (uint32_t)(np * 16 * 80) + ko;
                LDSM4(bh, BH + boff);
                LDSM4(bl, BL + boff);
                #pragma unroll
                for (int mt = 0; mt < 2; mt++) {
                    float* c0 = acc[mt][np * 2];
                    float* c1 = acc[mt][np * 2 + 1];
                    MMA16816(c0, ah[mt], bh[0], bh[2]);
                    MMA16816(c0, ah[mt], bl[0], bl[2]);
                    MMA16816(c0, al[mt], bh[0], bh[2]);
                    MMA16816(c1, ah[mt], bh[1], bh[3]);
                    MMA16816(c1, ah[mt], bl[1], bl[3]);
                    MMA16816(c1, al[mt], bh[1], bh[3]);
                }
            }
        }
        __syncthreads();
    }
}

// generic GEMM: C = A@B + bias (fp32 or split-bf16 out)
__global__ void __launch_bounds__(256, 2) gemm_mma(
    const __nv_bfloat16* __restrict__ Ah, const __nv_bfloat16* __restrict__ Al,
    const __nv_bfloat16* __restrict__ Bth, const __nv_bfloat16* __restrict__ Btl,
    const float* __restrict__ bias, float* __restrict__ Cf,
    __nv_bfloat16* __restrict__ Ch, __nv_bfloat16* __restrict__ Cl, int M)
{
    extern __shared__ char smbuf[];
    uint32_t smb = smem_u32(smbuf);
    int tid = threadIdx.x, lane = tid & 31, wid = tid >> 5;
    int wy = wid & 3, wx = wid >> 2;
    int m0 = blockIdx.y * 128, n0 = blockIdx.x * 128;
    float acc[2][8][4] = {};
    mma_mainloop(smb, Ah, Al, Bth, Btl, nullptr, m0, n0, M, tid, lane, wy, wx, acc);

    int g = lane >> 2, tig = lane & 3;
    #pragma unroll
    for (int mt = 0; mt < 2; mt++) {
        int r0 = m0 + wy * 32 + mt * 16 + g;
        #pragma unroll
        for (int nt = 0; nt < 8; nt++) {
            int col = n0 + wx * 64 + nt * 8 + tig * 2;
            float2 b2 = *(const float2*)&bias[col];
            float v00 = acc[mt][nt][0] + b2.x, v01 = acc[mt][nt][1] + b2.y;
            float v10 = acc[mt][nt][2] + b2.x, v11 = acc[mt][nt][3] + b2.y;
            if (Cf) {
                if (r0 < M)     *(float2*)&Cf[(size_t)r0 * DIM + col] = make_float2(v00, v01);
                if (r0 + 8 < M) *(float2*)&Cf[(size_t)(r0 + 8) * DIM + col] = make_float2(v10, v11);
            } else {
                uint32_t lo;
                if (r0 < M) {
                    uint32_t hi = splitpair(v00, v01, lo);
                    *(uint32_t*)&Ch[(size_t)r0 * DIM + col] = hi;
                    *(uint32_t*)&Cl[(size_t)r0 * DIM + col] = lo;
                }
                if (r0 + 8 < M) {
                    uint32_t hi = splitpair(v10, v11, lo);
                    *(uint32_t*)&Ch[(size_t)(r0 + 8) * DIM + col] = hi;
                    *(uint32_t*)&Cl[(size_t)(r0 + 8) * DIM + col] = lo;
                }
            }
        }
    }
}

// merged fx|xm GEMM: B has 1024 rows [W_fx^T ; W_x^T]; cols<512 -> g_fx fp32,
// cols>=512 -> g_xmh/g_xml split planes.
__global__ void __launch_bounds__(256, 2) gemm_fxxm()
{
    extern __shared__ char smbuf[];
    uint32_t smb = smem_u32(smbuf);
    int tid = threadIdx.x, lane = tid & 31, wid = tid >> 5;
    int wy = wid & 3, wx = wid >> 2;
    int m0 = blockIdx.y * 128, n0 = blockIdx.x * 128;
    float acc[2][8][4] = {};
    mma_mainloop(smb, g_xh, g_xl, g_Wth, g_Wtl, nullptr, m0, n0, NPTS, tid, lane, wy, wx, acc);

    int g = lane >> 2, tig = lane & 3;
    #pragma unroll
    for (int mt = 0; mt < 2; mt++) {
        int r0 = m0 + wy * 32 + mt * 16 + g;
        #pragma unroll
        for (int nt = 0; nt < 8; nt++) {
            int col = n0 + wx * 64 + nt * 8 + tig * 2;   // 0..1023
            float2 b2 = *(const float2*)&g_bcat[col];
            float v00 = acc[mt][nt][0] + b2.x, v01 = acc[mt][nt][1] + b2.y;
            float v10 = acc[mt][nt][2] + b2.x, v11 = acc[mt][nt][3] + b2.y;
            if (col < DIM) {
                if (r0 < NPTS)     *(float2*)&g_fx[(size_t)r0 * DIM + col] = make_float2(v00, v01);
                if (r0 + 8 < NPTS) *(float2*)&g_fx[(size_t)(r0 + 8) * DIM + col] = make_float2(v10, v11);
            } else {
                int c2 = col - DIM;
                uint32_t lo;
                if (r0 < NPTS) {
                    uint32_t hi = splitpair(v00, v01, lo);
                    *(uint32_t*)&g_xmh[(size_t)r0 * DIM + c2] = hi;
                    *(uint32_t*)&g_xml[(size_t)r0 * DIM + c2] = lo;
                }
                if (r0 + 8 < NPTS) {
                    uint32_t hi = splitpair(v10, v11, lo);
                    *(uint32_t*)&g_xmh[(size_t)(r0 + 8) * DIM + c2] = hi;
                    *(uint32_t*)&g_xml[(size_t)(r0 + 8) * DIM + c2] = lo;
                }
            }
        }
    }
}

__global__ void __launch_bounds__(256, 2) gemm_feat(
    const __nv_bfloat16* __restrict__ Bth, const __nv_bfloat16* __restrict__ Btl,
    const float* __restrict__ bcomp, const int* __restrict__ rowidx,
    int M, int o1_off, int o1_always)
{
    extern __shared__ char smbuf[];
    uint32_t smb = smem_u32(smbuf);
    int tid = threadIdx.x, lane = tid & 31, wid = tid >> 5;
    int wy = wid & 3, wx = wid >> 2;
    int m0 = blockIdx.y * 128, n0 = blockIdx.x * 128;
    float acc[2][8][4] = {};
    mma_mainloop(smb, g_xmh, g_xml, Bth, Btl, rowidx, m0, n0, M, tid, lane, wy, wx, acc);

    int g = lane >> 2, tig = lane & 3;
    #pragma unroll
    for (int mt = 0; mt < 2; mt++) {
        int gi0 = m0 + wy * 32 + mt * 16 + g;
        int gi1 = gi0 + 8;
        int or0 = (gi0 < M) ? rowidx[gi0] : 0;
        int or1 = (gi1 < M) ? rowidx[gi1] : 0;
        bool a0 = o1_always || (gi0 < FLAP);
        bool a1 = o1_always || (gi1 < FLAP);
        #pragma unroll
        for (int nt = 0; nt < 8; nt++) {
            int col = n0 + wx * 64 + nt * 8 + tig * 2;
            int h = col >> 6, dd = col & 63;
            float2 b2 = *(const float2*)&bcomp[col];
            uint32_t lo;
            if (gi0 < M) {
                float v0 = acc[mt][nt][0] + b2.x, v1 = acc[mt][nt][1] + b2.y;
                if (a0) {
                    const float* o1p = &g_o1[((size_t)h * L1 + (o1_off + gi0)) * DH + dd];
                    v0 += o1p[0]; v1 += o1p[1];
                }
                uint32_t hi = splitpair(v0, v1, lo);
                *(uint32_t*)&g_nfh[(size_t)or0 * DIM + col] = hi;
                *(uint32_t*)&g_nfl[(size_t)or0 * DIM + col] = lo;
            }
            if (gi1 < M) {
                float v0 = acc[mt][nt][2] + b2.x, v1 = acc[mt][nt][3] + b2.y;
                if (a1) {
                    const float* o1p = &g_o1[((size_t)h * L1 + (o1_off + gi1)) * DH + dd];
                    v0 += o1p[0]; v1 += o1p[1];
                }
                uint32_t hi = splitpair(v0, v1, lo);
                *(uint32_t*)&g_nfh[(size_t)or1 * DIM + col] = hi;
                *(uint32_t*)&g_nfl[(size_t)or1 * DIM + col] = lo;
            }
        }
    }
}

__global__ void conv_split(const float* __restrict__ s,
                           __nv_bfloat16* __restrict__ h,
                           __nv_bfloat16* __restrict__ l, int n4,
                           const int* __restrict__ velo_idx,
                           const int* __restrict__ surf_idx)
{
    int i = blockIdx.x * 256 + threadIdx.x;
    if (velo_idx && i < L1)
        g_tok1src[i] = (i < FLAP) ? velo_idx[i] : surf_idx[i - FLAP];
    if (i >= n4) return;
    float4 v = *(const float4*)&s[i * 4];
    float a[4] = {v.x, v.y, v.z, v.w};
    #pragma unroll
    for (int j = 0; j < 4; j++) {
        __nv_bfloat16 hh = __float2bfloat16(a[j]);
        h[i * 4 + j] = hh;
        l[i * 4 + j] = __float2bfloat16(a[j] - __bfloat162float(hh));
    }
}

__global__ void conv_wt3(const float* __restrict__ W0, const float* __restrict__ W1,
                         const float* __restrict__ W2,
                         const float* __restrict__ b0, const float* __restrict__ b1)
{
    int i = blockIdx.x * 256 + threadIdx.x;
    if (i < DIM) { g_bcat[i] = b0[i]; g_bcat[DIM + i] = b1[i]; }
    if (i >= 3 * DIM * DIM) return;
    int w = i / (DIM * DIM), r = i % (DIM * DIM);
    const float* W = (w == 0) ? W0 : ((w == 1) ? W1 : W2);
    int k = r >> 9, n = r & 511;
    float v = W[r];
    __nv_bfloat16 hh = __float2bfloat16(v);
    g_Wth[w * DIM * DIM + n * DIM + k] = hh;
    g_Wtl[w * DIM * DIM + n * DIM + k] = __float2bfloat16(v - __bfloat162float(hh));
}

__global__ void comp_kernel(const float* __restrict__ A, int ldA,
                            const float* __restrict__ bias,
                            const float* __restrict__ O, int C, float scale,
                            __nv_bfloat16* __restrict__ Bth,
                            __nv_bfloat16* __restrict__ Btl,
                            float* __restrict__ bc)
{
    int id = blockIdx.x * 256 + threadIdx.x;
    if (id >= (DIM + 1) * DIM) return;
    int k = id >> 9, n = id & 511;
    float acc = 0.f;
    if (k < DIM) {
        for (int c = 0; c < C; c++) acc += A[k * ldA + c] * O[c * DIM + n];
        acc *= scale;
        __nv_bfloat16 hh = __float2bfloat16(acc);
        Bth[n * DIM + k] = hh;
        Btl[n * DIM + k] = __float2bfloat16(acc - __bfloat162float(hh));
    } else {
        for (int c = 0; c < C; c++) acc += bias[c] * O[c * DIM + n];
        bc[n] = acc * scale;
    }
}

__global__ void prep_kernel(const float* __restrict__ onion,
                            const int* __restrict__ labels,
                            const int* __restrict__ closest,
                            const int* __restrict__ velo_idx,
                            const int* __restrict__ surf_idx,
                            const float* __restrict__ W_ws,
                            const float* __restrict__ b_ws,
                            const float* __restrict__ W_vc,
                            const float* __restrict__ b_vc)
{
    int i = blockIdx.x * 256 + threadIdx.x;
    if (i < NTOK * DIM) g_tokacc[i] = 0.f;
    if (i < DIM * 64) {
        int k = i >> 6, n = i & 63;
        g_Wsc[i] = (n < SC) ? W_ws[k * SC + n] : W_vc[k * VC + n - SC];
    }
    if (i < 64) g_bsc[i] = (i < SC) ? b_ws[i] : b_vc[i - SC];
    if (i >= NPT_TOT) return;
    if (i < NVELO) {
        int lab = 0;
        #pragma unroll
        for (int l = 1; l < ONION; l++)
            if (onion[l * NVELO + i] > 0.5f) lab = l;
        g_ptrow[i] = velo_idx[i];
        g_ptgrp[i] = SC + lab * SC + labels[closest[i]];
    } else {
        int j = i - NVELO;
        int sr = (j < 16) ? j : j + 96;
        g_ptrow[i] = surf_idx[sr];
        g_ptgrp[i] = labels[j];
    }
}

// q/k/v projection -> fp16 planes (ATT_SCALE*log2e folded into q)
__global__ void proj1_kernel(const float* __restrict__ Wq1,
                             const float* __restrict__ Wk1,
                             const float* __restrict__ Wv1)
{
    __shared__ float Ts[64][68];
    __shared__ float Ws[64][68];
    int h = blockIdx.y, t0 = blockIdx.x * 64;
    int tid = threadIdx.x, ty = tid >> 4, tx = tid & 15;
    #pragma unroll
    for (int e = tid; e < 4096; e += 256) {
        int t = e >> 6, d = e & 63;
        int gt = t0 + t;
        Ts[t][d] = (gt < L1) ? g_fx[g_tok1src[gt] * DIM + h * DH + d] : 0.f;
    }
    const float* Wm[3] = {Wq1, Wk1, Wv1};
    __half* Of[3] = {g_q1f, g_k1f, g_v1f};
    #pragma unroll
    for (int m = 0; m < 3; m++) {
        __syncthreads();
        #pragma unroll
        for (int e = tid; e < 4096; e += 256) Ws[e >> 6][e & 63] = Wm[m][e];
        __syncthreads();
        float acc[4][4] = {};
        #pragma unroll
        for (int x = 0; x < 64; x++) {
            float ar[4];
            #pragma unroll
            for (int i = 0; i < 4; i++) ar[i] = Ts[ty * 4 + i][x];
            float4 b4 = *(const float4*)&Ws[x][tx * 4];
            float br[4] = {b4.x, b4.y, b4.z, b4.w};
            #pragma unroll
            for (int i = 0; i < 4; i++)
                #pragma unroll
                for (int j = 0; j < 4; j++)
                    acc[i][j] += ar[i] * br[j];
        }
        float sc = (m == 0) ? (ATT_SCALE * LOG2E) : 1.f;
        #pragma unroll
        for (int i = 0; i < 4; i++) {
            int gt = t0 + ty * 4 + i;
            if (gt >= L1) continue;
            size_t base = (size_t)h * (L1 * DH) + (size_t)gt * DH + tx * 4;
            #pragma unroll
            for (int j = 0; j < 4; j++)
                Of[m][base + j] = __float2half(acc[i][j] * sc);
        }
    }
}

// ---------------------------------------------------------------------------
// flash attention, fp16 MMA, NO max-tracking (logits bounded ~|0.03|·log2e),
// exp2 softmax; l accumulated per-thread, reduced once at the end.
// ---------------------------------------------------------------------------
#define FL_STRIDE 144
#define FL_PLANE (64 * FL_STRIDE)
#define FL_BUF (2 * FL_PLANE)
#define FL_QOFF (2 * FL_BUF)
#define FL_SMEM (FL_QOFF + 128 * FL_STRIDE)
#define NKT ((L1 + 63) / 64)

__device__ __forceinline__ void fl_fill(uint32_t buf, int h, int kt, int tid)
{
    #pragma unroll
    for (int i = 0; i < 4; i++) {
        int s = tid + i * 256;
        int plane = s >> 9;
        int e = s & 511;
        int r = e >> 3, v = e & 7;
        int kk = kt * 64 + r;
        int sz = (kk < L1) ? 16 : 0;
        int kkc = (kk < L1) ? kk : (L1 - 1);
        const __half* src = plane ? g_v1f : g_k1f;
        CPA16(buf + plane * FL_PLANE + r * FL_STRIDE + v * 16,
              src + (size_t)h * (L1 * DH) + (size_t)kkc * DH + v * 8, sz);
    }
}

__global__ void __launch_bounds__(256, 2) flashmma_kernel()
{
    extern __shared__ char sm[];
    uint32_t smb = smem_u32(sm);
    int tid = threadIdx.x, lane = tid & 31, w = tid >> 5;
    int h = blockIdx.y, q0 = blockIdx.x * 128;
    int g = lane >> 2, tq = lane & 3;

    {
        uint32_t qbuf = smb + FL_QOFF;
        #pragma unroll
        for (int i = 0; i < 4; i++) {
            int s = tid + i * 256;
            int r = s >> 3, v = s & 7;
            int gq = q0 + r;
            int sz = (gq < L1) ? 16 : 0;
            int gqc = (gq < L1) ? gq : (L1 - 1);
            CPA16(qbuf + r * FL_STRIDE + v * 16,
                  g_q1f + (size_t)h * (L1 * DH) + (size_t)gqc * DH + v * 8, sz);
        }
        CPA_COMMIT();
    }
    fl_fill(smb, h, 0, tid);
    CPA_COMMIT();

    CPA_WAIT1();
    __syncthreads();
    uint32_t qh[4][4];
    {
        uint32_t qa = smb + FL_QOFF + (uint32_t)((w * 16 + (lane & 15)) * FL_STRIDE + (lane >> 4) * 16);
        #pragma unroll
        for (int kc = 0; kc < 4; kc++) LDSM4(qh[kc], qa + kc * 32);
    }

    float o[4][2][4] = {};
    float l0f = 0.f, l1f = 0.f;

    for (int kt = 0; kt < NKT; kt++) {
        uint32_t cur = smb + (uint32_t)(kt & 1) * FL_BUF;
        if (kt + 1 < NKT) {
            fl_fill(smb + (uint32_t)((kt + 1) & 1) * FL_BUF, h, kt + 1, tid);
            CPA_COMMIT();
            CPA_WAIT1();
        } else {
            CPA_WAIT0();
        }
        __syncthreads();

        // S = Q K^T (fp16), already in log2 domain
        float s[4][2][4];
        #pragma unroll
        for (int nb = 0; nb < 4; nb++)
            #pragma unroll
            for (int ng = 0; ng < 2; ng++)
                #pragma unroll
                for (int e = 0; e < 4; e++) s[nb][ng][e] = 0.f;
        uint32_t kBase = cur + (uint32_t)((lane & 15) * FL_STRIDE + (lane >> 4) * 16);
        #pragma unroll
        for (int nb = 0; nb < 4; nb++) {
            #pragma unroll
            for (int kc = 0; kc < 4; kc++) {
                uint32_t bh[4];
                LDSM4(bh, kBase + (uint32_t)(nb * 16 * FL_STRIDE + kc * 32));
                MMAH16816(s[nb][0], qh[kc], bh[0], bh[2]);
                MMAH16816(s[nb][1], qh[kc], bh[1], bh[3]);
            }
        }
        int ktb = kt * 64;
        if (ktb + 64 > L1) {
            #pragma unroll
            for (int nb = 0; nb < 4; nb++)
                #pragma unroll
                for (int ng = 0; ng < 2; ng++) {
                    int kk0 = ktb + nb * 16 + ng * 8 + tq * 2;
                    if (kk0 >= L1)     { s[nb][ng][0] = -1e30f; s[nb][ng][2] = -1e30f; }
                    if (kk0 + 1 >= L1) { s[nb][ng][1] = -1e30f; s[nb][ng][3] = -1e30f; }
                }
        }
        // p = exp2(s): logits tiny, no max needed; accumulate l per thread
        #pragma unroll
        for (int nb = 0; nb < 4; nb++)
            #pragma unroll
            for (int ng = 0; ng < 2; ng++) {
                float p0 = exp2f(s[nb][ng][0]);
                float p1 = exp2f(s[nb][ng][1]);
                float p2 = exp2f(s[nb][ng][2]);
                float p3 = exp2f(s[nb][ng][3]);
                s[nb][ng][0] = p0; s[nb][ng][1] = p1;
                s[nb][ng][2] = p2; s[nb][ng][3] = p3;
                l0f += p0 + p1; l1f += p2 + p3;
            }
        // O += P V (fp16)
        uint32_t vBase = cur + FL_PLANE +
            (uint32_t)(((lane & 7) + ((lane >> 4) & 1) * 8) * FL_STRIDE + ((lane >> 3) & 1) * 16);
        #pragma unroll
        for (int nbk = 0; nbk < 4; nbk++) {
            uint32_t pa[4];
            #pragma unroll
            for (int hv = 0; hv < 2; hv++)
                #pragma unroll
                for (int pr = 0; pr < 2; pr++)
                    pa[hv * 2 + pr] = pk2h(s[nbk][hv][pr * 2], s[nbk][hv][pr * 2 + 1]);
            #pragma unroll
            for (int nd = 0; nd < 4; nd++) {
                uint32_t vb[4];
                LDSM4T(vb, vBase + (uint32_t)(nbk * 16 * FL_STRIDE + nd * 32));
                MMAH16816(o[nd][0], pa, vb[0], vb[2]);
                MMAH16816(o[nd][1], pa, vb[1], vb[3]);
            }
        }
        __syncthreads();
    }

    // reduce l across the lane quad once
    l0f += __shfl_xor_sync(0xffffffffu, l0f, 1);
    l0f += __shfl_xor_sync(0xffffffffu, l0f, 2);
    l1f += __shfl_xor_sync(0xffffffffu, l1f, 1);
    l1f += __shfl_xor_sync(0xffffffffu, l1f, 2);

    float i0 = 1.f / l0f, i1 = 1.f / l1f;
    int r0 = q0 + w * 16 + g, r1 = r0 + 8;
    #pragma unroll
    for (int nd = 0; nd < 4; nd++)
        #pragma unroll
        for (int ng = 0; ng < 2; ng++) {
            int col = nd * 16 + ng * 8 + tq * 2;
            if (r0 < L1) {
                float2 v = make_float2(o[nd][ng][0] * i0, o[nd][ng][1] * i0);
                *(float2*)&g_o1[(size_t)h * (L1 * DH) + (size_t)r0 * DH + col] = v;
            }
            if (r1 < L1) {
                float2 v = make_float2(o[nd][ng][2] * i1, o[nd][ng][3] * i1);
                *(float2*)&g_o1[(size_t)h * (L1 * DH) + (size_t)r1 * DH + col] = v;
            }
        }
}

#define ACC_CHUNK 1024
__global__ void pool_accum()
{
    __shared__ float sa[64][64];
    int d0 = blockIdx.y * 64, p0 = blockIdx.x * ACC_CHUNK;
    int tid = threadIdx.x, dd = tid & 63, q4 = tid >> 6;
    #pragma unroll
    for (int e = tid; e < 4096; e += 256) ((float*)sa)[e] = 0.f;
    __syncthreads();
    int pend = min(p0 + ACC_CHUNK, NPT_TOT);
    for (int p = p0 + q4; p < pend; p += 4) {
        float v = g_fx[g_ptrow[p] * DIM + d0 + dd];
        atomicAdd(&sa[g_ptgrp[p]][dd], v);
    }
    __syncthreads();
    #pragma unroll
    for (int e = tid; e < 4096; e += 256) {
        int g = e >> 6, d = e & 63;
        float v = sa[g][d];
        if (v != 0.f) atomicAdd(&g_tokacc[g * DIM + d0 + d], v);
    }
}

// parallel over 8 blocks of 64 channels
__global__ void ln_kernel(const float* __restrict__ gamma,
                          const float* __restrict__ beta)
{
    int d = blockIdx.x * 64 + threadIdx.x;
    const float n_s = 1.f / (float)SKEEP, n_v = 1.f / (float)NVELO;
    float s = 0.f;
    #pragma unroll
    for (int t = 0; t < NTOK; t++)
        s += g_tokacc[t * DIM + d] * ((t < SC) ? n_s : n_v);
    float mu = s * (1.f / NTOK);
    float v2 = 0.f;
    #pragma unroll
    for (int t = 0; t < NTOK; t++) {
        float dv = g_tokacc[t * DIM + d] * ((t < SC) ? n_s : n_v) - mu;
        v2 += dv * dv;
    }
    float inv = rsqrtf(v2 * (1.f / NTOK) + LN_EPS);
    #pragma unroll
    for (int t = 0; t < NTOK; t++) {
        float val = g_tokacc[t * DIM + d] * ((t < SC) ? n_s : n_v);
        g_toknorm[t * DIM + d] = (val - mu) * inv * gamma[t] + beta[t];
    }
}

__global__ void attn2_kernel(const float* __restrict__ Wq,
                             const float* __restrict__ Wk,
                             const float* __restrict__ Wv)
{
    extern __shared__ float sm2[];
    float (*tk)[68] = (float(*)[68])sm2;
    float (*qs)[68] = tk + 64;
    float (*ks)[68] = qs + 64;
    float (*vs)[68] = ks + 64;
    float (*ss)[68] = vs + 64;
    int h = blockIdx.x, tid = threadIdx.x;
    #pragma unroll
    for (int e = tid; e < 4096; e += 256) {
        int t = e >> 6, d = e & 63;
        tk[t][d] = g_toknorm[t * DIM + h * DH + d];
    }
    __syncthreads();
    #pragma unroll
    for (int e = tid; e < 4096; e += 256) {
        int t = e >> 6, d = e & 63;
        float aq = 0.f, ak = 0.f, av = 0.f;
        for (int x = 0; x < 64; x++) {
            float tv = tk[t][x];
            aq += tv * Wq[x * 64 + d];
            ak += tv * Wk[x * 64 + d];
            av += tv * Wv[x * 64 + d];
        }
        qs[t][d] = aq; ks[t][d] = ak; vs[t][d] = av;
    }
    __syncthreads();
    #pragma unroll
    for (int e = tid; e < 4096; e += 256) {
        int t = e >> 6, u = e & 63;
        float sv = 0.f;
        for (int d = 0; d < 64; d++) sv += qs[t][d] * ks[u][d];
        ss[t][u] = sv * ATT_SCALE;
    }
    __syncthreads();
    if (tid < 64) {
        float mx = -1e30f;
        for (int j = 0; j < 64; j++) mx = fmaxf(mx, ss[tid][j]);
        float sum = 0.f;
        for (int j = 0; j < 64; j++) {
            float p = __expf(ss[tid][j] - mx);
            ss[tid][j] = p; sum += p;
        }
        float inv = 1.f / sum;
        for (int j = 0; j < 64; j++) ss[tid][j] *= inv;
    }
    __syncthreads();
    #pragma unroll
    for (int e = tid; e < 4096; e += 256) {
        int t = e >> 6, d = e & 63;
        float o = 0.f;
        for (int u = 0; u < 64; u++) o += ss[t][u] * vs[u][d];
        g_outtok[h * (NTOK * DH) + t * DH + d] = o;
    }
}

__global__ void mat_out_kernel()
{
    int i = blockIdx.x * 256 + threadIdx.x;
    if (i >= NTOK * DIM) return;
    int t = i >> 9, d = i & 511;
    float v;
    if (t < SC) {
        int f = t * 512 + d;
        v = g_outtok[(f >> 8) * 4096 + (((f >> 6) & 3) << 6) + (f & 63)];
    } else {
        int r = t - SC;
        v = g_outtok[(d >> 6) * 4096 + (SC + r) * 64 + (d & 63)];
    }
    g_osc[i] = v;
}

extern "C" void kernel_launch(void* const* d_in, const int* in_sizes, int n_in,
                              void* d_out, int out_size)
{
    (void)in_sizes; (void)n_in; (void)out_size;
    const float* x     = (const float*)d_in[0];
    const float* onion = (const float*)d_in[1];
    const float* W_fx  = (const float*)d_in[2];
    const float* b_fx  = (const float*)d_in[3];
    const float* W_x   = (const float*)d_in[4];
    const float* b_x   = (const float*)d_in[5];
    const float* Wq1   = (const float*)d_in[6];
    const float* Wk1   = (const float*)d_in[7];
    const float* Wv1   = (const float*)d_in[8];
    const float* Wq    = (const float*)d_in[9];
    const float* Wk    = (const float*)d_in[10];
    const float* Wv    = (const float*)d_in[11];
    const float* gamma = (const float*)d_in[12];
    const float* beta  = (const float*)d_in[13];
    const float* W_ws  = (const float*)d_in[14];
    const float* b_ws  = (const float*)d_in[15];
    const float* W_vv  = (const float*)d_in[16];
    const float* b_vv  = (const float*)d_in[17];
    const float* W_vc  = (const float*)d_in[18];
    const float* b_vc  = (const float*)d_in[19];
    const float* W_out = (const float*)d_in[20];
    const float* b_out = (const float*)d_in[21];
    const int* surf_idx = (const int*)d_in[22];
    const int* velo_idx = (const int*)d_in[23];
    const int* closest  = (const int*)d_in[25];
    const int* labels   = (const int*)d_in[26];
    float* out = (float*)d_out;

    float *p_Wsc, *p_bsc, *p_osc, *p_bc;
    __nv_bfloat16 *p_xh, *p_xl, *p_nfh, *p_nfl, *p_Wth, *p_Wtl, *p_Wcth, *p_Wctl;
    cudaGetSymbolAddress((void**)&p_Wsc, g_Wsc);
    cudaGetSymbolAddress((void**)&p_bsc, g_bsc);
    cudaGetSymbolAddress((void**)&p_osc, g_osc);
    cudaGetSymbolAddress((void**)&p_bc, g_bc);
    cudaGetSymbolAddress((void**)&p_xh, g_xh);
    cudaGetSymbolAddress((void**)&p_xl, g_xl);
    cudaGetSymbolAddress((void**)&p_nfh, g_nfh);
    cudaGetSymbolAddress((void**)&p_nfl, g_nfl);
    cudaGetSymbolAddress((void**)&p_Wth, g_Wth);
    cudaGetSymbolAddress((void**)&p_Wtl, g_Wtl);
    cudaGetSymbolAddress((void**)&p_Wcth, g_Wcth);
    cudaGetSymbolAddress((void**)&p_Wctl, g_Wctl);

    cudaFuncSetAttribute(attn2_kernel, cudaFuncAttributeMaxDynamicSharedMemorySize, ATTN2_SMEM);
    cudaFuncSetAttribute(gemm_mma, cudaFuncAttributeMaxDynamicSharedMemorySize, GMMA_SMEM);
    cudaFuncSetAttribute(gemm_fxxm, cudaFuncAttributeMaxDynamicSharedMemorySize, GMMA_SMEM);
    cudaFuncSetAttribute(gemm_feat, cudaFuncAttributeMaxDynamicSharedMemorySize, GMMA_SMEM);
    cudaFuncSetAttribute(flashmma_kernel, cudaFuncAttributeMaxDynamicSharedMemorySize, FL_SMEM);

    const int NELEM4 = NPTS * DIM / 4;

    conv_split<<<(NELEM4 + 255) / 256, 256>>>(x, p_xh, p_xl, NELEM4, velo_idx, surf_idx);
    conv_wt3<<<(3 * DIM * DIM + 255) / 256, 256>>>(W_fx, W_x, W_out, b_fx, b_x);

    // merged fx | xm GEMM (N = 1024)
    gemm_fxxm<<<dim3(8, (NPTS + 127) / 128), 256, GMMA_SMEM>>>();

    proj1_kernel<<<dim3((L1 + 63) / 64, HEADS), 256>>>(Wq1, Wk1, Wv1);
    flashmma_kernel<<<dim3((L1 + 127) / 128, HEADS), 256, FL_SMEM>>>();

    prep_kernel<<<(PREP_N + 255) / 256, 256>>>(onion, labels, closest, velo_idx, surf_idx,
                                               W_ws, b_ws, W_vc, b_vc);

    pool_accum<<<dim3((NPT_TOT + ACC_CHUNK - 1) / ACC_CHUNK, DIM / 64), 256>>>();
    ln_kernel<<<8, 64>>>(gamma, beta);
    attn2_kernel<<<HEADS, 256, ATTN2_SMEM>>>(Wq, Wk, Wv);
    mat_out_kernel<<<(NTOK * DIM + 255) / 256, 256>>>();

    int compBlocks = ((DIM + 1) * DIM + 255) / 256;
    comp_kernel<<<compBlocks, 256>>>(p_Wsc, 64, p_bsc, p_osc, 64, 0.5f,
                                     p_Wcth, p_Wctl, p_bc);
    comp_kernel<<<compBlocks, 256>>>(W_vv, VC, b_vv, p_osc + SC * DIM, VC, 1.0f,
                                     p_Wcth + DIM * DIM, p_Wctl + DIM * DIM, p_bc + DIM);

    gemm_feat<<<dim3(DIM / 128, (NSURF + 127) / 128), 256, GMMA_SMEM>>>(
        p_Wcth, p_Wctl, p_bc, surf_idx, NSURF, FLAP, 1);
    gemm_feat<<<dim3(DIM / 128, (NVELO + 127) / 128), 256, GMMA_SMEM>>>(
        p_Wcth + DIM * DIM, p_Wctl + DIM * DIM, p_bc + DIM, velo_idx, NVELO, 0, 0);

    gemm_mma<<<dim3(DIM / 128, (NPTS + 127) / 128), 256, GMMA_SMEM>>>(
        p_nfh, p_nfl, p_Wth + 2 * DIM * DIM, p_Wtl + 2 * DIM * DIM,
        b_out, out, nullptr, nullptr, NPTS);
}

// round 17
// speedup vs baseline: 4.4325x; 1.1343x over previous
#include <cuda_runtime.h>
#include <cuda_bf16.h>
#include <cuda_fp16.h>
#include <cstdint>

#define HEADS 8
#define DH 64
#define DIM 512
#define ONION 15
#define SC 4
#define NVELO 28504
#define NSURF 3682
#define NPTS 32186
#define SKEEP 3586
#define FLAP 500
#define NTOK 64
#define L1 4182
#define VC 60
#define NPT_TOT (NVELO + SKEEP)
#define PREP_N ((NTOK * DIM) > NPT_TOT ? (NTOK * DIM) : NPT_TOT)
#define ATT_SCALE 0.125f
#define LOG2E 1.4426950408889634f
#define LN_EPS 1e-5f
#define ATTN2_SMEM (5 * 64 * 68 * 4)

// ---------------- scratch ----------------
__device__ float g_fx[NPTS * DIM];
__device__ float g_o1[HEADS * L1 * DH];
__device__ __half g_q1f[HEADS * L1 * DH];
__device__ __half g_k1f[HEADS * L1 * DH];
__device__ __half g_v1f[HEADS * L1 * DH];
__device__ int   g_tok1src[L1];
__device__ int   g_ptrow[NPT_TOT];
__device__ int   g_ptgrp[NPT_TOT];
__device__ float g_tokacc[NTOK * DIM];
__device__ float g_toknorm[NTOK * DIM];
__device__ float g_outtok[HEADS * NTOK * DH];
__device__ float g_osc[NTOK * DIM];
__device__ float g_Wsc[DIM * 64];
__device__ float g_bsc[64];
__device__ __nv_bfloat16 g_xh[NPTS * DIM];
__device__ __nv_bfloat16 g_xl[NPTS * DIM];
__device__ __nv_bfloat16 g_xmh[NPTS * DIM];
__device__ __nv_bfloat16 g_xml[NPTS * DIM];
__device__ __nv_bfloat16 g_nfh[NPTS * DIM];
__device__ __nv_bfloat16 g_nfl[NPTS * DIM];
__device__ __nv_bfloat16 g_Wth[3 * DIM * DIM];
__device__ __nv_bfloat16 g_Wtl[3 * DIM * DIM];
__device__ __nv_bfloat16 g_Wcth[2 * DIM * DIM];
__device__ __nv_bfloat16 g_Wctl[2 * DIM * DIM];
__device__ float g_bc[2 * DIM];
__device__ float g_bcat[2 * DIM];

// ---------------- helpers --------
__device__ __forceinline__ uint32_t smem_u32(const void* p) {
    uint32_t a;
    asm("{ .reg .u64 t; cvta.to.shared.u64 t, %1; cvt.u32.u64 %0, t; }" : "=r"(a) : "l"(p));
    return a;
}
#define CPA16(dst, src, sz) \
    asm volatile("cp.async.cg.shared.global [%0], [%1], 16, %2;" \
                 :: "r"(dst), "l"(src), "r"(sz) : "memory")
#define CPA_COMMIT() asm volatile("cp.async.commit_group;" ::: "memory")
#define CPA_WAIT0()  asm volatile("cp.async.wait_group 0;" ::: "memory")
#define CPA_WAIT1()  asm volatile("cp.async.wait_group 1;" ::: "memory")
#define LDSM4(r, addr) \
    asm volatile("ldmatrix.sync.aligned.m8n8.x4.shared.b16 {%0,%1,%2,%3}, [%4];" \
                 : "=r"((r)[0]), "=r"((r)[1]), "=r"((r)[2]), "=r"((r)[3]) : "r"(addr))
#define LDSM4T(r, addr) \
    asm volatile("ldmatrix.sync.aligned.m8n8.x4.trans.shared.b16 {%0,%1,%2,%3}, [%4];" \
                 : "=r"((r)[0]), "=r"((r)[1]), "=r"((r)[2]), "=r"((r)[3]) : "r"(addr))
#define MMA16816(c, a, b0v, b1v) \
    asm volatile("mma.sync.aligned.m16n8k16.row.col.f32.bf16.bf16.f32 " \
                 "{%0,%1,%2,%3},{%4,%5,%6,%7},{%8,%9},{%0,%1,%2,%3};" \
                 : "+f"((c)[0]), "+f"((c)[1]), "+f"((c)[2]), "+f"((c)[3]) \
                 : "r"((a)[0]), "r"((a)[1]), "r"((a)[2]), "r"((a)[3]), "r"(b0v), "r"(b1v))
#define MMAH16816(c, a, b0v, b1v) \
    asm volatile("mma.sync.aligned.m16n8k16.row.col.f32.f16.f16.f32 " \
                 "{%0,%1,%2,%3},{%4,%5,%6,%7},{%8,%9},{%0,%1,%2,%3};" \
                 : "+f"((c)[0]), "+f"((c)[1]), "+f"((c)[2]), "+f"((c)[3]) \
                 : "r"((a)[0]), "r"((a)[1]), "r"((a)[2]), "r"((a)[3]), "r"(b0v), "r"(b1v))
__device__ __forceinline__ uint32_t pk2(float lo, float hi) {
    uint32_t r;
    asm("cvt.rn.bf16x2.f32 %0, %1, %2;" : "=r"(r) : "f"(hi), "f"(lo));
    return r;
}
__device__ __forceinline__ uint32_t pk2h(float lo, float hi) {
    uint32_t r;
    asm("cvt.rn.f16x2.f32 %0, %1, %2;" : "=r"(r) : "f"(hi), "f"(lo));
    return r;
}
__device__ __forceinline__ uint32_t splitpair(float v0, float v1, uint32_t& lopack) {
    uint32_t hp = pk2(v0, v1);
    __nv_bfloat162 hb = *(__nv_bfloat162*)&hp;
    lopack = pk2(v0 - __bfloat162float(hb.x), v1 - __bfloat162float(hb.y));
    return hp;
}

// ---------------------------------------------------------------------------
// split-bf16 HMMA GEMM machinery
// ---------------------------------------------------------------------------
#define PLANE_B 10240
#define BUF_B   (4 * PLANE_B)
#define GMMA_SMEM (2 * BUF_B)

__device__ __forceinline__ void fill_chunk(
    uint32_t sb, const __nv_bfloat16* __restrict__ Ah, const __nv_bfloat16* __restrict__ Al,
    const __nv_bfloat16* __restrict__ Bh, const __nv_bfloat16* __restrict__ Bl,
    const int* __restrict__ rowidx,
    int m0, int n0, int k0, int M, int tid)
{
    #pragma unroll
    for (int hf = 0; hf < 2; hf++) {
        int s = tid + hf * 256;
        int r = s >> 2, v = s & 3;
        uint32_t off = (uint32_t)(r * 80 + v * 16);
        int gm = m0 + r;
        int szA = (gm < M) ? 16 : 0;
        int gmc = (gm < M) ? gm : (M - 1);
        int arow = rowidx ? rowidx[gmc] : gmc;
        CPA16(sb + off,               Ah + (size_t)arow * DIM + k0 + v * 8, szA);
        CPA16(sb + PLANE_B + off,     Al + (size_t)arow * DIM + k0 + v * 8, szA);
        CPA16(sb + 2 * PLANE_B + off, Bh + (size_t)(n0 + r) * DIM + k0 + v * 8, 16);
        CPA16(sb + 3 * PLANE_B + off, Bl + (size_t)(n0 + r) * DIM + k0 + v * 8, 16);
    }
}

__device__ __forceinline__ void mma_mainloop(
    uint32_t smb, const __nv_bfloat16* Ah, const __nv_bfloat16* Al,
    const __nv_bfloat16* Bth, const __nv_bfloat16* Btl,
    const int* rowidx, int m0, int n0, int M, int tid, int lane, int wy, int wx,
    float acc[2][8][4])
{
    uint32_t aBase = (uint32_t)((wy * 32 + (lane & 15)) * 80 + (lane >> 4) * 16);
    uint32_t bBase = (uint32_t)((wx * 64 + (lane & 15)) * 80 + (lane >> 4) * 16);
    fill_chunk(smb, Ah, Al, Bth, Btl, rowidx, m0, n0, 0, M, tid);
    CPA_COMMIT();
    for (int ch = 0; ch < 16; ch++) {
        uint32_t sb = smb + (uint32_t)(ch & 1) * BUF_B;
        CPA_WAIT0();
        __syncthreads();
        if (ch < 15) {
            fill_chunk(smb + (uint32_t)((ch + 1) & 1) * BUF_B,
                       Ah, Al, Bth, Btl, rowidx, m0, n0, (ch + 1) * 32, M, tid);
            CPA_COMMIT();
        }
        uint32_t AH = sb, AL = sb + PLANE_B, BH = sb + 2 * PLANE_B, BL = sb + 3 * PLANE_B;
        #pragma unroll
        for (int ks = 0; ks < 2; ks++) {
            uint32_t ko = (uint32_t)(ks * 32);
            uint32_t ah[2][4], al[2][4];
            LDSM4(ah[0], AH + aBase + ko);
            LDSM4(ah[1], AH + aBase + 1280 + ko);
            LDSM4(al[0], AL + aBase + ko);
            LDSM4(al[1], AL + aBase + 1280 + ko);
            #pragma unroll
            for (int np = 0; np < 4; np++) {
                uint32_t bh[4], bl[4];
                uint32_t boff = bBase + (uint32_t)(np * 16 * 80) + ko;
                LDSM4(bh, BH + boff);
                LDSM4(bl, BL + boff);
                #pragma unroll
                for (int mt = 0; mt < 2; mt++) {
                    float* c0 = acc[mt][np * 2];
                    float* c1 = acc[mt][np * 2 + 1];
                    MMA16816(c0, ah[mt], bh[0], bh[2]);
                    MMA16816(c0, ah[mt], bl[0], bl[2]);
                    MMA16816(c0, al[mt], bh[0], bh[2]);
                    MMA16816(c1, ah[mt], bh[1], bh[3]);
                    MMA16816(c1, ah[mt], bl[1], bl[3]);
                    MMA16816(c1, al[mt], bh[1], bh[3]);
                }
            }
        }
        __syncthreads();
    }
}

__global__ void __launch_bounds__(256, 2) gemm_mma(
    const __nv_bfloat16* __restrict__ Ah, const __nv_bfloat16* __restrict__ Al,
    const __nv_bfloat16* __restrict__ Bth, const __nv_bfloat16* __restrict__ Btl,
    const float* __restrict__ bias, float* __restrict__ Cf,
    __nv_bfloat16* __restrict__ Ch, __nv_bfloat16* __restrict__ Cl, int M)
{
    extern __shared__ char smbuf[];
    uint32_t smb = smem_u32(smbuf);
    int tid = threadIdx.x, lane = tid & 31, wid = tid >> 5;
    int wy = wid & 3, wx = wid >> 2;
    int m0 = blockIdx.y * 128, n0 = blockIdx.x * 128;
    float acc[2][8][4] = {};
    mma_mainloop(smb, Ah, Al, Bth, Btl, nullptr, m0, n0, M, tid, lane, wy, wx, acc);

    int g = lane >> 2, tig = lane & 3;
    #pragma unroll
    for (int mt = 0; mt < 2; mt++) {
        int r0 = m0 + wy * 32 + mt * 16 + g;
        #pragma unroll
        for (int nt = 0; nt < 8; nt++) {
            int col = n0 + wx * 64 + nt * 8 + tig * 2;
            float2 b2 = *(const float2*)&bias[col];
            float v00 = acc[mt][nt][0] + b2.x, v01 = acc[mt][nt][1] + b2.y;
            float v10 = acc[mt][nt][2] + b2.x, v11 = acc[mt][nt][3] + b2.y;
            if (Cf) {
                if (r0 < M)     *(float2*)&Cf[(size_t)r0 * DIM + col] = make_float2(v00, v01);
                if (r0 + 8 < M) *(float2*)&Cf[(size_t)(r0 + 8) * DIM + col] = make_float2(v10, v11);
            } else {
                uint32_t lo;
                if (r0 < M) {
                    uint32_t hi = splitpair(v00, v01, lo);
                    *(uint32_t*)&Ch[(size_t)r0 * DIM + col] = hi;
                    *(uint32_t*)&Cl[(size_t)r0 * DIM + col] = lo;
                }
                if (r0 + 8 < M) {
                    uint32_t hi = splitpair(v10, v11, lo);
                    *(uint32_t*)&Ch[(size_t)(r0 + 8) * DIM + col] = hi;
                    *(uint32_t*)&Cl[(size_t)(r0 + 8) * DIM + col] = lo;
                }
            }
        }
    }
}

__global__ void __launch_bounds__(256, 2) gemm_fxxm()
{
    extern __shared__ char smbuf[];
    uint32_t smb = smem_u32(smbuf);
    int tid = threadIdx.x, lane = tid & 31, wid = tid >> 5;
    int wy = wid & 3, wx = wid >> 2;
    int m0 = blockIdx.y * 128, n0 = blockIdx.x * 128;
    float acc[2][8][4] = {};
    mma_mainloop(smb, g_xh, g_xl, g_Wth, g_Wtl, nullptr, m0, n0, NPTS, tid, lane, wy, wx, acc);

    int g = lane >> 2, tig = lane & 3;
    #pragma unroll
    for (int mt = 0; mt < 2; mt++) {
        int r0 = m0 + wy * 32 + mt * 16 + g;
        #pragma unroll
        for (int nt = 0; nt < 8; nt++) {
            int col = n0 + wx * 64 + nt * 8 + tig * 2;
            float2 b2 = *(const float2*)&g_bcat[col];
            float v00 = acc[mt][nt][0] + b2.x, v01 = acc[mt][nt][1] + b2.y;
            float v10 = acc[mt][nt][2] + b2.x, v11 = acc[mt][nt][3] + b2.y;
            if (col < DIM) {
                if (r0 < NPTS)     *(float2*)&g_fx[(size_t)r0 * DIM + col] = make_float2(v00, v01);
                if (r0 + 8 < NPTS) *(float2*)&g_fx[(size_t)(r0 + 8) * DIM + col] = make_float2(v10, v11);
            } else {
                int c2 = col - DIM;
                uint32_t lo;
                if (r0 < NPTS) {
                    uint32_t hi = splitpair(v00, v01, lo);
                    *(uint32_t*)&g_xmh[(size_t)r0 * DIM + c2] = hi;
                    *(uint32_t*)&g_xml[(size_t)r0 * DIM + c2] = lo;
                }
                if (r0 + 8 < NPTS) {
                    uint32_t hi = splitpair(v10, v11, lo);
                    *(uint32_t*)&g_xmh[(size_t)(r0 + 8) * DIM + c2] = hi;
                    *(uint32_t*)&g_xml[(size_t)(r0 + 8) * DIM + c2] = lo;
                }
            }
        }
    }
}

__global__ void __launch_bounds__(256, 2) gemm_feat(
    const __nv_bfloat16* __restrict__ Bth, const __nv_bfloat16* __restrict__ Btl,
    const float* __restrict__ bcomp, const int* __restrict__ rowidx,
    int M, int o1_off, int o1_always)
{
    extern __shared__ char smbuf[];
    uint32_t smb = smem_u32(smbuf);
    int tid = threadIdx.x, lane = tid & 31, wid = tid >> 5;
    int wy = wid & 3, wx = wid >> 2;
    int m0 = blockIdx.y * 128, n0 = blockIdx.x * 128;
    float acc[2][8][4] = {};
    mma_mainloop(smb, g_xmh, g_xml, Bth, Btl, rowidx, m0, n0, M, tid, lane, wy, wx, acc);

    int g = lane >> 2, tig = lane & 3;
    #pragma unroll
    for (int mt = 0; mt < 2; mt++) {
        int gi0 = m0 + wy * 32 + mt * 16 + g;
        int gi1 = gi0 + 8;
        int or0 = (gi0 < M) ? rowidx[gi0] : 0;
        int or1 = (gi1 < M) ? rowidx[gi1] : 0;
        bool a0 = o1_always || (gi0 < FLAP);
        bool a1 = o1_always || (gi1 < FLAP);
        #pragma unroll
        for (int nt = 0; nt < 8; nt++) {
            int col = n0 + wx * 64 + nt * 8 + tig * 2;
            int h = col >> 6, dd = col & 63;
            float2 b2 = *(const float2*)&bcomp[col];
            uint32_t lo;
            if (gi0 < M) {
                float v0 = acc[mt][nt][0] + b2.x, v1 = acc[mt][nt][1] + b2.y;
                if (a0) {
                    const float* o1p = &g_o1[((size_t)h * L1 + (o1_off + gi0)) * DH + dd];
                    v0 += o1p[0]; v1 += o1p[1];
                }
                uint32_t hi = splitpair(v0, v1, lo);
                *(uint32_t*)&g_nfh[(size_t)or0 * DIM + col] = hi;
                *(uint32_t*)&g_nfl[(size_t)or0 * DIM + col] = lo;
            }
            if (gi1 < M) {
                float v0 = acc[mt][nt][2] + b2.x, v1 = acc[mt][nt][3] + b2.y;
                if (a1) {
                    const float* o1p = &g_o1[((size_t)h * L1 + (o1_off + gi1)) * DH + dd];
                    v0 += o1p[0]; v1 += o1p[1];
                }
                uint32_t hi = splitpair(v0, v1, lo);
                *(uint32_t*)&g_nfh[(size_t)or1 * DIM + col] = hi;
                *(uint32_t*)&g_nfl[(size_t)or1 * DIM + col] = lo;
            }
        }
    }
}

__global__ void conv_split(const float* __restrict__ s,
                           __nv_bfloat16* __restrict__ h,
                           __nv_bfloat16* __restrict__ l, int n4,
                           const int* __restrict__ velo_idx,
                           const int* __restrict__ surf_idx)
{
    int i = blockIdx.x * 256 + threadIdx.x;
    if (velo_idx && i < L1)
        g_tok1src[i] = (i < FLAP) ? velo_idx[i] : surf_idx[i - FLAP];
    if (i >= n4) return;
    float4 v = *(const float4*)&s[i * 4];
    float a[4] = {v.x, v.y, v.z, v.w};
    #pragma unroll
    for (int j = 0; j < 4; j++) {
        __nv_bfloat16 hh = __float2bfloat16(a[j]);
        h[i * 4 + j] = hh;
        l[i * 4 + j] = __float2bfloat16(a[j] - __bfloat162float(hh));
    }
}

__global__ void conv_wt3(const float* __restrict__ W0, const float* __restrict__ W1,
                         const float* __restrict__ W2,
                         const float* __restrict__ b0, const float* __restrict__ b1)
{
    int i = blockIdx.x * 256 + threadIdx.x;
    if (i < DIM) { g_bcat[i] = b0[i]; g_bcat[DIM + i] = b1[i]; }
    if (i >= 3 * DIM * DIM) return;
    int w = i / (DIM * DIM), r = i % (DIM * DIM);
    const float* W = (w == 0) ? W0 : ((w == 1) ? W1 : W2);
    int k = r >> 9, n = r & 511;
    float v = W[r];
    __nv_bfloat16 hh = __float2bfloat16(v);
    g_Wth[w * DIM * DIM + n * DIM + k] = hh;
    g_Wtl[w * DIM * DIM + n * DIM + k] = __float2bfloat16(v - __bfloat162float(hh));
}

__global__ void comp_kernel(const float* __restrict__ A, int ldA,
                            const float* __restrict__ bias,
                            const float* __restrict__ O, int C, float scale,
                            __nv_bfloat16* __restrict__ Bth,
                            __nv_bfloat16* __restrict__ Btl,
                            float* __restrict__ bc)
{
    int id = blockIdx.x * 256 + threadIdx.x;
    if (id >= (DIM + 1) * DIM) return;
    int k = id >> 9, n = id & 511;
    float acc = 0.f;
    if (k < DIM) {
        for (int c = 0; c < C; c++) acc += A[k * ldA + c] * O[c * DIM + n];
        acc *= scale;
        __nv_bfloat16 hh = __float2bfloat16(acc);
        Bth[n * DIM + k] = hh;
        Btl[n * DIM + k] = __float2bfloat16(acc - __bfloat162float(hh));
    } else {
        for (int c = 0; c < C; c++) acc += bias[c] * O[c * DIM + n];
        bc[n] = acc * scale;
    }
}

__global__ void prep_kernel(const float* __restrict__ onion,
                            const int* __restrict__ labels,
                            const int* __restrict__ closest,
                            const int* __restrict__ velo_idx,
                            const int* __restrict__ surf_idx,
                            const float* __restrict__ W_ws,
                            const float* __restrict__ b_ws,
                            const float* __restrict__ W_vc,
                            const float* __restrict__ b_vc)
{
    int i = blockIdx.x * 256 + threadIdx.x;
    if (i < NTOK * DIM) g_tokacc[i] = 0.f;
    if (i < DIM * 64) {
        int k = i >> 6, n = i & 63;
        g_Wsc[i] = (n < SC) ? W_ws[k * SC + n] : W_vc[k * VC + n - SC];
    }
    if (i < 64) g_bsc[i] = (i < SC) ? b_ws[i] : b_vc[i - SC];
    if (i >= NPT_TOT) return;
    if (i < NVELO) {
        int lab = 0;
        #pragma unroll
        for (int l = 1; l < ONION; l++)
            if (onion[l * NVELO + i] > 0.5f) lab = l;
        g_ptrow[i] = velo_idx[i];
        g_ptgrp[i] = SC + lab * SC + labels[closest[i]];
    } else {
        int j = i - NVELO;
        int sr = (j < 16) ? j : j + 96;
        g_ptrow[i] = surf_idx[sr];
        g_ptgrp[i] = labels[j];
    }
}

__global__ void proj1_kernel(const float* __restrict__ Wq1,
                             const float* __restrict__ Wk1,
                             const float* __restrict__ Wv1)
{
    __shared__ float Ts[64][68];
    __shared__ float Ws[64][68];
    int h = blockIdx.y, t0 = blockIdx.x * 64;
    int tid = threadIdx.x, ty = tid >> 4, tx = tid & 15;
    #pragma unroll
    for (int e = tid; e < 4096; e += 256) {
        int t = e >> 6, d = e & 63;
        int gt = t0 + t;
        Ts[t][d] = (gt < L1) ? g_fx[g_tok1src[gt] * DIM + h * DH + d] : 0.f;
    }
    const float* Wm[3] = {Wq1, Wk1, Wv1};
    __half* Of[3] = {g_q1f, g_k1f, g_v1f};
    #pragma unroll
    for (int m = 0; m < 3; m++) {
        __syncthreads();
        #pragma unroll
        for (int e = tid; e < 4096; e += 256) Ws[e >> 6][e & 63] = Wm[m][e];
        __syncthreads();
        float acc[4][4] = {};
        #pragma unroll
        for (int x = 0; x < 64; x++) {
            float ar[4];
            #pragma unroll
            for (int i = 0; i < 4; i++) ar[i] = Ts[ty * 4 + i][x];
            float4 b4 = *(const float4*)&Ws[x][tx * 4];
            float br[4] = {b4.x, b4.y, b4.z, b4.w};
            #pragma unroll
            for (int i = 0; i < 4; i++)
                #pragma unroll
                for (int j = 0; j < 4; j++)
                    acc[i][j] += ar[i] * br[j];
        }
        float sc = (m == 0) ? (ATT_SCALE * LOG2E) : 1.f;
        #pragma unroll
        for (int i = 0; i < 4; i++) {
            int gt = t0 + ty * 4 + i;
            if (gt >= L1) continue;
            size_t base = (size_t)h * (L1 * DH) + (size_t)gt * DH + tx * 4;
            #pragma unroll
            for (int j = 0; j < 4; j++)
                Of[m][base + j] = __float2half(acc[i][j] * sc);
        }
    }
}

// ---------------------------------------------------------------------------
// flash attention (unchanged)
// ---------------------------------------------------------------------------
#define FL_STRIDE 144
#define FL_PLANE (64 * FL_STRIDE)
#define FL_BUF (2 * FL_PLANE)
#define FL_QOFF (2 * FL_BUF)
#define FL_SMEM (FL_QOFF + 128 * FL_STRIDE)
#define NKT ((L1 + 63) / 64)

__device__ __forceinline__ void fl_fill(uint32_t buf, int h, int kt, int tid)
{
    #pragma unroll
    for (int i = 0; i < 4; i++) {
        int s = tid + i * 256;
        int plane = s >> 9;
        int e = s & 511;
        int r = e >> 3, v = e & 7;
        int kk = kt * 64 + r;
        int sz = (kk < L1) ? 16 : 0;
        int kkc = (kk < L1) ? kk : (L1 - 1);
        const __half* src = plane ? g_v1f : g_k1f;
        CPA16(buf + plane * FL_PLANE + r * FL_STRIDE + v * 16,
              src + (size_t)h * (L1 * DH) + (size_t)kkc * DH + v * 8, sz);
    }
}

__global__ void __launch_bounds__(256, 2) flashmma_kernel()
{
    extern __shared__ char sm[];
    uint32_t smb = smem_u32(sm);
    int tid = threadIdx.x, lane = tid & 31, w = tid >> 5;
    int h = blockIdx.y, q0 = blockIdx.x * 128;
    int g = lane >> 2, tq = lane & 3;

    {
        uint32_t qbuf = smb + FL_QOFF;
        #pragma unroll
        for (int i = 0; i < 4; i++) {
            int s = tid + i * 256;
            int r = s >> 3, v = s & 7;
            int gq = q0 + r;
            int sz = (gq < L1) ? 16 : 0;
            int gqc = (gq < L1) ? gq : (L1 - 1);
            CPA16(qbuf + r * FL_STRIDE + v * 16,
                  g_q1f + (size_t)h * (L1 * DH) + (size_t)gqc * DH + v * 8, sz);
        }
        CPA_COMMIT();
    }
    fl_fill(smb, h, 0, tid);
    CPA_COMMIT();

    CPA_WAIT1();
    __syncthreads();
    uint32_t qh[4][4];
    {
        uint32_t qa = smb + FL_QOFF + (uint32_t)((w * 16 + (lane & 15)) * FL_STRIDE + (lane >> 4) * 16);
        #pragma unroll
        for (int kc = 0; kc < 4; kc++) LDSM4(qh[kc], qa + kc * 32);
    }

    float o[4][2][4] = {};
    float l0f = 0.f, l1f = 0.f;

    for (int kt = 0; kt < NKT; kt++) {
        uint32_t cur = smb + (uint32_t)(kt & 1) * FL_BUF;
        if (kt + 1 < NKT) {
            fl_fill(smb + (uint32_t)((kt + 1) & 1) * FL_BUF, h, kt + 1, tid);
            CPA_COMMIT();
            CPA_WAIT1();
        } else {
            CPA_WAIT0();
        }
        __syncthreads();

        float s[4][2][4];
        #pragma unroll
        for (int nb = 0; nb < 4; nb++)
            #pragma unroll
            for (int ng = 0; ng < 2; ng++)
                #pragma unroll
                for (int e = 0; e < 4; e++) s[nb][ng][e] = 0.f;
        uint32_t kBase = cur + (uint32_t)((lane & 15) * FL_STRIDE + (lane >> 4) * 16);
        #pragma unroll
        for (int nb = 0; nb < 4; nb++) {
            #pragma unroll
            for (int kc = 0; kc < 4; kc++) {
                uint32_t bh[4];
                LDSM4(bh, kBase + (uint32_t)(nb * 16 * FL_STRIDE + kc * 32));
                MMAH16816(s[nb][0], qh[kc], bh[0], bh[2]);
                MMAH16816(s[nb][1], qh[kc], bh[1], bh[3]);
            }
        }
        int ktb = kt * 64;
        if (ktb + 64 > L1) {
            #pragma unroll
            for (int nb = 0; nb < 4; nb++)
                #pragma unroll
                for (int ng = 0; ng < 2; ng++) {
                    int kk0 = ktb + nb * 16 + ng * 8 + tq * 2;
                    if (kk0 >= L1)     { s[nb][ng][0] = -1e30f; s[nb][ng][2] = -1e30f; }
                    if (kk0 + 1 >= L1) { s[nb][ng][1] = -1e30f; s[nb][ng][3] = -1e30f; }
                }
        }
        #pragma unroll
        for (int nb = 0; nb < 4; nb++)
            #pragma unroll
            for (int ng = 0; ng < 2; ng++) {
                float p0 = exp2f(s[nb][ng][0]);
                float p1 = exp2f(s[nb][ng][1]);
                float p2 = exp2f(s[nb][ng][2]);
                float p3 = exp2f(s[nb][ng][3]);
                s[nb][ng][0] = p0; s[nb][ng][1] = p1;
                s[nb][ng][2] = p2; s[nb][ng][3] = p3;
                l0f += p0 + p1; l1f += p2 + p3;
            }
        uint32_t vBase = cur + FL_PLANE +
            (uint32_t)(((lane & 7) + ((lane >> 4) & 1) * 8) * FL_STRIDE + ((lane >> 3) & 1) * 16);
        #pragma unroll
        for (int nbk = 0; nbk < 4; nbk++) {
            uint32_t pa[4];
            #pragma unroll
            for (int hv = 0; hv < 2; hv++)
                #pragma unroll
                for (int pr = 0; pr < 2; pr++)
                    pa[hv * 2 + pr] = pk2h(s[nbk][hv][pr * 2], s[nbk][hv][pr * 2 + 1]);
            #pragma unroll
            for (int nd = 0; nd < 4; nd++) {
                uint32_t vb[4];
                LDSM4T(vb, vBase + (uint32_t)(nbk * 16 * FL_STRIDE + nd * 32));
                MMAH16816(o[nd][0], pa, vb[0], vb[2]);
                MMAH16816(o[nd][1], pa, vb[1], vb[3]);
            }
        }
        __syncthreads();
    }

    l0f += __shfl_xor_sync(0xffffffffu, l0f, 1);
    l0f += __shfl_xor_sync(0xffffffffu, l0f, 2);
    l1f += __shfl_xor_sync(0xffffffffu, l1f, 1);
    l1f += __shfl_xor_sync(0xffffffffu, l1f, 2);

    float i0 = 1.f / l0f, i1 = 1.f / l1f;
    int r0 = q0 + w * 16 + g, r1 = r0 + 8;
    #pragma unroll
    for (int nd = 0; nd < 4; nd++)
        #pragma unroll
        for (int ng = 0; ng < 2; ng++) {
            int col = nd * 16 + ng * 8 + tq * 2;
            if (r0 < L1) {
                float2 v = make_float2(o[nd][ng][0] * i0, o[nd][ng][1] * i0);
                *(float2*)&g_o1[(size_t)h * (L1 * DH) + (size_t)r0 * DH + col] = v;
            }
            if (r1 < L1) {
                float2 v = make_float2(o[nd][ng][2] * i1, o[nd][ng][3] * i1);
                *(float2*)&g_o1[(size_t)h * (L1 * DH) + (size_t)r1 * DH + col] = v;
            }
        }
}

#define ACC_CHUNK 1024
__global__ void pool_accum()
{
    __shared__ float sa[64][64];
    int d0 = blockIdx.y * 64, p0 = blockIdx.x * ACC_CHUNK;
    int tid = threadIdx.x, dd = tid & 63, q4 = tid >> 6;
    #pragma unroll
    for (int e = tid; e < 4096; e += 256) ((float*)sa)[e] = 0.f;
    __syncthreads();
    int pend = min(p0 + ACC_CHUNK, NPT_TOT);
    for (int p = p0 + q4; p < pend; p += 4) {
        float v = g_fx[g_ptrow[p] * DIM + d0 + dd];
        atomicAdd(&sa[g_ptgrp[p]][dd], v);
    }
    __syncthreads();
    #pragma unroll
    for (int e = tid; e < 4096; e += 256) {
        int g = e >> 6, d = e & 63;
        float v = sa[g][d];
        if (v != 0.f) atomicAdd(&g_tokacc[g * DIM + d0 + d], v);
    }
}

__global__ void ln_kernel(const float* __restrict__ gamma,
                          const float* __restrict__ beta)
{
    int d = blockIdx.x * 64 + threadIdx.x;
    const float n_s = 1.f / (float)SKEEP, n_v = 1.f / (float)NVELO;
    float s = 0.f;
    #pragma unroll
    for (int t = 0; t < NTOK; t++)
        s += g_tokacc[t * DIM + d] * ((t < SC) ? n_s : n_v);
    float mu = s * (1.f / NTOK);
    float v2 = 0.f;
    #pragma unroll
    for (int t = 0; t < NTOK; t++) {
        float dv = g_tokacc[t * DIM + d] * ((t < SC) ? n_s : n_v) - mu;
        v2 += dv * dv;
    }
    float inv = rsqrtf(v2 * (1.f / NTOK) + LN_EPS);
    #pragma unroll
    for (int t = 0; t < NTOK; t++) {
        float val = g_tokacc[t * DIM + d] * ((t < SC) ? n_s : n_v);
        g_toknorm[t * DIM + d] = (val - mu) * inv * gamma[t] + beta[t];
    }
}

__global__ void attn2_kernel(const float* __restrict__ Wq,
                             const float* __restrict__ Wk,
                             const float* __restrict__ Wv)
{
    extern __shared__ float sm2[];
    float (*tk)[68] = (float(*)[68])sm2;
    float (*qs)[68] = tk + 64;
    float (*ks)[68] = qs + 64;
    float (*vs)[68] = ks + 64;
    float (*ss)[68] = vs + 64;
    int h = blockIdx.x, tid = threadIdx.x;
    #pragma unroll
    for (int e = tid; e < 4096; e += 256) {
        int t = e >> 6, d = e & 63;
        tk[t][d] = g_toknorm[t * DIM + h * DH + d];
    }
    __syncthreads();
    #pragma unroll
    for (int e = tid; e < 4096; e += 256) {
        int t = e >> 6, d = e & 63;
        float aq = 0.f, ak = 0.f, av = 0.f;
        for (int x = 0; x < 64; x++) {
            float tv = tk[t][x];
            aq += tv * Wq[x * 64 + d];
            ak += tv * Wk[x * 64 + d];
            av += tv * Wv[x * 64 + d];
        }
        qs[t][d] = aq; ks[t][d] = ak; vs[t][d] = av;
    }
    __syncthreads();
    #pragma unroll
    for (int e = tid; e < 4096; e += 256) {
        int t = e >> 6, u = e & 63;
        float sv = 0.f;
        for (int d = 0; d < 64; d++) sv += qs[t][d] * ks[u][d];
        ss[t][u] = sv * ATT_SCALE;
    }
    __syncthreads();
    if (tid < 64) {
        float mx = -1e30f;
        for (int j = 0; j < 64; j++) mx = fmaxf(mx, ss[tid][j]);
        float sum = 0.f;
        for (int j = 0; j < 64; j++) {
            float p = __expf(ss[tid][j] - mx);
            ss[tid][j] = p; sum += p;
        }
        float inv = 1.f / sum;
        for (int j = 0; j < 64; j++) ss[tid][j] *= inv;
    }
    __syncthreads();
    #pragma unroll
    for (int e = tid; e < 4096; e += 256) {
        int t = e >> 6, d = e & 63;
        float o = 0.f;
        for (int u = 0; u < 64; u++) o += ss[t][u] * vs[u][d];
        g_outtok[h * (NTOK * DH) + t * DH + d] = o;
    }
}

__global__ void mat_out_kernel()
{
    int i = blockIdx.x * 256 + threadIdx.x;
    if (i >= NTOK * DIM) return;
    int t = i >> 9, d = i & 511;
    float v;
    if (t < SC) {
        int f = t * 512 + d;
        v = g_outtok[(f >> 8) * 4096 + (((f >> 6) & 3) << 6) + (f & 63)];
    } else {
        int r = t - SC;
        v = g_outtok[(d >> 6) * 4096 + (SC + r) * 64 + (d & 63)];
    }
    g_osc[i] = v;
}

extern "C" void kernel_launch(void* const* d_in, const int* in_sizes, int n_in,
                              void* d_out, int out_size)
{
    (void)in_sizes; (void)n_in; (void)out_size;
    const float* x     = (const float*)d_in[0];
    const float* onion = (const float*)d_in[1];
    const float* W_fx  = (const float*)d_in[2];
    const float* b_fx  = (const float*)d_in[3];
    const float* W_x   = (const float*)d_in[4];
    const float* b_x   = (const float*)d_in[5];
    const float* Wq1   = (const float*)d_in[6];
    const float* Wk1   = (const float*)d_in[7];
    const float* Wv1   = (const float*)d_in[8];
    const float* Wq    = (const float*)d_in[9];
    const float* Wk    = (const float*)d_in[10];
    const float* Wv    = (const float*)d_in[11];
    const float* gamma = (const float*)d_in[12];
    const float* beta  = (const float*)d_in[13];
    const float* W_ws  = (const float*)d_in[14];
    const float* b_ws  = (const float*)d_in[15];
    const float* W_vv  = (const float*)d_in[16];
    const float* b_vv  = (const float*)d_in[17];
    const float* W_vc  = (const float*)d_in[18];
    const float* b_vc  = (const float*)d_in[19];
    const float* W_out = (const float*)d_in[20];
    const float* b_out = (const float*)d_in[21];
    const int* surf_idx = (const int*)d_in[22];
    const int* velo_idx = (const int*)d_in[23];
    const int* closest  = (const int*)d_in[25];
    const int* labels   = (const int*)d_in[26];
    float* out = (float*)d_out;

    float *p_Wsc, *p_bsc, *p_osc, *p_bc;
    __nv_bfloat16 *p_xh, *p_xl, *p_nfh, *p_nfl, *p_Wth, *p_Wtl, *p_Wcth, *p_Wctl;
    cudaGetSymbolAddress((void**)&p_Wsc, g_Wsc);
    cudaGetSymbolAddress((void**)&p_bsc, g_bsc);
    cudaGetSymbolAddress((void**)&p_osc, g_osc);
    cudaGetSymbolAddress((void**)&p_bc, g_bc);
    cudaGetSymbolAddress((void**)&p_xh, g_xh);
    cudaGetSymbolAddress((void**)&p_xl, g_xl);
    cudaGetSymbolAddress((void**)&p_nfh, g_nfh);
    cudaGetSymbolAddress((void**)&p_nfl, g_nfl);
    cudaGetSymbolAddress((void**)&p_Wth, g_Wth);
    cudaGetSymbolAddress((void**)&p_Wtl, g_Wtl);
    cudaGetSymbolAddress((void**)&p_Wcth, g_Wcth);
    cudaGetSymbolAddress((void**)&p_Wctl, g_Wctl);

    cudaFuncSetAttribute(attn2_kernel, cudaFuncAttributeMaxDynamicSharedMemorySize, ATTN2_SMEM);
    cudaFuncSetAttribute(gemm_mma, cudaFuncAttributeMaxDynamicSharedMemorySize, GMMA_SMEM);
    cudaFuncSetAttribute(gemm_fxxm, cudaFuncAttributeMaxDynamicSharedMemorySize, GMMA_SMEM);
    cudaFuncSetAttribute(gemm_feat, cudaFuncAttributeMaxDynamicSharedMemorySize, GMMA_SMEM);
    cudaFuncSetAttribute(flashmma_kernel, cudaFuncAttributeMaxDynamicSharedMemorySize, FL_SMEM);

    // host-side resources created once (graph-capture safe: same launch
    // topology on every call)
    static cudaStream_t s1 = nullptr;
    static cudaEvent_t evF = nullptr, ev1 = nullptr, evA = nullptr, evB = nullptr;
    if (!s1) {
        cudaStreamCreateWithFlags(&s1, cudaStreamNonBlocking);
        cudaEventCreateWithFlags(&evF, cudaEventDisableTiming);
        cudaEventCreateWithFlags(&ev1, cudaEventDisableTiming);
        cudaEventCreateWithFlags(&evA, cudaEventDisableTiming);
        cudaEventCreateWithFlags(&evB, cudaEventDisableTiming);
    }
    cudaStream_t s0 = (cudaStream_t)0;

    const int NELEM4 = NPTS * DIM / 4;

    // FORK: s1 must first wait on an event recorded in the capture-origin
    // stream before any of its work (capture requirement).
    cudaEventRecord(evF, s0);
    cudaStreamWaitEvent(s1, evF, 0);

    // s1: weight conversion + prep (independent of conv_split)
    conv_wt3<<<(3 * DIM * DIM + 255) / 256, 256, 0, s1>>>(W_fx, W_x, W_out, b_fx, b_x);
    prep_kernel<<<(PREP_N + 255) / 256, 256, 0, s1>>>(onion, labels, closest, velo_idx, surf_idx,
                                                      W_ws, b_ws, W_vc, b_vc);
    cudaEventRecord(ev1, s1);

    // s0: input split, then merged GEMM (needs conv_wt3)
    conv_split<<<(NELEM4 + 255) / 256, 256, 0, s0>>>(x, p_xh, p_xl, NELEM4, velo_idx, surf_idx);
    cudaStreamWaitEvent(s0, ev1, 0);
    gemm_fxxm<<<dim3(8, (NPTS + 127) / 128), 256, GMMA_SMEM, s0>>>();
    cudaEventRecord(evA, s0);

    // s0: attention chain
    proj1_kernel<<<dim3((L1 + 63) / 64, HEADS), 256, 0, s0>>>(Wq1, Wk1, Wv1);
    flashmma_kernel<<<dim3((L1 + 127) / 128, HEADS), 256, FL_SMEM, s0>>>();

    // s1: pooling chain, concurrent with attention chain (needs g_fx + prep)
    cudaStreamWaitEvent(s1, evA, 0);
    pool_accum<<<dim3((NPT_TOT + ACC_CHUNK - 1) / ACC_CHUNK, DIM / 64), 256, 0, s1>>>();
    ln_kernel<<<8, 64, 0, s1>>>(gamma, beta);
    attn2_kernel<<<HEADS, 256, ATTN2_SMEM, s1>>>(Wq, Wk, Wv);
    mat_out_kernel<<<(NTOK * DIM + 255) / 256, 256, 0, s1>>>();
    int compBlocks = ((DIM + 1) * DIM + 255) / 256;
    comp_kernel<<<compBlocks, 256, 0, s1>>>(p_Wsc, 64, p_bsc, p_osc, 64, 0.5f,
                                            p_Wcth, p_Wctl, p_bc);
    comp_kernel<<<compBlocks, 256, 0, s1>>>(W_vv, VC, b_vv, p_osc + SC * DIM, VC, 1.0f,
                                            p_Wcth + DIM * DIM, p_Wctl + DIM * DIM, p_bc + DIM);
    cudaEventRecord(evB, s1);

    // s0: join, then feature GEMMs + output GEMM
    cudaStreamWaitEvent(s0, evB, 0);
    gemm_feat<<<dim3(DIM / 128, (NSURF + 127) / 128), 256, GMMA_SMEM, s0>>>(
        p_Wcth, p_Wctl, p_bc, surf_idx, NSURF, FLAP, 1);
    gemm_feat<<<dim3(DIM / 128, (NVELO + 127) / 128), 256, GMMA_SMEM, s0>>>(
        p_Wcth + DIM * DIM, p_Wctl + DIM * DIM, p_bc + DIM, velo_idx, NVELO, 0, 0);

    gemm_mma<<<dim3(DIM / 128, (NPTS + 127) / 128), 256, GMMA_SMEM, s0>>>(
        p_nfh, p_nfl, p_Wth + 2 * DIM * DIM, p_Wtl + 2 * DIM * DIM,
        b_out, out, nullptr, nullptr, NPTS);
}